// round 9
// baseline (speedup 1.0000x reference)
#include <cuda_runtime.h>
#include <math.h>

#define B_    64
#define T_    512
#define NHID_ 1024
#define NG_   4096
#define NTOK_ 2048
#define NINP_ 512
#define NB_   128            // persistent CTAs (one per 8 hidden units)
#define WPC_  65536ULL       // packed-W floats per (phase, ub) = 2 kw * 64 chunks * 512

// ---------------- device scratch (static: no allocations) ----------------
__device__ float d_P[(size_t)NTOK_ * NG_];       // 32 MB per-token low-gate base
__device__ float d_hl[2][B_ * NHID_];            // h stored pre-rounded to tf32
__device__ float d_hh[2][B_ * NHID_];
__device__ float d_hs[(size_t)T_ * B_ * NHID_];  // h_low per step, [t][b][k] (tf32)
__device__ float d_biasHi[NG_];
__device__ float d_Wp[2ULL * NB_ * WPC_];        // 67 MB frag-packed tf32 weights
__device__ unsigned g_cnt;
__device__ unsigned g_gen;

// ---------------- helpers ----------------
__device__ __forceinline__ unsigned tf(float f) {
    unsigned u;
    asm("cvt.rna.tf32.f32 %0, %1;" : "=r"(u) : "f"(f));
    return u;
}
__device__ __forceinline__ float tff(float f) { return __uint_as_float(tf(f)); }
__device__ __forceinline__ unsigned fau(float f) { return __float_as_uint(f); }

__device__ __forceinline__ void mma_tf32(float* d, const unsigned* a,
                                         unsigned b0, unsigned b1) {
    asm volatile(
        "mma.sync.aligned.m16n8k8.row.col.f32.tf32.tf32.f32 "
        "{%0,%1,%2,%3},{%4,%5,%6,%7},{%8,%9},{%0,%1,%2,%3};\n"
        : "+f"(d[0]), "+f"(d[1]), "+f"(d[2]), "+f"(d[3])
        : "r"(a[0]), "r"(a[1]), "r"(a[2]), "r"(a[3]), "r"(b0), "r"(b1));
}

__device__ __forceinline__ uint4 tf4(float4 v) {
    return make_uint4(tf(v.x), tf(v.y), tf(v.z), tf(v.w));
}

__device__ __forceinline__ float sigm(float x) { return 1.0f / (1.0f + expf(-x)); }

// Grid-wide barrier
__device__ __forceinline__ void gridbar() {
    __threadfence();
    __syncthreads();
    if (threadIdx.x == 0) {
        unsigned gen = *(volatile unsigned*)&g_gen;
        unsigned prev = atomicAdd(&g_cnt, 1u);
        if (prev == NB_ - 1) {
            atomicExch(&g_cnt, 0u);
            __threadfence();
            atomicExch(&g_gen, gen + 1u);
        } else {
            while (*(volatile unsigned*)&g_gen == gen) __nanosleep(32);
        }
    }
    __syncthreads();
}

// ---------------- weight prepack: lane-coalesced frag-quads ----------------
// Consumer warp (mw, kw) at chunk c (16 k of its K-half) loads, per lane:
//   4 uint4 at wq + c*128 + j*32 + lane, j = kk2*2 + pair, holding
//   {W[n0][k], W[n0][k+4], W[n1][k], W[n1][k+4]},
//   n0 = pair*16 + (lane>>2), n1 = n0 + 8, k = kw*1024 + c*16 + kk2*8 + (lane&3).
// Gate-col n (0..31): gate g = n>>3, unit u = n&7 -> W row = g*NHID + ub*8 + u.
__global__ void __launch_bounds__(128) prepack2_k(
    const float* __restrict__ Wk0, int ldw0, int col0,   // kw = 0 source
    const float* __restrict__ Wk1, int ldw1,             // kw = 1 source
    float* __restrict__ outp)                            // phase base
{
    const int c = blockIdx.x, ub = blockIdx.y, kw = blockIdx.z;
    const int t = threadIdx.x, l = t & 31, j = t >> 5;
    const int kk2 = j >> 1, pair = j & 1;
    const int kloc = c * 16 + kk2 * 8 + (l & 3);
    const float* Ws; int ld, co;
    if (kw == 0) { Ws = Wk0; ld = ldw0; co = col0; }
    else         { Ws = Wk1; ld = ldw1; co = 0; }
    const int n0 = pair * 16 + (l >> 2), n1 = n0 + 8;
    const size_t r0 = (size_t)(n0 >> 3) * NHID_ + ub * 8 + (n0 & 7);
    const size_t r1 = (size_t)(n1 >> 3) * NHID_ + ub * 8 + (n1 & 7);
    uint4 v;
    v.x = tf(Ws[r0 * ld + co + kloc]);
    v.y = tf(Ws[r0 * ld + co + kloc + 4]);
    v.z = tf(Ws[r1 * ld + co + kloc]);
    v.w = tf(Ws[r1 * ld + co + kloc + 4]);
    uint4* o = (uint4*)outp + (((size_t)ub * 2 + kw) * 64 + c) * 128 + j * 32 + l;
    *o = v;
}

// ---------------- per-warp chunk body (S = reg-ring slot = c % 3) ----------
template <int S>
__device__ __forceinline__ void body(
    int c, float (&Ar)[3][8], uint4 (&Wr)[3][4], float (&acc)[4][4],
    const float* __restrict__ ar0, const float* __restrict__ ar1,
    const uint4* __restrict__ wq)
{
    constexpr int SN = (S + 2) % 3;
    if (c + 2 < 64) {                 // prefetch chunk c+2 (distance 2)
        const int kc = (c + 2) * 16;
        Ar[SN][0] = __ldcg(ar0 + kc);      Ar[SN][1] = __ldcg(ar1 + kc);
        Ar[SN][2] = __ldcg(ar0 + kc + 4);  Ar[SN][3] = __ldcg(ar1 + kc + 4);
        Ar[SN][4] = __ldcg(ar0 + kc + 8);  Ar[SN][5] = __ldcg(ar1 + kc + 8);
        Ar[SN][6] = __ldcg(ar0 + kc + 12); Ar[SN][7] = __ldcg(ar1 + kc + 12);
        const uint4* p = wq + (size_t)(c + 2) * 128;
        Wr[SN][0] = __ldg(p);      Wr[SN][1] = __ldg(p + 32);
        Wr[SN][2] = __ldg(p + 64); Wr[SN][3] = __ldg(p + 96);
    }
#pragma unroll
    for (int kk2 = 0; kk2 < 2; kk2++) {
        unsigned a[4];
        a[0] = fau(Ar[S][kk2 * 4 + 0]); a[1] = fau(Ar[S][kk2 * 4 + 1]);
        a[2] = fau(Ar[S][kk2 * 4 + 2]); a[3] = fau(Ar[S][kk2 * 4 + 3]);
        mma_tf32(acc[0], a, Wr[S][kk2 * 2].x,     Wr[S][kk2 * 2].y);
        mma_tf32(acc[1], a, Wr[S][kk2 * 2].z,     Wr[S][kk2 * 2].w);
        mma_tf32(acc[2], a, Wr[S][kk2 * 2 + 1].x, Wr[S][kk2 * 2 + 1].y);
        mma_tf32(acc[3], a, Wr[S][kk2 * 2 + 1].z, Wr[S][kk2 * 2 + 1].w);
    }
}

// ---------------- gate GEMM for one phase (barrier-free mainloop) ----------
// Warp (mw, kw): rows mw*16..+15 of A_{kw}, K-half kw, all 32 gate cols.
// Partials land in sg2[kw]; caller sums sg2[0] + sg2[1].
__device__ __forceinline__ void gemm_phase(
    float (&sg2)[2][64][34],
    const float* __restrict__ A0, const float* __restrict__ A1,
    const uint4* __restrict__ Wq)     // (phase, ub) base
{
    const int tid = threadIdx.x, lane = tid & 31, wid = tid >> 5;
    const int mw = wid & 3, kw = wid >> 2;
    const float* Am = kw ? A1 : A0;
    const float* ar0 = Am + (size_t)(mw * 16 + (lane >> 2)) * NHID_ + (lane & 3);
    const float* ar1 = ar0 + 8 * NHID_;
    const uint4* wq = Wq + (size_t)kw * (64 * 128) + lane;

    float Ar[3][8];
    uint4 Wr[3][4];
    float acc[4][4] = {};

    // prologue: chunks 0,1 into slots 0,1
#pragma unroll
    for (int s = 0; s < 2; s++) {
        const int kc = s * 16;
        Ar[s][0] = __ldcg(ar0 + kc);      Ar[s][1] = __ldcg(ar1 + kc);
        Ar[s][2] = __ldcg(ar0 + kc + 4);  Ar[s][3] = __ldcg(ar1 + kc + 4);
        Ar[s][4] = __ldcg(ar0 + kc + 8);  Ar[s][5] = __ldcg(ar1 + kc + 8);
        Ar[s][6] = __ldcg(ar0 + kc + 12); Ar[s][7] = __ldcg(ar1 + kc + 12);
        const uint4* p = wq + (size_t)s * 128;
        Wr[s][0] = __ldg(p);      Wr[s][1] = __ldg(p + 32);
        Wr[s][2] = __ldg(p + 64); Wr[s][3] = __ldg(p + 96);
    }

    for (int kb = 0; kb < 21; kb++) {
        body<0>(kb * 3,     Ar, Wr, acc, ar0, ar1, wq);
        body<1>(kb * 3 + 1, Ar, Wr, acc, ar0, ar1, wq);
        body<2>(kb * 3 + 2, Ar, Wr, acc, ar0, ar1, wq);
    }
    body<0>(63, Ar, Wr, acc, ar0, ar1, wq);

    // dump partials: sg2[kw][batch row][gate-col]
    {
        const int er = mw * 16 + (lane >> 2);
        const int ec = (lane & 3) * 2;
#pragma unroll
        for (int nt = 0; nt < 4; nt++) {
            const int cc = nt * 8 + ec;
            *(float2*)&sg2[kw][er][cc]     = make_float2(acc[nt][0], acc[nt][1]);
            *(float2*)&sg2[kw][er + 8][cc] = make_float2(acc[nt][2], acc[nt][3]);
        }
    }
    __syncthreads();   // single CTA barrier per phase (before epilogue reads)
}

// ---------------- persistent recurrence kernel ----------------
__global__ void __launch_bounds__(256, 1) hrnn_persist(
    const int* __restrict__ tokens, const int* __restrict__ measure,
    const float* __restrict__ c0l, const float* __restrict__ c0h,
    float* __restrict__ out, int out_size)
{
    __shared__ float sg2[2][64][34];

    const int tid = threadIdx.x;
    const int ub = blockIdx.x;
    const int u0 = ub * 8;
    const uint4* WqL = (const uint4*)d_Wp + (size_t)ub * (2 * 64 * 128);
    const uint4* WqH = (const uint4*)d_Wp + (size_t)(NB_ + ub) * (2 * 64 * 128);

    float* hl0 = d_hl[0]; float* hl1 = d_hl[1];
    float* hh0 = d_hh[0]; float* hh1 = d_hh[1];

    const int bA = tid >> 3;
    const int uA = tid & 7;
    const int unit = u0 + uA;
    const int bArr[2] = { bA, bA + 32 };

    float cl[2], ch[2], bv[4];
#pragma unroll
    for (int it = 0; it < 2; it++) {
        cl[it] = c0l[bArr[it] * NHID_ + unit];
        ch[it] = c0h[bArr[it] * NHID_ + unit];
    }
#pragma unroll
    for (int g = 0; g < 4; g++) bv[g] = __ldg(&d_biasHi[g * NHID_ + unit]);
    const int mval = *measure;

    for (int t = 0; t < T_; t++) {
        float* hlA = (t & 1) ? hl1 : hl0;
        float* hlN = (t & 1) ? hl0 : hl1;
        float* hhA = (t & 1) ? hh1 : hh0;
        float* hhN = (t & 1) ? hh0 : hh1;

        // prefetch epilogue operands for the low phase
        int tok[2];
        float pv[2][4];
#pragma unroll
        for (int it = 0; it < 2; it++) {
            tok[it] = __ldg(&tokens[bArr[it] * T_ + t]);
            const float* bp = d_P + (size_t)tok[it] * NG_ + unit;
#pragma unroll
            for (int g = 0; g < 4; g++) pv[it][g] = __ldg(bp + g * NHID_);
        }

        // ---- low cell: inp = [emb(tok) | h_h]; emb folded into d_P ----
        // kw=0: A0 = h_high vs Wil[:,512:]; kw=1: A1 = h_low vs Whl
        gemm_phase(sg2, hhA, hlA, WqL);
#pragma unroll
        for (int it = 0; it < 2; it++) {
            int b = bArr[it];
            float gi = sg2[0][b][uA]      + sg2[1][b][uA]      + pv[it][0];
            float gf = sg2[0][b][8 + uA]  + sg2[1][b][8 + uA]  + pv[it][1];
            float gg = sg2[0][b][16 + uA] + sg2[1][b][16 + uA] + pv[it][2];
            float go = sg2[0][b][24 + uA] + sg2[1][b][24 + uA] + pv[it][3];
            float cn = sigm(gf) * cl[it] + sigm(gi) * tanhf(gg);
            float hn = tff(sigm(go) * tanhf(cn));   // pre-rounded to tf32
            cl[it] = cn;
            hlN[b * NHID_ + unit] = hn;
            d_hs[((size_t)t * B_ + b) * NHID_ + unit] = hn;
        }
        gridbar();

        // prefetch kept-path previous high h
        float hp[2];
#pragma unroll
        for (int it = 0; it < 2; it++)
            hp[it] = __ldcg(&hhA[bArr[it] * NHID_ + unit]);

        // ---- high cell: masked update ----
        // kw=0: A0 = h_low(new) vs Wih; kw=1: A1 = h_high vs Whh
        gemm_phase(sg2, hlN, hhA, WqH);
#pragma unroll
        for (int it = 0; it < 2; it++) {
            int b = bArr[it];
            float gi = sg2[0][b][uA]      + sg2[1][b][uA]      + bv[0];
            float gf = sg2[0][b][8 + uA]  + sg2[1][b][8 + uA]  + bv[1];
            float gg = sg2[0][b][16 + uA] + sg2[1][b][16 + uA] + bv[2];
            float go = sg2[0][b][24 + uA] + sg2[1][b][24 + uA] + bv[3];
            float cn = sigm(gf) * ch[it] + sigm(gi) * tanhf(gg);
            float hn = tff(sigm(go) * tanhf(cn));
            bool m = (tok[it] == mval);
            ch[it] = m ? cn : ch[it];
            hhN[b * NHID_ + unit] = m ? hn : hp[it];
        }
        gridbar();
    }

    // final states (t=511 wrote ping 0); c still exact in registers
    size_t q = (size_t)B_ * T_ * NTOK_;
    size_t S = (size_t)B_ * NHID_;
    if ((size_t)out_size >= q + 4 * S) {
#pragma unroll
        for (int it = 0; it < 2; it++) {
            size_t o = (size_t)bArr[it] * NHID_ + unit;
            out[q + o]         = __ldcg(&hl0[o]);
            out[q + S + o]     = cl[it];
            out[q + 2 * S + o] = __ldcg(&hh0[o]);
            out[q + 3 * S + o] = ch[it];
        }
    }
}

// ---------------- generic tf32 GEMM: C[MxN] = A[MxK] @ Bw[N,K]^T + bias ----
template <int REMAP>
__global__ void __launch_bounds__(256) gemm_k(
    const float* __restrict__ A, int lda,
    const float* __restrict__ Bw, int ldb,
    const float* __restrict__ bias1, const float* __restrict__ bias2,
    float* __restrict__ C, int ldc, int K)
{
    __shared__ unsigned As[64][36];
    __shared__ unsigned Bs[64][36];

    const int tid = threadIdx.x, lane = tid & 31, wid = tid >> 5;
    const int m0 = blockIdx.y * 64, n0 = blockIdx.x * 64;

    const float* Ab;
    long as;
    if (REMAP) {
        Ab = A + ((size_t)(m0 % T_) * B_ + (m0 / T_)) * NHID_;
        as = (long)B_ * NHID_;
    } else {
        Ab = A + (size_t)m0 * lda;
        as = lda;
    }

    const int r = tid >> 3, c4 = (tid & 7) * 4;
    float4 pa0 = *(const float4*)(Ab + (long)r * as + c4);
    float4 pa1 = *(const float4*)(Ab + (long)(r + 32) * as + c4);
    float4 pb0 = *(const float4*)(Bw + (size_t)(n0 + r) * ldb + c4);
    float4 pb1 = *(const float4*)(Bw + (size_t)(n0 + r + 32) * ldb + c4);

    const int mw = wid >> 1, nw = wid & 1;
    float acc[4][4] = {};

    const int nch = K / 32;
    for (int kc = 0; kc < nch; kc++) {
        *(uint4*)&As[r][c4]      = tf4(pa0);
        *(uint4*)&As[r + 32][c4] = tf4(pa1);
        *(uint4*)&Bs[r][c4]      = tf4(pb0);
        *(uint4*)&Bs[r + 32][c4] = tf4(pb1);
        __syncthreads();
        if (kc + 1 < nch) {
            int ko = (kc + 1) * 32 + c4;
            pa0 = *(const float4*)(Ab + (long)r * as + ko);
            pa1 = *(const float4*)(Ab + (long)(r + 32) * as + ko);
            pb0 = *(const float4*)(Bw + (size_t)(n0 + r) * ldb + ko);
            pb1 = *(const float4*)(Bw + (size_t)(n0 + r + 32) * ldb + ko);
        }
#pragma unroll
        for (int kk = 0; kk < 4; kk++) {
            const int ak = kk * 8 + (lane & 3);
            const int ar = mw * 16 + (lane >> 2);
            unsigned a[4];
            a[0] = As[ar][ak];     a[1] = As[ar + 8][ak];
            a[2] = As[ar][ak + 4]; a[3] = As[ar + 8][ak + 4];
#pragma unroll
            for (int nt = 0; nt < 4; nt++) {
                const int br = nw * 32 + nt * 8 + (lane >> 2);
                mma_tf32(acc[nt], a, Bs[br][ak], Bs[br][ak + 4]);
            }
        }
        __syncthreads();
    }

    const int er = m0 + mw * 16 + (lane >> 2);
    const int ec0 = n0 + nw * 32 + (lane & 3) * 2;
#pragma unroll
    for (int nt = 0; nt < 4; nt++) {
        int c = ec0 + nt * 8;
        float bv0 = bias1[c]     + (bias2 ? bias2[c]     : 0.0f);
        float bv1 = bias1[c + 1] + (bias2 ? bias2[c + 1] : 0.0f);
        *(float2*)&C[(size_t)er * ldc + c] =
            make_float2(acc[nt][0] + bv0, acc[nt][1] + bv1);
        *(float2*)&C[(size_t)(er + 8) * ldc + c] =
            make_float2(acc[nt][2] + bv0, acc[nt][3] + bv1);
    }
}

// ---------------- init ----------------
__global__ void init_k(const float* h0l, const float* h0h,
                       const float* bih, const float* bhh)
{
    int i = blockIdx.x * blockDim.x + threadIdx.x;
    if (i < B_ * NHID_) {
        d_hl[0][i] = __uint_as_float(tf(h0l[i]));   // pre-round h to tf32
        d_hh[0][i] = __uint_as_float(tf(h0h[i]));
    }
    if (i < NG_) d_biasHi[i] = bih[i] + bhh[i];
}

// ---------------- launch ----------------
extern "C" void kernel_launch(void* const* d_in, const int* in_sizes, int n_in,
                              void* d_out, int out_size)
{
    const int*   tokens  = (const int*)d_in[0];
    const int*   measure = (const int*)d_in[1];
    const float* emb     = (const float*)d_in[2];
    const float* Wil     = (const float*)d_in[3];   // [4096][1536]
    const float* Whl     = (const float*)d_in[4];   // [4096][1024]
    const float* bil     = (const float*)d_in[5];
    const float* bhl     = (const float*)d_in[6];
    const float* Wih     = (const float*)d_in[7];   // [4096][1024]
    const float* Whh     = (const float*)d_in[8];   // [4096][1024]
    const float* bih     = (const float*)d_in[9];
    const float* bhh     = (const float*)d_in[10];
    const float* Wd      = (const float*)d_in[11];  // [2048][1024]
    const float* bd      = (const float*)d_in[12];
    const float* h0l     = (const float*)d_in[13];
    const float* c0l     = (const float*)d_in[14];
    const float* h0h     = (const float*)d_in[15];
    const float* c0h     = (const float*)d_in[16];
    float* out = (float*)d_out;

    void* p;
    cudaGetSymbolAddress(&p, d_P);  float* Pp  = (float*)p;
    cudaGetSymbolAddress(&p, d_hs); float* hsP = (float*)p;
    cudaGetSymbolAddress(&p, d_Wp); float* WpP = (float*)p;

    init_k<<<256, 256>>>(h0l, h0h, bih, bhh);

    // frag-pack recurrent weights
    // low phase:  kw0 = Wil cols 512..1535 (vs h_high), kw1 = Whl (vs h_low)
    // high phase: kw0 = Wih (vs h_low),                 kw1 = Whh (vs h_high)
    prepack2_k<<<dim3(64, NB_, 2), 128>>>(Wil, NINP_ + NHID_, NINP_,
                                          Whl, NHID_, WpP);
    prepack2_k<<<dim3(64, NB_, 2), 128>>>(Wih, NHID_, 0,
                                          Whh, NHID_, WpP + (size_t)NB_ * WPC_);

    // P[v][j] = emb[v,:512] @ W_ih_low[j,:512]^T + b_ih_low[j] + b_hh_low[j]
    gemm_k<0><<<dim3(NG_ / 64, NTOK_ / 64), 256>>>(
        emb, NINP_, Wil, NINP_ + NHID_, bil, bhl, Pp, NG_, NINP_);

    // entire 512-step recurrence in one persistent kernel
    hrnn_persist<<<NB_, 256>>>(tokens, measure, c0l, c0h, out, out_size);

    // decode: out[b*T+t][n] = hs[t][b][:] @ W_dec[n][:]^T + b_dec[n]
    gemm_k<1><<<dim3(NTOK_ / 64, (B_ * T_) / 64), 256>>>(
        hsP, 0, Wd, NHID_, bd, (const float*)0, out, NTOK_, NHID_);
}

// round 10
// speedup vs baseline: 1.0688x; 1.0688x over previous
#include <cuda_runtime.h>
#include <math.h>

#define B_    64
#define T_    512
#define NHID_ 1024
#define NG_   4096
#define NTOK_ 2048
#define NINP_ 512
#define NB_   64             // persistent CTAs (one per 16 hidden units)
#define WPC2_ 65536ULL       // packed-W uint2 per (phase, ub): 64 chunks * 1024

// ---------------- device scratch (static: no allocations) ----------------
__device__ float d_P[(size_t)NTOK_ * NG_];       // 32 MB per-token low-gate base
__device__ float d_hl[2][B_ * NHID_];            // h stored pre-rounded to tf32
__device__ float d_hh[2][B_ * NHID_];
__device__ float d_hs[(size_t)T_ * B_ * NHID_];  // h_low per step, [t][b][k] (tf32)
__device__ float d_biasHi[NG_];
__device__ uint2 d_Wp2[2ULL * NB_ * WPC2_];      // 64 MB frag-packed tf32 weights
__device__ unsigned g_cnt;
__device__ unsigned g_gen;

// ---------------- helpers ----------------
__device__ __forceinline__ unsigned tf(float f) {
    unsigned u;
    asm("cvt.rna.tf32.f32 %0, %1;" : "=r"(u) : "f"(f));
    return u;
}
__device__ __forceinline__ float tff(float f) { return __uint_as_float(tf(f)); }
__device__ __forceinline__ unsigned fau(float f) { return __float_as_uint(f); }

__device__ __forceinline__ void mma_tf32(float* d, const unsigned* a,
                                         unsigned b0, unsigned b1) {
    asm volatile(
        "mma.sync.aligned.m16n8k8.row.col.f32.tf32.tf32.f32 "
        "{%0,%1,%2,%3},{%4,%5,%6,%7},{%8,%9},{%0,%1,%2,%3};\n"
        : "+f"(d[0]), "+f"(d[1]), "+f"(d[2]), "+f"(d[3])
        : "r"(a[0]), "r"(a[1]), "r"(a[2]), "r"(a[3]), "r"(b0), "r"(b1));
}

__device__ __forceinline__ uint4 tf4(float4 v) {
    return make_uint4(tf(v.x), tf(v.y), tf(v.z), tf(v.w));
}

__device__ __forceinline__ float sigm(float x) { return 1.0f / (1.0f + expf(-x)); }

__device__ __forceinline__ unsigned s2u(const void* p) {
    return (unsigned)__cvta_generic_to_shared(p);
}
__device__ __forceinline__ void cpa16(unsigned sa, const void* g) {
    asm volatile("cp.async.cg.shared.global [%0], [%1], 16;" :: "r"(sa), "l"(g));
}
__device__ __forceinline__ void cpa_commit() {
    asm volatile("cp.async.commit_group;" ::: "memory");
}
template <int N>
__device__ __forceinline__ void cpa_wait() {
    asm volatile("cp.async.wait_group %0;" :: "n"(N) : "memory");
}

// Grid-wide barrier
__device__ __forceinline__ void gridbar() {
    __threadfence();
    __syncthreads();
    if (threadIdx.x == 0) {
        unsigned gen = *(volatile unsigned*)&g_gen;
        unsigned prev = atomicAdd(&g_cnt, 1u);
        if (prev == NB_ - 1) {
            atomicExch(&g_cnt, 0u);
            __threadfence();
            atomicExch(&g_gen, gen + 1u);
        } else {
            while (*(volatile unsigned*)&g_gen == gen) __nanosleep(32);
        }
    }
    __syncthreads();
}

// ---------------- weight prepack: lane-coalesced frag pairs ----------------
// Consumer warp (mw2, kw, nw) at chunk c loads 8 uint2 per lane:
//   idx = ub*65536 + c*1024 + kw*512 + nw*256 + grp*32 + lane, grp = kk2*4 + nt,
//   value {W[n][k], W[n][k+4]},
//   n = nw*32 + nt*8 + (lane>>2)  (gate-col 0..63),
//   k = c*32 + kw*16 + kk2*8 + (lane&3).
// Gate-col n: gate g = n>>4, unit u = n&15 -> W row = g*NHID + ub*16 + u.
__global__ void __launch_bounds__(256) prepack3_k(
    const float* __restrict__ W0, int ldw0, int col0,   // k < 1024 source
    const float* __restrict__ W1, int ldw1,             // k >= 1024 source
    uint2* __restrict__ outp)                           // phase base
{
    const int c = blockIdx.x, ub = blockIdx.y, z = blockIdx.z;
    const int kw = z >> 1, nw = z & 1;
    const int t = threadIdx.x, lane = t & 31, grp = t >> 5;
    const int kk2 = grp >> 2, nt = grp & 3;
    const int n = nw * 32 + nt * 8 + (lane >> 2);
    const size_t row = (size_t)(n >> 4) * NHID_ + ub * 16 + (n & 15);
    const int k = c * 32 + kw * 16 + kk2 * 8 + (lane & 3);
    float v0, v1;
    if (k < 1024) {
        v0 = W0[row * ldw0 + col0 + k];
        v1 = W0[row * ldw0 + col0 + k + 4];
    } else {
        v0 = W1[row * ldw1 + (k - 1024)];
        v1 = W1[row * ldw1 + (k - 1024) + 4];
    }
    outp[(size_t)ub * 65536 + (size_t)c * 1024 + kw * 512 + nw * 256
         + grp * 32 + lane] = make_uint2(tf(v0), tf(v1));
}

// ---------------- chunk body (S = stage/slot = c % 3) ----------------
// A staged via cp.async (3 stages), W via 3-slot register ring (distance 2).
template <int S, int WAITN>
__device__ __forceinline__ void chunk_body(
    int c,
    float (*As)[64][36], uint2 (&w)[3][8], float (&acc)[2][4][4],
    const float* __restrict__ A0, const float* __restrict__ A1,
    const uint2* __restrict__ wqw,
    int r, int c4, int lane, int mw2, int kw)
{
    constexpr int SN = (S + 2) % 3;
    if (c + 2 < 64) {
        const uint2* wc = wqw + (size_t)(c + 2) * 1024;
#pragma unroll
        for (int q = 0; q < 8; q++) w[SN][q] = __ldg(wc + q * 32);
    }
    cpa_wait<WAITN>();
    __syncthreads();
    if (c + 2 < 64) {
        const int kn = c + 2;
        const float* src = (kn < 32) ? (A0 + kn * 32) : (A1 + (kn - 32) * 32);
        cpa16(s2u(&As[SN][r][c4]),      src + (size_t)r * NHID_ + c4);
        cpa16(s2u(&As[SN][r + 32][c4]), src + (size_t)(r + 32) * NHID_ + c4);
        cpa_commit();
    }
    // compute chunk c from stage S: 2 m-tiles x 4 n-tiles x 2 k8-steps
#pragma unroll
    for (int kk2 = 0; kk2 < 2; kk2++) {
        const int ak = kw * 16 + kk2 * 8 + (lane & 3);
        unsigned a[2][4];
#pragma unroll
        for (int mt = 0; mt < 2; mt++) {
            const int ar = mw2 * 32 + mt * 16 + (lane >> 2);
            a[mt][0] = fau(As[S][ar][ak]);     a[mt][1] = fau(As[S][ar + 8][ak]);
            a[mt][2] = fau(As[S][ar][ak + 4]); a[mt][3] = fau(As[S][ar + 8][ak + 4]);
        }
#pragma unroll
        for (int nt = 0; nt < 4; nt++) {
            const uint2 bb = w[S][kk2 * 4 + nt];
#pragma unroll
            for (int mt = 0; mt < 2; mt++)
                mma_tf32(acc[mt][nt], a[mt], bb.x, bb.y);
        }
    }
}

// ---------------- gate GEMM for one phase ----------------
// sg2[kw][64 batch][66] partial gates (cols 0..63); caller sums sg2[0]+sg2[1].
__device__ __forceinline__ void gemm_phase(
    float (*As)[64][36], float (*sg2)[64][66],
    const float* __restrict__ A0, const float* __restrict__ A1,
    const uint2* __restrict__ Wq)     // (phase, ub) base
{
    const int tid = threadIdx.x, lane = tid & 31, wid = tid >> 5;
    const int nw = wid & 1, kw = (wid >> 1) & 1, mw2 = wid >> 2;
    const int r = tid >> 3, c4 = (tid & 7) * 4;

    const uint2* wqw = Wq + kw * 512 + nw * 256 + lane;

    // prologue: A chunks 0,1 via cp.async; W chunks 0,1 into slots 0,1
    cpa16(s2u(&As[0][r][c4]),      A0 + (size_t)r * NHID_ + c4);
    cpa16(s2u(&As[0][r + 32][c4]), A0 + (size_t)(r + 32) * NHID_ + c4);
    cpa_commit();
    cpa16(s2u(&As[1][r][c4]),      A0 + (size_t)r * NHID_ + 32 + c4);
    cpa16(s2u(&As[1][r + 32][c4]), A0 + (size_t)(r + 32) * NHID_ + 32 + c4);
    cpa_commit();

    uint2 w[3][8];
#pragma unroll
    for (int q = 0; q < 8; q++) w[0][q] = __ldg(wqw + q * 32);
#pragma unroll
    for (int q = 0; q < 8; q++) w[1][q] = __ldg(wqw + 1024 + q * 32);

    float acc[2][4][4] = {};
    for (int kb = 0; kb < 21; kb++) {
        chunk_body<0, 1>(kb * 3,     As, w, acc, A0, A1, wqw, r, c4, lane, mw2, kw);
        chunk_body<1, 1>(kb * 3 + 1, As, w, acc, A0, A1, wqw, r, c4, lane, mw2, kw);
        chunk_body<2, 1>(kb * 3 + 2, As, w, acc, A0, A1, wqw, r, c4, lane, mw2, kw);
    }
    chunk_body<0, 0>(63, As, w, acc, A0, A1, wqw, r, c4, lane, mw2, kw);

    // dump partials: sg2[kw][batch][gate-col]
#pragma unroll
    for (int mt = 0; mt < 2; mt++) {
        const int er = mw2 * 32 + mt * 16 + (lane >> 2);
        const int ec = nw * 32 + (lane & 3) * 2;
#pragma unroll
        for (int nt = 0; nt < 4; nt++) {
            const int cc = ec + nt * 8;
            *(float2*)&sg2[kw][er][cc]     = make_float2(acc[mt][nt][0], acc[mt][nt][1]);
            *(float2*)&sg2[kw][er + 8][cc] = make_float2(acc[mt][nt][2], acc[mt][nt][3]);
        }
    }
    __syncthreads();
}

// ---------------- persistent recurrence kernel ----------------
__global__ void __launch_bounds__(256, 1) hrnn_persist(
    const int* __restrict__ tokens, const int* __restrict__ measure,
    const float* __restrict__ c0l, const float* __restrict__ c0h,
    float* __restrict__ out, int out_size)
{
    extern __shared__ char dsm[];
    float (*As)[64][36]  = reinterpret_cast<float(*)[64][36]>(dsm);          // 27648 B
    float (*sg2)[64][66] = reinterpret_cast<float(*)[64][66]>(dsm + 27648);  // 33792 B

    const int tid = threadIdx.x;
    const int ub = blockIdx.x;
    const int u0 = ub * 16;
    const uint2* WqL = d_Wp2 + (size_t)ub * WPC2_;
    const uint2* WqH = d_Wp2 + (size_t)(NB_ + ub) * WPC2_;

    float* hl0 = d_hl[0]; float* hl1 = d_hl[1];
    float* hh0 = d_hh[0]; float* hh1 = d_hh[1];

    // epilogue ownership: 4 (b,u) pairs per thread
    int bE[4];
    const int uA = tid & 15;
    const int unit = u0 + uA;
#pragma unroll
    for (int it = 0; it < 4; it++) bE[it] = it * 16 + (tid >> 4);

    float cl[4], ch[4], bv[4];
#pragma unroll
    for (int it = 0; it < 4; it++) {
        cl[it] = c0l[bE[it] * NHID_ + unit];
        ch[it] = c0h[bE[it] * NHID_ + unit];
    }
#pragma unroll
    for (int g = 0; g < 4; g++) bv[g] = __ldg(&d_biasHi[g * NHID_ + unit]);
    const int mval = *measure;

    for (int t = 0; t < T_; t++) {
        float* hlA = (t & 1) ? hl1 : hl0;
        float* hlN = (t & 1) ? hl0 : hl1;
        float* hhA = (t & 1) ? hh1 : hh0;
        float* hhN = (t & 1) ? hh0 : hh1;

        // prefetch epilogue operands for the low phase
        int tok[4];
        float pv[4][4];
#pragma unroll
        for (int it = 0; it < 4; it++) {
            tok[it] = __ldg(&tokens[bE[it] * T_ + t]);
            const float* bp = d_P + (size_t)tok[it] * NG_ + unit;
#pragma unroll
            for (int g = 0; g < 4; g++) pv[it][g] = __ldg(bp + g * NHID_);
        }

        // ---- low cell: inp = [emb(tok) | h_h]; emb folded into d_P ----
        gemm_phase(As, sg2, hhA, hlA, WqL);
#pragma unroll
        for (int it = 0; it < 4; it++) {
            int b = bE[it];
            float gi = sg2[0][b][uA]      + sg2[1][b][uA]      + pv[it][0];
            float gf = sg2[0][b][16 + uA] + sg2[1][b][16 + uA] + pv[it][1];
            float gg = sg2[0][b][32 + uA] + sg2[1][b][32 + uA] + pv[it][2];
            float go = sg2[0][b][48 + uA] + sg2[1][b][48 + uA] + pv[it][3];
            float cn = sigm(gf) * cl[it] + sigm(gi) * tanhf(gg);
            float hn = tff(sigm(go) * tanhf(cn));   // pre-rounded to tf32
            cl[it] = cn;
            hlN[b * NHID_ + unit] = hn;
            d_hs[((size_t)t * B_ + b) * NHID_ + unit] = hn;
        }
        gridbar();

        // prefetch kept-path previous high h
        float hp[4];
#pragma unroll
        for (int it = 0; it < 4; it++)
            hp[it] = __ldcg(&hhA[bE[it] * NHID_ + unit]);

        // ---- high cell: masked update ----
        gemm_phase(As, sg2, hlN, hhA, WqH);
#pragma unroll
        for (int it = 0; it < 4; it++) {
            int b = bE[it];
            float gi = sg2[0][b][uA]      + sg2[1][b][uA]      + bv[0];
            float gf = sg2[0][b][16 + uA] + sg2[1][b][16 + uA] + bv[1];
            float gg = sg2[0][b][32 + uA] + sg2[1][b][32 + uA] + bv[2];
            float go = sg2[0][b][48 + uA] + sg2[1][b][48 + uA] + bv[3];
            float cn = sigm(gf) * ch[it] + sigm(gi) * tanhf(gg);
            float hn = tff(sigm(go) * tanhf(cn));
            bool m = (tok[it] == mval);
            ch[it] = m ? cn : ch[it];
            hhN[b * NHID_ + unit] = m ? hn : hp[it];
        }
        gridbar();
    }

    // final states (t=511 wrote ping 0); c still exact in registers
    size_t q = (size_t)B_ * T_ * NTOK_;
    size_t S = (size_t)B_ * NHID_;
    if ((size_t)out_size >= q + 4 * S) {
#pragma unroll
        for (int it = 0; it < 4; it++) {
            size_t o = (size_t)bE[it] * NHID_ + unit;
            out[q + o]         = __ldcg(&hl0[o]);
            out[q + S + o]     = cl[it];
            out[q + 2 * S + o] = __ldcg(&hh0[o]);
            out[q + 3 * S + o] = ch[it];
        }
    }
}

// ---------------- generic tf32 GEMM: C[MxN] = A[MxK] @ Bw[N,K]^T + bias ----
template <int REMAP>
__global__ void __launch_bounds__(256) gemm_k(
    const float* __restrict__ A, int lda,
    const float* __restrict__ Bw, int ldb,
    const float* __restrict__ bias1, const float* __restrict__ bias2,
    float* __restrict__ C, int ldc, int K)
{
    __shared__ unsigned As[64][36];
    __shared__ unsigned Bs[64][36];

    const int tid = threadIdx.x, lane = tid & 31, wid = tid >> 5;
    const int m0 = blockIdx.y * 64, n0 = blockIdx.x * 64;

    const float* Ab;
    long as;
    if (REMAP) {
        Ab = A + ((size_t)(m0 % T_) * B_ + (m0 / T_)) * NHID_;
        as = (long)B_ * NHID_;
    } else {
        Ab = A + (size_t)m0 * lda;
        as = lda;
    }

    const int r = tid >> 3, c4 = (tid & 7) * 4;
    float4 pa0 = *(const float4*)(Ab + (long)r * as + c4);
    float4 pa1 = *(const float4*)(Ab + (long)(r + 32) * as + c4);
    float4 pb0 = *(const float4*)(Bw + (size_t)(n0 + r) * ldb + c4);
    float4 pb1 = *(const float4*)(Bw + (size_t)(n0 + r + 32) * ldb + c4);

    const int mw = wid >> 1, nw = wid & 1;
    float acc[4][4] = {};

    const int nch = K / 32;
    for (int kc = 0; kc < nch; kc++) {
        *(uint4*)&As[r][c4]      = tf4(pa0);
        *(uint4*)&As[r + 32][c4] = tf4(pa1);
        *(uint4*)&Bs[r][c4]      = tf4(pb0);
        *(uint4*)&Bs[r + 32][c4] = tf4(pb1);
        __syncthreads();
        if (kc + 1 < nch) {
            int ko = (kc + 1) * 32 + c4;
            pa0 = *(const float4*)(Ab + (long)r * as + ko);
            pa1 = *(const float4*)(Ab + (long)(r + 32) * as + ko);
            pb0 = *(const float4*)(Bw + (size_t)(n0 + r) * ldb + ko);
            pb1 = *(const float4*)(Bw + (size_t)(n0 + r + 32) * ldb + ko);
        }
#pragma unroll
        for (int kk = 0; kk < 4; kk++) {
            const int ak = kk * 8 + (lane & 3);
            const int ar = mw * 16 + (lane >> 2);
            unsigned a[4];
            a[0] = As[ar][ak];     a[1] = As[ar + 8][ak];
            a[2] = As[ar][ak + 4]; a[3] = As[ar + 8][ak + 4];
#pragma unroll
            for (int nt = 0; nt < 4; nt++) {
                const int br = nw * 32 + nt * 8 + (lane >> 2);
                mma_tf32(acc[nt], a, Bs[br][ak], Bs[br][ak + 4]);
            }
        }
        __syncthreads();
    }

    const int er = m0 + mw * 16 + (lane >> 2);
    const int ec0 = n0 + nw * 32 + (lane & 3) * 2;
#pragma unroll
    for (int nt = 0; nt < 4; nt++) {
        int c = ec0 + nt * 8;
        float bv0 = bias1[c]     + (bias2 ? bias2[c]     : 0.0f);
        float bv1 = bias1[c + 1] + (bias2 ? bias2[c + 1] : 0.0f);
        *(float2*)&C[(size_t)er * ldc + c] =
            make_float2(acc[nt][0] + bv0, acc[nt][1] + bv1);
        *(float2*)&C[(size_t)(er + 8) * ldc + c] =
            make_float2(acc[nt][2] + bv0, acc[nt][3] + bv1);
    }
}

// ---------------- init ----------------
__global__ void init_k(const float* h0l, const float* h0h,
                       const float* bih, const float* bhh)
{
    int i = blockIdx.x * blockDim.x + threadIdx.x;
    if (i < B_ * NHID_) {
        d_hl[0][i] = __uint_as_float(tf(h0l[i]));   // pre-round h to tf32
        d_hh[0][i] = __uint_as_float(tf(h0h[i]));
    }
    if (i < NG_) d_biasHi[i] = bih[i] + bhh[i];
}

// ---------------- launch ----------------
extern "C" void kernel_launch(void* const* d_in, const int* in_sizes, int n_in,
                              void* d_out, int out_size)
{
    const int*   tokens  = (const int*)d_in[0];
    const int*   measure = (const int*)d_in[1];
    const float* emb     = (const float*)d_in[2];
    const float* Wil     = (const float*)d_in[3];   // [4096][1536]
    const float* Whl     = (const float*)d_in[4];   // [4096][1024]
    const float* bil     = (const float*)d_in[5];
    const float* bhl     = (const float*)d_in[6];
    const float* Wih     = (const float*)d_in[7];   // [4096][1024]
    const float* Whh     = (const float*)d_in[8];   // [4096][1024]
    const float* bih     = (const float*)d_in[9];
    const float* bhh     = (const float*)d_in[10];
    const float* Wd      = (const float*)d_in[11];  // [2048][1024]
    const float* bd      = (const float*)d_in[12];
    const float* h0l     = (const float*)d_in[13];
    const float* c0l     = (const float*)d_in[14];
    const float* h0h     = (const float*)d_in[15];
    const float* c0h     = (const float*)d_in[16];
    float* out = (float*)d_out;

    void* p;
    cudaGetSymbolAddress(&p, d_P);   float* Pp  = (float*)p;
    cudaGetSymbolAddress(&p, d_hs);  float* hsP = (float*)p;
    cudaGetSymbolAddress(&p, d_Wp2); uint2* WpP = (uint2*)p;

    init_k<<<256, 256>>>(h0l, h0h, bih, bhh);

    // frag-pack recurrent weights
    // low phase:  k<1024 = Wil cols 512.. (vs h_high), k>=1024 = Whl (vs h_low)
    // high phase: k<1024 = Wih (vs h_low),             k>=1024 = Whh (vs h_high)
    prepack3_k<<<dim3(64, NB_, 4), 256>>>(Wil, NINP_ + NHID_, NINP_,
                                          Whl, NHID_, WpP);
    prepack3_k<<<dim3(64, NB_, 4), 256>>>(Wih, NHID_, 0,
                                          Whh, NHID_, WpP + (size_t)NB_ * WPC2_);

    // P[v][j] = emb[v,:512] @ W_ih_low[j,:512]^T + b_ih_low[j] + b_hh_low[j]
    gemm_k<0><<<dim3(NG_ / 64, NTOK_ / 64), 256>>>(
        emb, NINP_, Wil, NINP_ + NHID_, bil, bhl, Pp, NG_, NINP_);

    // entire 512-step recurrence in one persistent kernel (61.4 KB dyn smem)
    cudaFuncSetAttribute(hrnn_persist,
                         cudaFuncAttributeMaxDynamicSharedMemorySize, 61440);
    hrnn_persist<<<NB_, 256, 61440>>>(tokens, measure, c0l, c0h, out, out_size);

    // decode: out[b*T+t][n] = hs[t][b][:] @ W_dec[n][:]^T + b_dec[n]
    gemm_k<1><<<dim3(NTOK_ / 64, (B_ * T_) / 64), 256>>>(
        hsP, 0, Wd, NHID_, bd, (const float*)0, out, NTOK_, NHID_);
}

// round 11
// speedup vs baseline: 1.2295x; 1.1504x over previous
#include <cuda_runtime.h>
#include <math.h>

#define B_    64
#define T_    512
#define NHID_ 1024
#define NG_   4096
#define NTOK_ 2048
#define NINP_ 512
#define NB_   128            // persistent CTAs (one per 8 hidden units)
#define WQC_  16384ULL       // packed-W uint4 per (phase, ub): 64 chunks * 256

// ---------------- device scratch (static: no allocations) ----------------
__device__ float d_P[(size_t)NTOK_ * NG_];       // 32 MB per-token low-gate base
__device__ float d_hl[2][B_ * NHID_];            // h stored pre-rounded to tf32
__device__ float d_hh[2][B_ * NHID_];
__device__ float d_hs[(size_t)T_ * B_ * NHID_];  // h_low per step, [t][b][k] (tf32)
__device__ float d_biasHi[NG_];
__device__ uint4 d_Wp4[2ULL * NB_ * WQC_];       // 64 MB frag-packed tf32 weights
__device__ unsigned g_cnt;
__device__ unsigned g_gen;

// ---------------- helpers ----------------
__device__ __forceinline__ unsigned tf(float f) {
    unsigned u;
    asm("cvt.rna.tf32.f32 %0, %1;" : "=r"(u) : "f"(f));
    return u;
}
__device__ __forceinline__ float tff(float f) { return __uint_as_float(tf(f)); }
__device__ __forceinline__ unsigned fau(float f) { return __float_as_uint(f); }

__device__ __forceinline__ void mma_tf32(float* d, const unsigned* a,
                                         unsigned b0, unsigned b1) {
    asm volatile(
        "mma.sync.aligned.m16n8k8.row.col.f32.tf32.tf32.f32 "
        "{%0,%1,%2,%3},{%4,%5,%6,%7},{%8,%9},{%0,%1,%2,%3};\n"
        : "+f"(d[0]), "+f"(d[1]), "+f"(d[2]), "+f"(d[3])
        : "r"(a[0]), "r"(a[1]), "r"(a[2]), "r"(a[3]), "r"(b0), "r"(b1));
}

__device__ __forceinline__ uint4 tf4(float4 v) {
    return make_uint4(tf(v.x), tf(v.y), tf(v.z), tf(v.w));
}

__device__ __forceinline__ float sigm(float x) { return 1.0f / (1.0f + expf(-x)); }

__device__ __forceinline__ unsigned s2u(const void* p) {
    return (unsigned)__cvta_generic_to_shared(p);
}
__device__ __forceinline__ void cpa16(unsigned sa, const void* g) {
    asm volatile("cp.async.cg.shared.global [%0], [%1], 16;" :: "r"(sa), "l"(g));
}
__device__ __forceinline__ void cpa_commit() {
    asm volatile("cp.async.commit_group;" ::: "memory");
}
template <int N>
__device__ __forceinline__ void cpa_wait() {
    asm volatile("cp.async.wait_group %0;" :: "n"(N) : "memory");
}

// Grid-wide barrier
__device__ __forceinline__ void gridbar() {
    __threadfence();
    __syncthreads();
    if (threadIdx.x == 0) {
        unsigned gen = *(volatile unsigned*)&g_gen;
        unsigned prev = atomicAdd(&g_cnt, 1u);
        if (prev == NB_ - 1) {
            atomicExch(&g_cnt, 0u);
            __threadfence();
            atomicExch(&g_gen, gen + 1u);
        } else {
            while (*(volatile unsigned*)&g_gen == gen) __nanosleep(32);
        }
    }
    __syncthreads();
}

// ---------------- weight prepack: uint4 frag-quads ----------------
// Per (ub, chunk c): 256 uint4. Consumer warp (mw, kw), lane l reads
//   wq4 = base + ub*16384 + c*256 + kw*128 + l, items + j*32 (j = 0..3).
// uint4 j = { pair(q=2j), pair(q=2j+1) } where q = kk2*4 + nt,
//   pair(q) = { W[n][k], W[n][k+4] },
//   n = (q&3)*8 + (l>>2)   (gate-col 0..31),
//   k = c*32 + (kw*2 + (q>>2))*8 + (l&3).
// Gate-col n: gate g = n>>3, unit u = n&7 -> W row = g*NHID + ub*8 + u.
__global__ void __launch_bounds__(256) prepack4_k(
    const float* __restrict__ W0, int ldw0, int col0,   // k < 1024 source
    const float* __restrict__ W1, int ldw1,             // k >= 1024 source
    uint4* __restrict__ outp)                           // phase base
{
    const int c = blockIdx.x, ub = blockIdx.y;
    const int t = threadIdx.x, lane = t & 31, j = (t >> 5) & 3, kw = t >> 7;
    unsigned pr[2][2];
#pragma unroll
    for (int h = 0; h < 2; h++) {
        const int q = 2 * j + h;
        const int n = (q & 3) * 8 + (lane >> 2);
        const size_t row = (size_t)(n >> 3) * NHID_ + ub * 8 + (n & 7);
        const int k = c * 32 + (kw * 2 + (q >> 2)) * 8 + (lane & 3);
        float v0, v1;
        if (k < 1024) {
            v0 = W0[row * ldw0 + col0 + k];
            v1 = W0[row * ldw0 + col0 + k + 4];
        } else {
            v0 = W1[row * ldw1 + (k - 1024)];
            v1 = W1[row * ldw1 + (k - 1024) + 4];
        }
        pr[h][0] = tf(v0); pr[h][1] = tf(v1);
    }
    outp[(size_t)ub * WQC_ + (size_t)c * 256 + kw * 128 + j * 32 + lane] =
        make_uint4(pr[0][0], pr[0][1], pr[1][0], pr[1][1]);
}

// ---------------- chunk body (S = stage/slot = c % 4) ----------------
// A staged via cp.async (4 stages, distance 3), W via 4-slot reg ring (dist 3).
template <int S>
__device__ __forceinline__ void chunk_body(
    int c,
    float (*As)[64][36], uint4 (&w4)[4][4], float (&acc)[4][4],
    const float* __restrict__ A0, const float* __restrict__ A1,
    const uint4* __restrict__ wq,
    int r, int c4, int lane, int mw, int kw)
{
    constexpr int SN = (S + 3) & 3;
    // W prefetch: chunk c+3 -> slot SN (last consumed in chunk c-1)
    if (c + 3 < 64) {
        const uint4* wc = wq + (size_t)(c + 3) * 256;
#pragma unroll
        for (int j = 0; j < 4; j++) w4[SN][j] = __ldg(wc + j * 32);
    }
    cpa_wait<2>();       // chunk c resident (2 newer groups may be in flight)
    __syncthreads();
    // issue A chunk c+3 -> stage SN; commit unconditionally (group accounting)
    {
        const int kn = c + 3;
        if (kn < 64) {
            const float* src = (kn < 32) ? (A0 + kn * 32) : (A1 + (kn - 32) * 32);
            cpa16(s2u(&As[SN][r][c4]),      src + (size_t)r * NHID_ + c4);
            cpa16(s2u(&As[SN][r + 32][c4]), src + (size_t)(r + 32) * NHID_ + c4);
        }
        cpa_commit();
    }
    // compute chunk c from stage S
#pragma unroll
    for (int kk2 = 0; kk2 < 2; kk2++) {
        const int ak = (kw * 2 + kk2) * 8 + (lane & 3);
        const int ar = mw * 16 + (lane >> 2);
        unsigned a[4];
        a[0] = fau(As[S][ar][ak]);     a[1] = fau(As[S][ar + 8][ak]);
        a[2] = fau(As[S][ar][ak + 4]); a[3] = fau(As[S][ar + 8][ak + 4]);
#pragma unroll
        for (int nt = 0; nt < 4; nt++) {
            const uint4 v = w4[S][kk2 * 2 + (nt >> 1)];
            if ((nt & 1) == 0) mma_tf32(acc[nt], a, v.x, v.y);
            else               mma_tf32(acc[nt], a, v.z, v.w);
        }
    }
}

// ---------------- gate GEMM for one phase ----------------
// sg2[kw][64 batch][34] partial gates; caller sums sg2[0] + sg2[1].
__device__ __forceinline__ void gemm_phase(
    float (*As)[64][36], float (*sg2)[64][34],
    const float* __restrict__ A0, const float* __restrict__ A1,
    const uint4* __restrict__ Wq)     // (phase, ub) base
{
    const int tid = threadIdx.x, lane = tid & 31, wid = tid >> 5;
    const int mw = wid >> 1, kw = wid & 1;
    const int r = tid >> 3, c4 = (tid & 7) * 4;

    const uint4* wq = Wq + kw * 128 + lane;

    // prologue: A chunks 0,1,2 via cp.async; W chunks 0,1,2 into slots 0,1,2
#pragma unroll
    for (int s = 0; s < 3; s++) {
        const float* src = A0 + s * 32;
        cpa16(s2u(&As[s][r][c4]),      src + (size_t)r * NHID_ + c4);
        cpa16(s2u(&As[s][r + 32][c4]), src + (size_t)(r + 32) * NHID_ + c4);
        cpa_commit();
    }
    uint4 w4[4][4];
#pragma unroll
    for (int s = 0; s < 3; s++)
#pragma unroll
        for (int j = 0; j < 4; j++)
            w4[s][j] = __ldg(wq + (size_t)s * 256 + j * 32);

    float acc[4][4] = {};
    for (int kb = 0; kb < 16; kb++) {
        chunk_body<0>(kb * 4,     As, w4, acc, A0, A1, wq, r, c4, lane, mw, kw);
        chunk_body<1>(kb * 4 + 1, As, w4, acc, A0, A1, wq, r, c4, lane, mw, kw);
        chunk_body<2>(kb * 4 + 2, As, w4, acc, A0, A1, wq, r, c4, lane, mw, kw);
        chunk_body<3>(kb * 4 + 3, As, w4, acc, A0, A1, wq, r, c4, lane, mw, kw);
    }

    // dump partials: sg2[kw][batch row][gate-col]
    {
        const int er = mw * 16 + (lane >> 2);
        const int ec = (lane & 3) * 2;
#pragma unroll
        for (int nt = 0; nt < 4; nt++) {
            const int cc = nt * 8 + ec;
            *(float2*)&sg2[kw][er][cc]     = make_float2(acc[nt][0], acc[nt][1]);
            *(float2*)&sg2[kw][er + 8][cc] = make_float2(acc[nt][2], acc[nt][3]);
        }
    }
    __syncthreads();
}

// ---------------- persistent recurrence kernel ----------------
__global__ void __launch_bounds__(256, 1) hrnn_persist(
    const int* __restrict__ tokens, const int* __restrict__ measure,
    const float* __restrict__ c0l, const float* __restrict__ c0h,
    float* __restrict__ out, int out_size)
{
    extern __shared__ char dsm[];
    float (*As)[64][36]  = reinterpret_cast<float(*)[64][36]>(dsm);          // 36864 B
    float (*sg2)[64][34] = reinterpret_cast<float(*)[64][34]>(dsm + 36864);  // 17408 B

    const int tid = threadIdx.x;
    const int ub = blockIdx.x;
    const int u0 = ub * 8;
    const uint4* WqL = d_Wp4 + (size_t)ub * WQC_;
    const uint4* WqH = d_Wp4 + (size_t)(NB_ + ub) * WQC_;

    float* hl0 = d_hl[0]; float* hl1 = d_hl[1];
    float* hh0 = d_hh[0]; float* hh1 = d_hh[1];

    const int bA = tid >> 3;
    const int uA = tid & 7;
    const int unit = u0 + uA;
    const int bArr[2] = { bA, bA + 32 };

    float cl[2], ch[2], bv[4];
#pragma unroll
    for (int it = 0; it < 2; it++) {
        cl[it] = c0l[bArr[it] * NHID_ + unit];
        ch[it] = c0h[bArr[it] * NHID_ + unit];
    }
#pragma unroll
    for (int g = 0; g < 4; g++) bv[g] = __ldg(&d_biasHi[g * NHID_ + unit]);
    const int mval = *measure;

    for (int t = 0; t < T_; t++) {
        float* hlA = (t & 1) ? hl1 : hl0;
        float* hlN = (t & 1) ? hl0 : hl1;
        float* hhA = (t & 1) ? hh1 : hh0;
        float* hhN = (t & 1) ? hh0 : hh1;

        // prefetch epilogue operands for the low phase
        int tok[2];
        float pv[2][4];
#pragma unroll
        for (int it = 0; it < 2; it++) {
            tok[it] = __ldg(&tokens[bArr[it] * T_ + t]);
            const float* bp = d_P + (size_t)tok[it] * NG_ + unit;
#pragma unroll
            for (int g = 0; g < 4; g++) pv[it][g] = __ldg(bp + g * NHID_);
        }

        // ---- low cell: inp = [emb(tok) | h_h]; emb folded into d_P ----
        gemm_phase(As, sg2, hhA, hlA, WqL);
#pragma unroll
        for (int it = 0; it < 2; it++) {
            int b = bArr[it];
            float gi = sg2[0][b][uA]      + sg2[1][b][uA]      + pv[it][0];
            float gf = sg2[0][b][8 + uA]  + sg2[1][b][8 + uA]  + pv[it][1];
            float gg = sg2[0][b][16 + uA] + sg2[1][b][16 + uA] + pv[it][2];
            float go = sg2[0][b][24 + uA] + sg2[1][b][24 + uA] + pv[it][3];
            float cn = sigm(gf) * cl[it] + sigm(gi) * tanhf(gg);
            float hn = tff(sigm(go) * tanhf(cn));   // pre-rounded to tf32
            cl[it] = cn;
            hlN[b * NHID_ + unit] = hn;
            d_hs[((size_t)t * B_ + b) * NHID_ + unit] = hn;
        }
        gridbar();

        // prefetch kept-path previous high h
        float hp[2];
#pragma unroll
        for (int it = 0; it < 2; it++)
            hp[it] = __ldcg(&hhA[bArr[it] * NHID_ + unit]);

        // ---- high cell: masked update ----
        gemm_phase(As, sg2, hlN, hhA, WqH);
#pragma unroll
        for (int it = 0; it < 2; it++) {
            int b = bArr[it];
            float gi = sg2[0][b][uA]      + sg2[1][b][uA]      + bv[0];
            float gf = sg2[0][b][8 + uA]  + sg2[1][b][8 + uA]  + bv[1];
            float gg = sg2[0][b][16 + uA] + sg2[1][b][16 + uA] + bv[2];
            float go = sg2[0][b][24 + uA] + sg2[1][b][24 + uA] + bv[3];
            float cn = sigm(gf) * ch[it] + sigm(gi) * tanhf(gg);
            float hn = tff(sigm(go) * tanhf(cn));
            bool m = (tok[it] == mval);
            ch[it] = m ? cn : ch[it];
            hhN[b * NHID_ + unit] = m ? hn : hp[it];
        }
        gridbar();
    }

    // final states (t=511 wrote ping 0); c still exact in registers
    size_t q = (size_t)B_ * T_ * NTOK_;
    size_t S = (size_t)B_ * NHID_;
    if ((size_t)out_size >= q + 4 * S) {
#pragma unroll
        for (int it = 0; it < 2; it++) {
            size_t o = (size_t)bArr[it] * NHID_ + unit;
            out[q + o]         = __ldcg(&hl0[o]);
            out[q + S + o]     = cl[it];
            out[q + 2 * S + o] = __ldcg(&hh0[o]);
            out[q + 3 * S + o] = ch[it];
        }
    }
}

// ---------------- generic tf32 GEMM: C[MxN] = A[MxK] @ Bw[N,K]^T + bias ----
template <int REMAP>
__global__ void __launch_bounds__(256) gemm_k(
    const float* __restrict__ A, int lda,
    const float* __restrict__ Bw, int ldb,
    const float* __restrict__ bias1, const float* __restrict__ bias2,
    float* __restrict__ C, int ldc, int K)
{
    __shared__ unsigned As[64][36];
    __shared__ unsigned Bs[64][36];

    const int tid = threadIdx.x, lane = tid & 31, wid = tid >> 5;
    const int m0 = blockIdx.y * 64, n0 = blockIdx.x * 64;

    const float* Ab;
    long as;
    if (REMAP) {
        Ab = A + ((size_t)(m0 % T_) * B_ + (m0 / T_)) * NHID_;
        as = (long)B_ * NHID_;
    } else {
        Ab = A + (size_t)m0 * lda;
        as = lda;
    }

    const int r = tid >> 3, c4 = (tid & 7) * 4;
    float4 pa0 = *(const float4*)(Ab + (long)r * as + c4);
    float4 pa1 = *(const float4*)(Ab + (long)(r + 32) * as + c4);
    float4 pb0 = *(const float4*)(Bw + (size_t)(n0 + r) * ldb + c4);
    float4 pb1 = *(const float4*)(Bw + (size_t)(n0 + r + 32) * ldb + c4);

    const int mw = wid >> 1, nw = wid & 1;
    float acc[4][4] = {};

    const int nch = K / 32;
    for (int kc = 0; kc < nch; kc++) {
        *(uint4*)&As[r][c4]      = tf4(pa0);
        *(uint4*)&As[r + 32][c4] = tf4(pa1);
        *(uint4*)&Bs[r][c4]      = tf4(pb0);
        *(uint4*)&Bs[r + 32][c4] = tf4(pb1);
        __syncthreads();
        if (kc + 1 < nch) {
            int ko = (kc + 1) * 32 + c4;
            pa0 = *(const float4*)(Ab + (long)r * as + ko);
            pa1 = *(const float4*)(Ab + (long)(r + 32) * as + ko);
            pb0 = *(const float4*)(Bw + (size_t)(n0 + r) * ldb + ko);
            pb1 = *(const float4*)(Bw + (size_t)(n0 + r + 32) * ldb + ko);
        }
#pragma unroll
        for (int kk = 0; kk < 4; kk++) {
            const int ak = kk * 8 + (lane & 3);
            const int ar = mw * 16 + (lane >> 2);
            unsigned a[4];
            a[0] = As[ar][ak];     a[1] = As[ar + 8][ak];
            a[2] = As[ar][ak + 4]; a[3] = As[ar + 8][ak + 4];
#pragma unroll
            for (int nt = 0; nt < 4; nt++) {
                const int br = nw * 32 + nt * 8 + (lane >> 2);
                mma_tf32(acc[nt], a, Bs[br][ak], Bs[br][ak + 4]);
            }
        }
        __syncthreads();
    }

    const int er = m0 + mw * 16 + (lane >> 2);
    const int ec0 = n0 + nw * 32 + (lane & 3) * 2;
#pragma unroll
    for (int nt = 0; nt < 4; nt++) {
        int c = ec0 + nt * 8;
        float bv0 = bias1[c]     + (bias2 ? bias2[c]     : 0.0f);
        float bv1 = bias1[c + 1] + (bias2 ? bias2[c + 1] : 0.0f);
        *(float2*)&C[(size_t)er * ldc + c] =
            make_float2(acc[nt][0] + bv0, acc[nt][1] + bv1);
        *(float2*)&C[(size_t)(er + 8) * ldc + c] =
            make_float2(acc[nt][2] + bv0, acc[nt][3] + bv1);
    }
}

// ---------------- init ----------------
__global__ void init_k(const float* h0l, const float* h0h,
                       const float* bih, const float* bhh)
{
    int i = blockIdx.x * blockDim.x + threadIdx.x;
    if (i < B_ * NHID_) {
        d_hl[0][i] = __uint_as_float(tf(h0l[i]));   // pre-round h to tf32
        d_hh[0][i] = __uint_as_float(tf(h0h[i]));
    }
    if (i < NG_) d_biasHi[i] = bih[i] + bhh[i];
}

// ---------------- launch ----------------
extern "C" void kernel_launch(void* const* d_in, const int* in_sizes, int n_in,
                              void* d_out, int out_size)
{
    const int*   tokens  = (const int*)d_in[0];
    const int*   measure = (const int*)d_in[1];
    const float* emb     = (const float*)d_in[2];
    const float* Wil     = (const float*)d_in[3];   // [4096][1536]
    const float* Whl     = (const float*)d_in[4];   // [4096][1024]
    const float* bil     = (const float*)d_in[5];
    const float* bhl     = (const float*)d_in[6];
    const float* Wih     = (const float*)d_in[7];   // [4096][1024]
    const float* Whh     = (const float*)d_in[8];   // [4096][1024]
    const float* bih     = (const float*)d_in[9];
    const float* bhh     = (const float*)d_in[10];
    const float* Wd      = (const float*)d_in[11];  // [2048][1024]
    const float* bd      = (const float*)d_in[12];
    const float* h0l     = (const float*)d_in[13];
    const float* c0l     = (const float*)d_in[14];
    const float* h0h     = (const float*)d_in[15];
    const float* c0h     = (const float*)d_in[16];
    float* out = (float*)d_out;

    void* p;
    cudaGetSymbolAddress(&p, d_P);   float* Pp  = (float*)p;
    cudaGetSymbolAddress(&p, d_hs);  float* hsP = (float*)p;
    cudaGetSymbolAddress(&p, d_Wp4); uint4* WpP = (uint4*)p;

    init_k<<<256, 256>>>(h0l, h0h, bih, bhh);

    // frag-pack recurrent weights
    // low phase:  k<1024 = Wil cols 512.. (vs h_high), k>=1024 = Whl (vs h_low)
    // high phase: k<1024 = Wih (vs h_low),             k>=1024 = Whh (vs h_high)
    prepack4_k<<<dim3(64, NB_), 256>>>(Wil, NINP_ + NHID_, NINP_,
                                       Whl, NHID_, WpP);
    prepack4_k<<<dim3(64, NB_), 256>>>(Wih, NHID_, 0,
                                       Whh, NHID_, WpP + (size_t)NB_ * WQC_);

    // P[v][j] = emb[v,:512] @ W_ih_low[j,:512]^T + b_ih_low[j] + b_hh_low[j]
    gemm_k<0><<<dim3(NG_ / 64, NTOK_ / 64), 256>>>(
        emb, NINP_, Wil, NINP_ + NHID_, bil, bhl, Pp, NG_, NINP_);

    // entire 512-step recurrence in one persistent kernel (54.3 KB dyn smem)
    cudaFuncSetAttribute(hrnn_persist,
                         cudaFuncAttributeMaxDynamicSharedMemorySize, 55296);
    hrnn_persist<<<NB_, 256, 55296>>>(tokens, measure, c0l, c0h, out, out_size);

    // decode: out[b*T+t][n] = hs[t][b][:] @ W_dec[n][:]^T + b_dec[n]
    gemm_k<1><<<dim3(NTOK_ / 64, (B_ * T_) / 64), 256>>>(
        hsP, 0, Wd, NHID_, bd, (const float*)0, out, NTOK_, NHID_);
}

// round 12
// speedup vs baseline: 1.6194x; 1.3171x over previous
#include <cuda_runtime.h>
#include <cuda_fp16.h>
#include <math.h>

#define B_    64
#define T_    512
#define NHID_ 1024
#define NG_   4096
#define NTOK_ 2048
#define NINP_ 512
#define NB_   128            // persistent CTAs (one per 8 hidden units)
#define WQH_  8192ULL        // packed-W uint4 per (phase, ub): 64 chunks * 128

// ---------------- device scratch (static: no allocations) ----------------
__device__ float  d_P[(size_t)NTOK_ * NG_];       // 32 MB per-token low-gate base
__device__ __half d_hl[2][B_ * NHID_];            // h state, fp16
__device__ __half d_hh[2][B_ * NHID_];
__device__ float  d_hs[(size_t)T_ * B_ * NHID_];  // h_low per step (fp32, for decode)
__device__ float  d_biasHi[NG_];
__device__ uint4  d_Wph[2ULL * NB_ * WQH_];       // 32 MB frag-packed fp16 weights
__device__ unsigned g_cnt;
__device__ unsigned g_gen;

// ---------------- helpers ----------------
__device__ __forceinline__ unsigned tf(float f) {
    unsigned u;
    asm("cvt.rna.tf32.f32 %0, %1;" : "=r"(u) : "f"(f));
    return u;
}
__device__ __forceinline__ uint4 tf4(float4 v) {
    return make_uint4(tf(v.x), tf(v.y), tf(v.z), tf(v.w));
}

__device__ __forceinline__ void mma_tf32(float* d, const unsigned* a,
                                         unsigned b0, unsigned b1) {
    asm volatile(
        "mma.sync.aligned.m16n8k8.row.col.f32.tf32.tf32.f32 "
        "{%0,%1,%2,%3},{%4,%5,%6,%7},{%8,%9},{%0,%1,%2,%3};\n"
        : "+f"(d[0]), "+f"(d[1]), "+f"(d[2]), "+f"(d[3])
        : "r"(a[0]), "r"(a[1]), "r"(a[2]), "r"(a[3]), "r"(b0), "r"(b1));
}

__device__ __forceinline__ void mma_f16(float* d, const unsigned* a,
                                        unsigned b0, unsigned b1) {
    asm volatile(
        "mma.sync.aligned.m16n8k16.row.col.f32.f16.f16.f32 "
        "{%0,%1,%2,%3},{%4,%5,%6,%7},{%8,%9},{%0,%1,%2,%3};\n"
        : "+f"(d[0]), "+f"(d[1]), "+f"(d[2]), "+f"(d[3])
        : "r"(a[0]), "r"(a[1]), "r"(a[2]), "r"(a[3]), "r"(b0), "r"(b1));
}

__device__ __forceinline__ float sigm(float x) { return 1.0f / (1.0f + expf(-x)); }

__device__ __forceinline__ unsigned s2u(const void* p) {
    return (unsigned)__cvta_generic_to_shared(p);
}
__device__ __forceinline__ void cpa16(unsigned sa, const void* g) {
    asm volatile("cp.async.cg.shared.global [%0], [%1], 16;" :: "r"(sa), "l"(g));
}
__device__ __forceinline__ void cpa_commit() {
    asm volatile("cp.async.commit_group;" ::: "memory");
}
template <int N>
__device__ __forceinline__ void cpa_wait() {
    asm volatile("cp.async.wait_group %0;" :: "n"(N) : "memory");
}
__device__ __forceinline__ unsigned h2u(float a, float b) {
    __half2 h = __floats2half2_rn(a, b);
    return *reinterpret_cast<unsigned*>(&h);
}

// Grid-wide barrier
__device__ __forceinline__ void gridbar() {
    __threadfence();
    __syncthreads();
    if (threadIdx.x == 0) {
        unsigned gen = *(volatile unsigned*)&g_gen;
        unsigned prev = atomicAdd(&g_cnt, 1u);
        if (prev == NB_ - 1) {
            atomicExch(&g_cnt, 0u);
            __threadfence();
            atomicExch(&g_gen, gen + 1u);
        } else {
            while (*(volatile unsigned*)&g_gen == gen) __nanosleep(32);
        }
    }
    __syncthreads();
}

// ---------------- weight prepack: fp16 frag-quads ----------------
// Per (ub, chunk c): 128 uint4 at base + ub*WQH_ + c*128 + kw*64 + j*32 + lane.
// uint4 j (j = 0,1) for warp kw, lane l:
//   { p0(nt=2j), p1(nt=2j), p0(nt=2j+1), p1(nt=2j+1) } where
//   p0(nt) = half2{ W[n][k],   W[n][k+1] },
//   p1(nt) = half2{ W[n][k+8], W[n][k+9] },
//   n = nt*8 + (l>>2) (gate-col 0..31), k = c*32 + kw*16 + (l&3)*2.
// Gate-col n: gate g = n>>3, unit u = n&7 -> W row = g*NHID + ub*8 + u.
__global__ void __launch_bounds__(128) prepack_h_k(
    const float* __restrict__ W0, int ldw0, int col0,   // k < 1024 source
    const float* __restrict__ W1, int ldw1,             // k >= 1024 source
    uint4* __restrict__ outp)                           // phase base
{
    const int c = blockIdx.x, ub = blockIdx.y;
    const int t = threadIdx.x, lane = t & 31, j = (t >> 5) & 1, kw = t >> 6;
    const int k = c * 32 + kw * 16 + (lane & 3) * 2;
    unsigned r[4];
#pragma unroll
    for (int h = 0; h < 2; h++) {
        const int n = (2 * j + h) * 8 + (lane >> 2);
        const size_t row = (size_t)(n >> 3) * NHID_ + ub * 8 + (n & 7);
        float v0, v1, v8, v9;
        if (k < 1024) {
            const float* s = W0 + row * ldw0 + col0 + k;
            v0 = s[0]; v1 = s[1]; v8 = s[8]; v9 = s[9];
        } else {
            const float* s = W1 + row * ldw1 + (k - 1024);
            v0 = s[0]; v1 = s[1]; v8 = s[8]; v9 = s[9];
        }
        r[h * 2]     = h2u(v0, v1);
        r[h * 2 + 1] = h2u(v8, v9);
    }
    outp[(size_t)ub * WQH_ + (size_t)c * 128 + kw * 64 + j * 32 + lane] =
        make_uint4(r[0], r[1], r[2], r[3]);
}

// ---------------- chunk body (S = stage/slot = c % 4) ----------------
// A (fp16) staged via cp.async (4 stages, dist 3); W via 4-slot reg ring (dist 3).
// As rows: 40 halfs pitch (80 B, 16B-multiple; frag LDS bank-conflict-free).
template <int S>
__device__ __forceinline__ void chunk_body(
    int c,
    __half (*As)[64][40], uint4 (&w4)[4][2], float (&acc)[4][4],
    const __half* __restrict__ A0, const __half* __restrict__ A1,
    const uint4* __restrict__ wq,
    int r, int c8, int lane, int mw, int kw)
{
    constexpr int SN = (S + 3) & 3;
    // W prefetch: chunk c+3 -> slot SN
    if (c + 3 < 64) {
        const uint4* wc = wq + (size_t)(c + 3) * 128;
        w4[SN][0] = __ldg(wc);
        w4[SN][1] = __ldg(wc + 32);
    }
    cpa_wait<2>();
    __syncthreads();
    // issue A chunk c+3 -> stage SN (1 cp.async.16B per thread = 4 KB chunk)
    {
        const int kn = c + 3;
        if (kn < 64) {
            const __half* src = (kn < 32) ? (A0 + kn * 32) : (A1 + (kn - 32) * 32);
            cpa16(s2u(&As[SN][r][c8]), src + (size_t)r * NHID_ + c8);
        }
        cpa_commit();
    }
    // compute chunk c from stage S: one k16 slab, 4 n8 tiles
    {
        const int ak = kw * 16 + (lane & 3) * 2;
        const int ar = mw * 16 + (lane >> 2);
        unsigned a[4];
        a[0] = *(const unsigned*)&As[S][ar][ak];
        a[1] = *(const unsigned*)&As[S][ar + 8][ak];
        a[2] = *(const unsigned*)&As[S][ar][ak + 8];
        a[3] = *(const unsigned*)&As[S][ar + 8][ak + 8];
        mma_f16(acc[0], a, w4[S][0].x, w4[S][0].y);
        mma_f16(acc[1], a, w4[S][0].z, w4[S][0].w);
        mma_f16(acc[2], a, w4[S][1].x, w4[S][1].y);
        mma_f16(acc[3], a, w4[S][1].z, w4[S][1].w);
    }
}

// ---------------- gate GEMM for one phase ----------------
// sg2[kw][64 batch][34] partial gates; caller sums sg2[0] + sg2[1].
__device__ __forceinline__ void gemm_phase(
    __half (*As)[64][40], float (*sg2)[64][34],
    const __half* __restrict__ A0, const __half* __restrict__ A1,
    const uint4* __restrict__ Wq)     // (phase, ub) base
{
    const int tid = threadIdx.x, lane = tid & 31, wid = tid >> 5;
    const int mw = wid >> 1, kw = wid & 1;
    const int r = tid >> 2, c8 = (tid & 3) * 8;   // staging: row 0..63, 8-half seg

    const uint4* wq = Wq + kw * 64 + lane;

    // prologue: A chunks 0,1,2 via cp.async; W chunks 0,1,2 into slots
#pragma unroll
    for (int s = 0; s < 3; s++) {
        cpa16(s2u(&As[s][r][c8]), A0 + (size_t)r * NHID_ + s * 32 + c8);
        cpa_commit();
    }
    uint4 w4[4][2];
#pragma unroll
    for (int s = 0; s < 3; s++) {
        w4[s][0] = __ldg(wq + (size_t)s * 128);
        w4[s][1] = __ldg(wq + (size_t)s * 128 + 32);
    }

    float acc[4][4] = {};
    for (int kb = 0; kb < 16; kb++) {
        chunk_body<0>(kb * 4,     As, w4, acc, A0, A1, wq, r, c8, lane, mw, kw);
        chunk_body<1>(kb * 4 + 1, As, w4, acc, A0, A1, wq, r, c8, lane, mw, kw);
        chunk_body<2>(kb * 4 + 2, As, w4, acc, A0, A1, wq, r, c8, lane, mw, kw);
        chunk_body<3>(kb * 4 + 3, As, w4, acc, A0, A1, wq, r, c8, lane, mw, kw);
    }

    // dump partials: sg2[kw][batch row][gate-col]
    {
        const int er = mw * 16 + (lane >> 2);
        const int ec = (lane & 3) * 2;
#pragma unroll
        for (int nt = 0; nt < 4; nt++) {
            const int cc = nt * 8 + ec;
            *(float2*)&sg2[kw][er][cc]     = make_float2(acc[nt][0], acc[nt][1]);
            *(float2*)&sg2[kw][er + 8][cc] = make_float2(acc[nt][2], acc[nt][3]);
        }
    }
    __syncthreads();
}

// ---------------- persistent recurrence kernel ----------------
__global__ void __launch_bounds__(256, 1) hrnn_persist(
    const int* __restrict__ tokens, const int* __restrict__ measure,
    const float* __restrict__ c0l, const float* __restrict__ c0h,
    float* __restrict__ out, int out_size)
{
    extern __shared__ char dsm[];
    __half (*As)[64][40] = reinterpret_cast<__half(*)[64][40]>(dsm);         // 20480 B
    float (*sg2)[64][34] = reinterpret_cast<float(*)[64][34]>(dsm + 20480);  // 17408 B

    const int tid = threadIdx.x;
    const int ub = blockIdx.x;
    const int u0 = ub * 8;
    const uint4* WqL = d_Wph + (size_t)ub * WQH_;
    const uint4* WqH = d_Wph + (size_t)(NB_ + ub) * WQH_;

    __half* hl0 = d_hl[0]; __half* hl1 = d_hl[1];
    __half* hh0 = d_hh[0]; __half* hh1 = d_hh[1];

    const int bA = tid >> 3;
    const int uA = tid & 7;
    const int unit = u0 + uA;
    const int bArr[2] = { bA, bA + 32 };

    float cl[2], ch[2], bv[4];
#pragma unroll
    for (int it = 0; it < 2; it++) {
        cl[it] = c0l[bArr[it] * NHID_ + unit];
        ch[it] = c0h[bArr[it] * NHID_ + unit];
    }
#pragma unroll
    for (int g = 0; g < 4; g++) bv[g] = __ldg(&d_biasHi[g * NHID_ + unit]);
    const int mval = *measure;

    for (int t = 0; t < T_; t++) {
        __half* hlA = (t & 1) ? hl1 : hl0;
        __half* hlN = (t & 1) ? hl0 : hl1;
        __half* hhA = (t & 1) ? hh1 : hh0;
        __half* hhN = (t & 1) ? hh0 : hh1;

        // prefetch epilogue operands for the low phase
        int tok[2];
        float pv[2][4];
#pragma unroll
        for (int it = 0; it < 2; it++) {
            tok[it] = __ldg(&tokens[bArr[it] * T_ + t]);
            const float* bp = d_P + (size_t)tok[it] * NG_ + unit;
#pragma unroll
            for (int g = 0; g < 4; g++) pv[it][g] = __ldg(bp + g * NHID_);
        }

        // ---- low cell: inp = [emb(tok) | h_h]; emb folded into d_P ----
        gemm_phase(As, sg2, hhA, hlA, WqL);
#pragma unroll
        for (int it = 0; it < 2; it++) {
            int b = bArr[it];
            float gi = sg2[0][b][uA]      + sg2[1][b][uA]      + pv[it][0];
            float gf = sg2[0][b][8 + uA]  + sg2[1][b][8 + uA]  + pv[it][1];
            float gg = sg2[0][b][16 + uA] + sg2[1][b][16 + uA] + pv[it][2];
            float go = sg2[0][b][24 + uA] + sg2[1][b][24 + uA] + pv[it][3];
            float cn = sigm(gf) * cl[it] + sigm(gi) * tanhf(gg);
            float hn = sigm(go) * tanhf(cn);
            cl[it] = cn;
            hlN[b * NHID_ + unit] = __float2half_rn(hn);
            d_hs[((size_t)t * B_ + b) * NHID_ + unit] = hn;
        }
        gridbar();

        // prefetch kept-path previous high h
        __half hp[2];
#pragma unroll
        for (int it = 0; it < 2; it++)
            hp[it] = __ldcg(&hhA[bArr[it] * NHID_ + unit]);

        // ---- high cell: masked update ----
        gemm_phase(As, sg2, hlN, hhA, WqH);
#pragma unroll
        for (int it = 0; it < 2; it++) {
            int b = bArr[it];
            float gi = sg2[0][b][uA]      + sg2[1][b][uA]      + bv[0];
            float gf = sg2[0][b][8 + uA]  + sg2[1][b][8 + uA]  + bv[1];
            float gg = sg2[0][b][16 + uA] + sg2[1][b][16 + uA] + bv[2];
            float go = sg2[0][b][24 + uA] + sg2[1][b][24 + uA] + bv[3];
            float cn = sigm(gf) * ch[it] + sigm(gi) * tanhf(gg);
            float hn = sigm(go) * tanhf(cn);
            bool m = (tok[it] == mval);
            ch[it] = m ? cn : ch[it];
            hhN[b * NHID_ + unit] = m ? __float2half_rn(hn) : hp[it];
        }
        gridbar();
    }

    // final states (t=511 wrote ping 0); c still exact in registers
    size_t q = (size_t)B_ * T_ * NTOK_;
    size_t S = (size_t)B_ * NHID_;
    if ((size_t)out_size >= q + 4 * S) {
#pragma unroll
        for (int it = 0; it < 2; it++) {
            size_t o = (size_t)bArr[it] * NHID_ + unit;
            out[q + o]         = __half2float(__ldcg(&hl0[o]));
            out[q + S + o]     = cl[it];
            out[q + 2 * S + o] = __half2float(__ldcg(&hh0[o]));
            out[q + 3 * S + o] = ch[it];
        }
    }
}

// ---------------- generic tf32 GEMM: C[MxN] = A[MxK] @ Bw[N,K]^T + bias ----
template <int REMAP>
__global__ void __launch_bounds__(256) gemm_k(
    const float* __restrict__ A, int lda,
    const float* __restrict__ Bw, int ldb,
    const float* __restrict__ bias1, const float* __restrict__ bias2,
    float* __restrict__ C, int ldc, int K)
{
    __shared__ unsigned As[64][36];
    __shared__ unsigned Bs[64][36];

    const int tid = threadIdx.x, lane = tid & 31, wid = tid >> 5;
    const int m0 = blockIdx.y * 64, n0 = blockIdx.x * 64;

    const float* Ab;
    long as;
    if (REMAP) {
        Ab = A + ((size_t)(m0 % T_) * B_ + (m0 / T_)) * NHID_;
        as = (long)B_ * NHID_;
    } else {
        Ab = A + (size_t)m0 * lda;
        as = lda;
    }

    const int r = tid >> 3, c4 = (tid & 7) * 4;
    float4 pa0 = *(const float4*)(Ab + (long)r * as + c4);
    float4 pa1 = *(const float4*)(Ab + (long)(r + 32) * as + c4);
    float4 pb0 = *(const float4*)(Bw + (size_t)(n0 + r) * ldb + c4);
    float4 pb1 = *(const float4*)(Bw + (size_t)(n0 + r + 32) * ldb + c4);

    const int mw = wid >> 1, nw = wid & 1;
    float acc[4][4] = {};

    const int nch = K / 32;
    for (int kc = 0; kc < nch; kc++) {
        *(uint4*)&As[r][c4]      = tf4(pa0);
        *(uint4*)&As[r + 32][c4] = tf4(pa1);
        *(uint4*)&Bs[r][c4]      = tf4(pb0);
        *(uint4*)&Bs[r + 32][c4] = tf4(pb1);
        __syncthreads();
        if (kc + 1 < nch) {
            int ko = (kc + 1) * 32 + c4;
            pa0 = *(const float4*)(Ab + (long)r * as + ko);
            pa1 = *(const float4*)(Ab + (long)(r + 32) * as + ko);
            pb0 = *(const float4*)(Bw + (size_t)(n0 + r) * ldb + ko);
            pb1 = *(const float4*)(Bw + (size_t)(n0 + r + 32) * ldb + ko);
        }
#pragma unroll
        for (int kk = 0; kk < 4; kk++) {
            const int ak = kk * 8 + (lane & 3);
            const int ar = mw * 16 + (lane >> 2);
            unsigned a[4];
            a[0] = As[ar][ak];     a[1] = As[ar + 8][ak];
            a[2] = As[ar][ak + 4]; a[3] = As[ar + 8][ak + 4];
#pragma unroll
            for (int nt = 0; nt < 4; nt++) {
                const int br = nw * 32 + nt * 8 + (lane >> 2);
                mma_tf32(acc[nt], a, Bs[br][ak], Bs[br][ak + 4]);
            }
        }
        __syncthreads();
    }

    const int er = m0 + mw * 16 + (lane >> 2);
    const int ec0 = n0 + nw * 32 + (lane & 3) * 2;
#pragma unroll
    for (int nt = 0; nt < 4; nt++) {
        int c = ec0 + nt * 8;
        float bv0 = bias1[c]     + (bias2 ? bias2[c]     : 0.0f);
        float bv1 = bias1[c + 1] + (bias2 ? bias2[c + 1] : 0.0f);
        *(float2*)&C[(size_t)er * ldc + c] =
            make_float2(acc[nt][0] + bv0, acc[nt][1] + bv1);
        *(float2*)&C[(size_t)(er + 8) * ldc + c] =
            make_float2(acc[nt][2] + bv0, acc[nt][3] + bv1);
    }
}

// ---------------- init ----------------
__global__ void init_k(const float* h0l, const float* h0h,
                       const float* bih, const float* bhh)
{
    int i = blockIdx.x * blockDim.x + threadIdx.x;
    if (i < B_ * NHID_) {
        d_hl[0][i] = __float2half_rn(h0l[i]);
        d_hh[0][i] = __float2half_rn(h0h[i]);
    }
    if (i < NG_) d_biasHi[i] = bih[i] + bhh[i];
}

// ---------------- launch ----------------
extern "C" void kernel_launch(void* const* d_in, const int* in_sizes, int n_in,
                              void* d_out, int out_size)
{
    const int*   tokens  = (const int*)d_in[0];
    const int*   measure = (const int*)d_in[1];
    const float* emb     = (const float*)d_in[2];
    const float* Wil     = (const float*)d_in[3];   // [4096][1536]
    const float* Whl     = (const float*)d_in[4];   // [4096][1024]
    const float* bil     = (const float*)d_in[5];
    const float* bhl     = (const float*)d_in[6];
    const float* Wih     = (const float*)d_in[7];   // [4096][1024]
    const float* Whh     = (const float*)d_in[8];   // [4096][1024]
    const float* bih     = (const float*)d_in[9];
    const float* bhh     = (const float*)d_in[10];
    const float* Wd      = (const float*)d_in[11];  // [2048][1024]
    const float* bd      = (const float*)d_in[12];
    const float* h0l     = (const float*)d_in[13];
    const float* c0l     = (const float*)d_in[14];
    const float* h0h     = (const float*)d_in[15];
    const float* c0h     = (const float*)d_in[16];
    float* out = (float*)d_out;

    void* p;
    cudaGetSymbolAddress(&p, d_P);   float* Pp  = (float*)p;
    cudaGetSymbolAddress(&p, d_hs);  float* hsP = (float*)p;
    cudaGetSymbolAddress(&p, d_Wph); uint4* WpP = (uint4*)p;

    init_k<<<256, 256>>>(h0l, h0h, bih, bhh);

    // frag-pack recurrent weights to fp16
    // low phase:  k<1024 = Wil cols 512.. (vs h_high), k>=1024 = Whl (vs h_low)
    // high phase: k<1024 = Wih (vs h_low),             k>=1024 = Whh (vs h_high)
    prepack_h_k<<<dim3(64, NB_), 128>>>(Wil, NINP_ + NHID_, NINP_,
                                        Whl, NHID_, WpP);
    prepack_h_k<<<dim3(64, NB_), 128>>>(Wih, NHID_, 0,
                                        Whh, NHID_, WpP + (size_t)NB_ * WQH_);

    // P[v][j] = emb[v,:512] @ W_ih_low[j,:512]^T + b_ih_low[j] + b_hh_low[j]
    gemm_k<0><<<dim3(NG_ / 64, NTOK_ / 64), 256>>>(
        emb, NINP_, Wil, NINP_ + NHID_, bil, bhl, Pp, NG_, NINP_);

    // entire 512-step recurrence in one persistent kernel (37.9 KB dyn smem)
    cudaFuncSetAttribute(hrnn_persist,
                         cudaFuncAttributeMaxDynamicSharedMemorySize, 38912);
    hrnn_persist<<<NB_, 256, 38912>>>(tokens, measure, c0l, c0h, out, out_size);

    // decode: out[b*T+t][n] = hs[t][b][:] @ W_dec[n][:]^T + b_dec[n]
    gemm_k<1><<<dim3(NTOK_ / 64, (B_ * T_) / 64), 256>>>(
        hsP, 0, Wd, NHID_, bd, (const float*)0, out, NTOK_, NHID_);
}

// round 13
// speedup vs baseline: 1.7478x; 1.0793x over previous
#include <cuda_runtime.h>
#include <cuda_fp16.h>
#include <math.h>

#define B_    64
#define T_    512
#define NHID_ 1024
#define NG_   4096
#define NTOK_ 2048
#define NINP_ 512
#define NB_   128            // persistent CTAs (one per 8 hidden units)
#define WQH_  8192ULL        // packed-W uint4 per (phase, ub): 64 chunks * 128

// ---------------- device scratch (static: no allocations) ----------------
__device__ float  d_P[(size_t)NTOK_ * NG_];       // 32 MB per-token low-gate base
__device__ __half d_hl[2][B_ * NHID_];            // h state, fp16
__device__ __half d_hh[2][B_ * NHID_];
__device__ float  d_hs[(size_t)T_ * B_ * NHID_];  // h_low per step (fp32, for decode)
__device__ float  d_biasHi[NG_];
__device__ uint4  d_Wph[2ULL * NB_ * WQH_];       // 32 MB frag-packed fp16 weights
__device__ unsigned g_cnt;
__device__ unsigned g_gen;

// ---------------- helpers ----------------
__device__ __forceinline__ unsigned tf(float f) {
    unsigned u;
    asm("cvt.rna.tf32.f32 %0, %1;" : "=r"(u) : "f"(f));
    return u;
}
__device__ __forceinline__ uint4 tf4(float4 v) {
    return make_uint4(tf(v.x), tf(v.y), tf(v.z), tf(v.w));
}

__device__ __forceinline__ void mma_tf32(float* d, const unsigned* a,
                                         unsigned b0, unsigned b1) {
    asm volatile(
        "mma.sync.aligned.m16n8k8.row.col.f32.tf32.tf32.f32 "
        "{%0,%1,%2,%3},{%4,%5,%6,%7},{%8,%9},{%0,%1,%2,%3};\n"
        : "+f"(d[0]), "+f"(d[1]), "+f"(d[2]), "+f"(d[3])
        : "r"(a[0]), "r"(a[1]), "r"(a[2]), "r"(a[3]), "r"(b0), "r"(b1));
}

__device__ __forceinline__ void mma_f16(float* d, const unsigned* a,
                                        unsigned b0, unsigned b1) {
    asm volatile(
        "mma.sync.aligned.m16n8k16.row.col.f32.f16.f16.f32 "
        "{%0,%1,%2,%3},{%4,%5,%6,%7},{%8,%9},{%0,%1,%2,%3};\n"
        : "+f"(d[0]), "+f"(d[1]), "+f"(d[2]), "+f"(d[3])
        : "r"(a[0]), "r"(a[1]), "r"(a[2]), "r"(a[3]), "r"(b0), "r"(b1));
}

__device__ __forceinline__ float sigm(float x) { return 1.0f / (1.0f + expf(-x)); }

__device__ __forceinline__ unsigned s2u(const void* p) {
    return (unsigned)__cvta_generic_to_shared(p);
}
__device__ __forceinline__ void cpa16(unsigned sa, const void* g) {
    asm volatile("cp.async.cg.shared.global [%0], [%1], 16;" :: "r"(sa), "l"(g));
}
__device__ __forceinline__ void cpa_commit() {
    asm volatile("cp.async.commit_group;" ::: "memory");
}
template <int N>
__device__ __forceinline__ void cpa_wait() {
    asm volatile("cp.async.wait_group %0;" :: "n"(N) : "memory");
}
__device__ __forceinline__ unsigned h2u(float a, float b) {
    __half2 h = __floats2half2_rn(a, b);
    return *reinterpret_cast<unsigned*>(&h);
}

// Grid-wide barrier
__device__ __forceinline__ void gridbar() {
    __threadfence();
    __syncthreads();
    if (threadIdx.x == 0) {
        unsigned gen = *(volatile unsigned*)&g_gen;
        unsigned prev = atomicAdd(&g_cnt, 1u);
        if (prev == NB_ - 1) {
            atomicExch(&g_cnt, 0u);
            __threadfence();
            atomicExch(&g_gen, gen + 1u);
        } else {
            while (*(volatile unsigned*)&g_gen == gen) __nanosleep(32);
        }
    }
    __syncthreads();
}

// ---------------- weight prepack: fp16 frag-quads (same as R12) ----------
__global__ void __launch_bounds__(128) prepack_h_k(
    const float* __restrict__ W0, int ldw0, int col0,   // k < 1024 source
    const float* __restrict__ W1, int ldw1,             // k >= 1024 source
    uint4* __restrict__ outp)                           // phase base
{
    const int c = blockIdx.x, ub = blockIdx.y;
    const int t = threadIdx.x, lane = t & 31, j = (t >> 5) & 1, kw = t >> 6;
    const int k = c * 32 + kw * 16 + (lane & 3) * 2;
    unsigned r[4];
#pragma unroll
    for (int h = 0; h < 2; h++) {
        const int n = (2 * j + h) * 8 + (lane >> 2);
        const size_t row = (size_t)(n >> 3) * NHID_ + ub * 8 + (n & 7);
        float v0, v1, v8, v9;
        if (k < 1024) {
            const float* s = W0 + row * ldw0 + col0 + k;
            v0 = s[0]; v1 = s[1]; v8 = s[8]; v9 = s[9];
        } else {
            const float* s = W1 + row * ldw1 + (k - 1024);
            v0 = s[0]; v1 = s[1]; v8 = s[8]; v9 = s[9];
        }
        r[h * 2]     = h2u(v0, v1);
        r[h * 2 + 1] = h2u(v8, v9);
    }
    outp[(size_t)ub * WQH_ + (size_t)c * 128 + kw * 64 + j * 32 + lane] =
        make_uint4(r[0], r[1], r[2], r[3]);
}

// ---------------- warp-private chunk body (S = stage = c % 4) ------------
// Warp stages ONLY its own 16-row x 16-k A slice (512 B = 32 lanes x 16 B).
// Sync: per-warp cp.async wait + __syncwarp. NO CTA barriers in mainloop.
// Asw rows: 24 halfs pitch (48 B) -> all 4 frag LDS patterns conflict-free.
template <int S>
__device__ __forceinline__ void chunk_body(
    int c,
    __half (*Asw)[16][24], uint4 (&w4)[4][2], float (&acc)[4][4],
    const __half* __restrict__ A0, const __half* __restrict__ A1,
    const uint4* __restrict__ wq,
    size_t aoff, int srowL, int scol, int lane)
{
    constexpr int SN = (S + 3) & 3;
    // W prefetch: chunk c+3 -> slot SN
    if (c + 3 < 64) {
        const uint4* wc = wq + (size_t)(c + 3) * 128;
        w4[SN][0] = __ldg(wc);
        w4[SN][1] = __ldg(wc + 32);
    }
    cpa_wait<2>();       // this warp's chunk-c slice resident
    __syncwarp();
    // issue A chunk c+3 slice -> warp stage SN; commit unconditionally
    {
        const int kn = c + 3;
        if (kn < 64) {
            const __half* src = (kn < 32) ? (A0 + kn * 32) : (A1 + (kn - 32) * 32);
            cpa16(s2u(&Asw[SN][srowL][scol]), src + aoff);
        }
        cpa_commit();
    }
    // compute chunk c from stage S: one k16 slab, 4 n8 tiles
    {
        const int ar = lane >> 2;
        const int ak = (lane & 3) * 2;
        unsigned a[4];
        a[0] = *(const unsigned*)&Asw[S][ar][ak];
        a[1] = *(const unsigned*)&Asw[S][ar + 8][ak];
        a[2] = *(const unsigned*)&Asw[S][ar][ak + 8];
        a[3] = *(const unsigned*)&Asw[S][ar + 8][ak + 8];
        mma_f16(acc[0], a, w4[S][0].x, w4[S][0].y);
        mma_f16(acc[1], a, w4[S][0].z, w4[S][0].w);
        mma_f16(acc[2], a, w4[S][1].x, w4[S][1].y);
        mma_f16(acc[3], a, w4[S][1].z, w4[S][1].w);
    }
}

// ---------------- gate GEMM for one phase (barrier-free mainloop) --------
// sg2[kw][64 batch][34] partial gates; caller sums sg2[0] + sg2[1].
__device__ __forceinline__ void gemm_phase(
    __half* AsBase, float (*sg2)[64][34],
    const __half* __restrict__ A0, const __half* __restrict__ A1,
    const uint4* __restrict__ Wq)     // (phase, ub) base
{
    const int tid = threadIdx.x, lane = tid & 31, wid = tid >> 5;
    const int mw = wid >> 1, kw = wid & 1;

    // warp-private staging region: [4 stages][16 rows][24 halfs]
    __half (*Asw)[16][24] =
        reinterpret_cast<__half(*)[16][24]>(AsBase + (size_t)wid * (4 * 16 * 24));

    // staging coords: lane covers (row = lane>>1, 8-half seg = lane&1)
    const int srowL = lane >> 1;
    const int scol  = (lane & 1) * 8;
    const size_t aoff = (size_t)(mw * 16 + srowL) * NHID_ + kw * 16 + scol;

    const uint4* wq = Wq + kw * 64 + lane;

    // prologue: A slices of chunks 0,1,2; W chunks 0,1,2 into reg slots
#pragma unroll
    for (int s = 0; s < 3; s++) {
        cpa16(s2u(&Asw[s][srowL][scol]), A0 + s * 32 + aoff);
        cpa_commit();
    }
    uint4 w4[4][2];
#pragma unroll
    for (int s = 0; s < 3; s++) {
        w4[s][0] = __ldg(wq + (size_t)s * 128);
        w4[s][1] = __ldg(wq + (size_t)s * 128 + 32);
    }

    float acc[4][4] = {};
    for (int kb = 0; kb < 16; kb++) {
        chunk_body<0>(kb * 4,     Asw, w4, acc, A0, A1, wq, aoff, srowL, scol, lane);
        chunk_body<1>(kb * 4 + 1, Asw, w4, acc, A0, A1, wq, aoff, srowL, scol, lane);
        chunk_body<2>(kb * 4 + 2, Asw, w4, acc, A0, A1, wq, aoff, srowL, scol, lane);
        chunk_body<3>(kb * 4 + 3, Asw, w4, acc, A0, A1, wq, aoff, srowL, scol, lane);
    }

    // dump partials: sg2[kw][batch row][gate-col]
    {
        const int er = mw * 16 + (lane >> 2);
        const int ec = (lane & 3) * 2;
#pragma unroll
        for (int nt = 0; nt < 4; nt++) {
            const int cc = nt * 8 + ec;
            *(float2*)&sg2[kw][er][cc]     = make_float2(acc[nt][0], acc[nt][1]);
            *(float2*)&sg2[kw][er + 8][cc] = make_float2(acc[nt][2], acc[nt][3]);
        }
    }
    __syncthreads();   // the ONLY CTA barrier in the phase
}

// ---------------- persistent recurrence kernel ----------------
__global__ void __launch_bounds__(256, 1) hrnn_persist(
    const int* __restrict__ tokens, const int* __restrict__ measure,
    const float* __restrict__ c0l, const float* __restrict__ c0h,
    float* __restrict__ out, int out_size)
{
    extern __shared__ char dsm[];
    __half* AsBase = reinterpret_cast<__half*>(dsm);                         // 24576 B
    float (*sg2)[64][34] = reinterpret_cast<float(*)[64][34]>(dsm + 24576);  // 17408 B

    const int tid = threadIdx.x;
    const int ub = blockIdx.x;
    const int u0 = ub * 8;
    const uint4* WqL = d_Wph + (size_t)ub * WQH_;
    const uint4* WqH = d_Wph + (size_t)(NB_ + ub) * WQH_;

    __half* hl0 = d_hl[0]; __half* hl1 = d_hl[1];
    __half* hh0 = d_hh[0]; __half* hh1 = d_hh[1];

    const int bA = tid >> 3;
    const int uA = tid & 7;
    const int unit = u0 + uA;
    const int bArr[2] = { bA, bA + 32 };

    float cl[2], ch[2], bv[4];
#pragma unroll
    for (int it = 0; it < 2; it++) {
        cl[it] = c0l[bArr[it] * NHID_ + unit];
        ch[it] = c0h[bArr[it] * NHID_ + unit];
    }
#pragma unroll
    for (int g = 0; g < 4; g++) bv[g] = __ldg(&d_biasHi[g * NHID_ + unit]);
    const int mval = *measure;

    for (int t = 0; t < T_; t++) {
        __half* hlA = (t & 1) ? hl1 : hl0;
        __half* hlN = (t & 1) ? hl0 : hl1;
        __half* hhA = (t & 1) ? hh1 : hh0;
        __half* hhN = (t & 1) ? hh0 : hh1;

        // prefetch epilogue operands for the low phase
        int tok[2];
        float pv[2][4];
#pragma unroll
        for (int it = 0; it < 2; it++) {
            tok[it] = __ldg(&tokens[bArr[it] * T_ + t]);
            const float* bp = d_P + (size_t)tok[it] * NG_ + unit;
#pragma unroll
            for (int g = 0; g < 4; g++) pv[it][g] = __ldg(bp + g * NHID_);
        }

        // ---- low cell: inp = [emb(tok) | h_h]; emb folded into d_P ----
        gemm_phase(AsBase, sg2, hhA, hlA, WqL);
#pragma unroll
        for (int it = 0; it < 2; it++) {
            int b = bArr[it];
            float gi = sg2[0][b][uA]      + sg2[1][b][uA]      + pv[it][0];
            float gf = sg2[0][b][8 + uA]  + sg2[1][b][8 + uA]  + pv[it][1];
            float gg = sg2[0][b][16 + uA] + sg2[1][b][16 + uA] + pv[it][2];
            float go = sg2[0][b][24 + uA] + sg2[1][b][24 + uA] + pv[it][3];
            float cn = sigm(gf) * cl[it] + sigm(gi) * tanhf(gg);
            float hn = sigm(go) * tanhf(cn);
            cl[it] = cn;
            hlN[b * NHID_ + unit] = __float2half_rn(hn);
            d_hs[((size_t)t * B_ + b) * NHID_ + unit] = hn;
        }
        gridbar();

        // prefetch kept-path previous high h
        __half hp[2];
#pragma unroll
        for (int it = 0; it < 2; it++)
            hp[it] = __ldcg(&hhA[bArr[it] * NHID_ + unit]);

        // ---- high cell: masked update ----
        gemm_phase(AsBase, sg2, hlN, hhA, WqH);
#pragma unroll
        for (int it = 0; it < 2; it++) {
            int b = bArr[it];
            float gi = sg2[0][b][uA]      + sg2[1][b][uA]      + bv[0];
            float gf = sg2[0][b][8 + uA]  + sg2[1][b][8 + uA]  + bv[1];
            float gg = sg2[0][b][16 + uA] + sg2[1][b][16 + uA] + bv[2];
            float go = sg2[0][b][24 + uA] + sg2[1][b][24 + uA] + bv[3];
            float cn = sigm(gf) * ch[it] + sigm(gi) * tanhf(gg);
            float hn = sigm(go) * tanhf(cn);
            bool m = (tok[it] == mval);
            ch[it] = m ? cn : ch[it];
            hhN[b * NHID_ + unit] = m ? __float2half_rn(hn) : hp[it];
        }
        gridbar();
    }

    // final states (t=511 wrote ping 0); c still exact in registers
    size_t q = (size_t)B_ * T_ * NTOK_;
    size_t S = (size_t)B_ * NHID_;
    if ((size_t)out_size >= q + 4 * S) {
#pragma unroll
        for (int it = 0; it < 2; it++) {
            size_t o = (size_t)bArr[it] * NHID_ + unit;
            out[q + o]         = __half2float(__ldcg(&hl0[o]));
            out[q + S + o]     = cl[it];
            out[q + 2 * S + o] = __half2float(__ldcg(&hh0[o]));
            out[q + 3 * S + o] = ch[it];
        }
    }
}

// ---------------- generic tf32 GEMM: C[MxN] = A[MxK] @ Bw[N,K]^T + bias ----
template <int REMAP>
__global__ void __launch_bounds__(256) gemm_k(
    const float* __restrict__ A, int lda,
    const float* __restrict__ Bw, int ldb,
    const float* __restrict__ bias1, const float* __restrict__ bias2,
    float* __restrict__ C, int ldc, int K)
{
    __shared__ unsigned As[64][36];
    __shared__ unsigned Bs[64][36];

    const int tid = threadIdx.x, lane = tid & 31, wid = tid >> 5;
    const int m0 = blockIdx.y * 64, n0 = blockIdx.x * 64;

    const float* Ab;
    long as;
    if (REMAP) {
        Ab = A + ((size_t)(m0 % T_) * B_ + (m0 / T_)) * NHID_;
        as = (long)B_ * NHID_;
    } else {
        Ab = A + (size_t)m0 * lda;
        as = lda;
    }

    const int r = tid >> 3, c4 = (tid & 7) * 4;
    float4 pa0 = *(const float4*)(Ab + (long)r * as + c4);
    float4 pa1 = *(const float4*)(Ab + (long)(r + 32) * as + c4);
    float4 pb0 = *(const float4*)(Bw + (size_t)(n0 + r) * ldb + c4);
    float4 pb1 = *(const float4*)(Bw + (size_t)(n0 + r + 32) * ldb + c4);

    const int mw = wid >> 1, nw = wid & 1;
    float acc[4][4] = {};

    const int nch = K / 32;
    for (int kc = 0; kc < nch; kc++) {
        *(uint4*)&As[r][c4]      = tf4(pa0);
        *(uint4*)&As[r + 32][c4] = tf4(pa1);
        *(uint4*)&Bs[r][c4]      = tf4(pb0);
        *(uint4*)&Bs[r + 32][c4] = tf4(pb1);
        __syncthreads();
        if (kc + 1 < nch) {
            int ko = (kc + 1) * 32 + c4;
            pa0 = *(const float4*)(Ab + (long)r * as + ko);
            pa1 = *(const float4*)(Ab + (long)(r + 32) * as + ko);
            pb0 = *(const float4*)(Bw + (size_t)(n0 + r) * ldb + ko);
            pb1 = *(const float4*)(Bw + (size_t)(n0 + r + 32) * ldb + ko);
        }
#pragma unroll
        for (int kk = 0; kk < 4; kk++) {
            const int ak = kk * 8 + (lane & 3);
            const int ar = mw * 16 + (lane >> 2);
            unsigned a[4];
            a[0] = As[ar][ak];     a[1] = As[ar + 8][ak];
            a[2] = As[ar][ak + 4]; a[3] = As[ar + 8][ak + 4];
#pragma unroll
            for (int nt = 0; nt < 4; nt++) {
                const int br = nw * 32 + nt * 8 + (lane >> 2);
                mma_tf32(acc[nt], a, Bs[br][ak], Bs[br][ak + 4]);
            }
        }
        __syncthreads();
    }

    const int er = m0 + mw * 16 + (lane >> 2);
    const int ec0 = n0 + nw * 32 + (lane & 3) * 2;
#pragma unroll
    for (int nt = 0; nt < 4; nt++) {
        int c = ec0 + nt * 8;
        float bv0 = bias1[c]     + (bias2 ? bias2[c]     : 0.0f);
        float bv1 = bias1[c + 1] + (bias2 ? bias2[c + 1] : 0.0f);
        *(float2*)&C[(size_t)er * ldc + c] =
            make_float2(acc[nt][0] + bv0, acc[nt][1] + bv1);
        *(float2*)&C[(size_t)(er + 8) * ldc + c] =
            make_float2(acc[nt][2] + bv0, acc[nt][3] + bv1);
    }
}

// ---------------- init ----------------
__global__ void init_k(const float* h0l, const float* h0h,
                       const float* bih, const float* bhh)
{
    int i = blockIdx.x * blockDim.x + threadIdx.x;
    if (i < B_ * NHID_) {
        d_hl[0][i] = __float2half_rn(h0l[i]);
        d_hh[0][i] = __float2half_rn(h0h[i]);
    }
    if (i < NG_) d_biasHi[i] = bih[i] + bhh[i];
}

// ---------------- launch ----------------
extern "C" void kernel_launch(void* const* d_in, const int* in_sizes, int n_in,
                              void* d_out, int out_size)
{
    const int*   tokens  = (const int*)d_in[0];
    const int*   measure = (const int*)d_in[1];
    const float* emb     = (const float*)d_in[2];
    const float* Wil     = (const float*)d_in[3];   // [4096][1536]
    const float* Whl     = (const float*)d_in[4];   // [4096][1024]
    const float* bil     = (const float*)d_in[5];
    const float* bhl     = (const float*)d_in[6];
    const float* Wih     = (const float*)d_in[7];   // [4096][1024]
    const float* Whh     = (const float*)d_in[8];   // [4096][1024]
    const float* bih     = (const float*)d_in[9];
    const float* bhh     = (const float*)d_in[10];
    const float* Wd      = (const float*)d_in[11];  // [2048][1024]
    const float* bd      = (const float*)d_in[12];
    const float* h0l     = (const float*)d_in[13];
    const float* c0l     = (const float*)d_in[14];
    const float* h0h     = (const float*)d_in[15];
    const float* c0h     = (const float*)d_in[16];
    float* out = (float*)d_out;

    void* p;
    cudaGetSymbolAddress(&p, d_P);   float* Pp  = (float*)p;
    cudaGetSymbolAddress(&p, d_hs);  float* hsP = (float*)p;
    cudaGetSymbolAddress(&p, d_Wph); uint4* WpP = (uint4*)p;

    init_k<<<256, 256>>>(h0l, h0h, bih, bhh);

    // frag-pack recurrent weights to fp16
    prepack_h_k<<<dim3(64, NB_), 128>>>(Wil, NINP_ + NHID_, NINP_,
                                        Whl, NHID_, WpP);
    prepack_h_k<<<dim3(64, NB_), 128>>>(Wih, NHID_, 0,
                                        Whh, NHID_, WpP + (size_t)NB_ * WQH_);

    // P[v][j] = emb[v,:512] @ W_ih_low[j,:512]^T + b_ih_low[j] + b_hh_low[j]
    gemm_k<0><<<dim3(NG_ / 64, NTOK_ / 64), 256>>>(
        emb, NINP_, Wil, NINP_ + NHID_, bil, bhl, Pp, NG_, NINP_);

    // entire 512-step recurrence in one persistent kernel (41 KB dyn smem)
    cudaFuncSetAttribute(hrnn_persist,
                         cudaFuncAttributeMaxDynamicSharedMemorySize, 41984);
    hrnn_persist<<<NB_, 256, 41984>>>(tokens, measure, c0l, c0h, out, out_size);

    // decode: out[b*T+t][n] = hs[t][b][:] @ W_dec[n][:]^T + b_dec[n]
    gemm_k<1><<<dim3(NTOK_ / 64, (B_ * T_) / 64), 256>>>(
        hsP, 0, Wd, NHID_, bd, (const float*)0, out, NTOK_, NHID_);
}

// round 14
// speedup vs baseline: 1.9107x; 1.0932x over previous
#include <cuda_runtime.h>
#include <cuda_fp16.h>
#include <math.h>

#define B_    64
#define T_    512
#define NHID_ 1024
#define NG_   4096
#define NTOK_ 2048
#define NINP_ 512
#define NB_   128            // persistent CTAs (one per 8 hidden units)
#define WQH_  8192ULL        // packed-W uint4 per (phase, ub): 4 kw * 32 chunks * 64

// ---------------- device scratch (static: no allocations) ----------------
__device__ float  d_P[(size_t)NTOK_ * NG_];       // 32 MB per-token low-gate base
__device__ __half d_hl[2][B_ * NHID_];            // h state, fp16
__device__ __half d_hh[2][B_ * NHID_];
__device__ float  d_hs[(size_t)T_ * B_ * NHID_];  // h_low per step (fp32, for decode)
__device__ float  d_biasHi[NG_];
__device__ uint4  d_Wph[2ULL * NB_ * WQH_];       // 32 MB frag-packed fp16 weights
__device__ unsigned g_cnt;
__device__ unsigned g_gen;

// ---------------- helpers ----------------
__device__ __forceinline__ unsigned tf(float f) {
    unsigned u;
    asm("cvt.rna.tf32.f32 %0, %1;" : "=r"(u) : "f"(f));
    return u;
}
__device__ __forceinline__ uint4 tf4(float4 v) {
    return make_uint4(tf(v.x), tf(v.y), tf(v.z), tf(v.w));
}

__device__ __forceinline__ void mma_tf32(float* d, const unsigned* a,
                                         unsigned b0, unsigned b1) {
    asm volatile(
        "mma.sync.aligned.m16n8k8.row.col.f32.tf32.tf32.f32 "
        "{%0,%1,%2,%3},{%4,%5,%6,%7},{%8,%9},{%0,%1,%2,%3};\n"
        : "+f"(d[0]), "+f"(d[1]), "+f"(d[2]), "+f"(d[3])
        : "r"(a[0]), "r"(a[1]), "r"(a[2]), "r"(a[3]), "r"(b0), "r"(b1));
}

__device__ __forceinline__ void mma_f16(float* d, const unsigned* a,
                                        unsigned b0, unsigned b1) {
    asm volatile(
        "mma.sync.aligned.m16n8k16.row.col.f32.f16.f16.f32 "
        "{%0,%1,%2,%3},{%4,%5,%6,%7},{%8,%9},{%0,%1,%2,%3};\n"
        : "+f"(d[0]), "+f"(d[1]), "+f"(d[2]), "+f"(d[3])
        : "r"(a[0]), "r"(a[1]), "r"(a[2]), "r"(a[3]), "r"(b0), "r"(b1));
}

__device__ __forceinline__ float sigm(float x) { return 1.0f / (1.0f + expf(-x)); }

__device__ __forceinline__ unsigned s2u(const void* p) {
    return (unsigned)__cvta_generic_to_shared(p);
}
__device__ __forceinline__ void cpa16(unsigned sa, const void* g) {
    asm volatile("cp.async.cg.shared.global [%0], [%1], 16;" :: "r"(sa), "l"(g));
}
__device__ __forceinline__ void cpa_commit() {
    asm volatile("cp.async.commit_group;" ::: "memory");
}
template <int N>
__device__ __forceinline__ void cpa_wait() {
    asm volatile("cp.async.wait_group %0;" :: "n"(N) : "memory");
}
__device__ __forceinline__ unsigned h2u(float a, float b) {
    __half2 h = __floats2half2_rn(a, b);
    return *reinterpret_cast<unsigned*>(&h);
}

// Grid-wide barrier
__device__ __forceinline__ void gridbar() {
    __threadfence();
    __syncthreads();
    if (threadIdx.x == 0) {
        unsigned gen = *(volatile unsigned*)&g_gen;
        unsigned prev = atomicAdd(&g_cnt, 1u);
        if (prev == NB_ - 1) {
            atomicExch(&g_cnt, 0u);
            __threadfence();
            atomicExch(&g_gen, gen + 1u);
        } else {
            while (*(volatile unsigned*)&g_gen == gen) __nanosleep(32);
        }
    }
    __syncthreads();
}

// ---------------- weight prepack: fp16 frag-quads, per-kw K-quarters -----
// Consumer warp (mw, kw) chunk c (c = 0..31, k16 within kw's K-quarter):
//   wq = base + ub*WQH_ + kw*2048 + c*64; lane l loads wq[l], wq[32+l].
// uint4 j (j = 0,1), lane l: { p0(2j), p1(2j), p0(2j+1), p1(2j+1) } with
//   p0(nt) = half2{ W[n][k],   W[n][k+1] }, p1(nt) = half2{ W[n][k+8], W[n][k+9] },
//   n = nt*8 + (l>>2)  (gate-col 0..31),
//   k = kw*512 + c*16 + (l&3)*2.
// Gate-col n: gate g = n>>3, unit u = n&7 -> W row = g*NHID + ub*8 + u.
__global__ void __launch_bounds__(64) prepack_h_k(
    const float* __restrict__ W0, int ldw0, int col0,   // k < 1024 source
    const float* __restrict__ W1, int ldw1,             // k >= 1024 source
    uint4* __restrict__ outp)                           // phase base
{
    const int c = blockIdx.x, ub = blockIdx.y, kw = blockIdx.z;
    const int t = threadIdx.x, lane = t & 31, j = t >> 5;
    const int k = kw * 512 + c * 16 + (lane & 3) * 2;
    unsigned r[4];
#pragma unroll
    for (int h = 0; h < 2; h++) {
        const int n = (2 * j + h) * 8 + (lane >> 2);
        const size_t row = (size_t)(n >> 3) * NHID_ + ub * 8 + (n & 7);
        float v0, v1, v8, v9;
        if (k < 1024) {
            const float* s = W0 + row * ldw0 + col0 + k;
            v0 = s[0]; v1 = s[1]; v8 = s[8]; v9 = s[9];
        } else {
            const float* s = W1 + row * ldw1 + (k - 1024);
            v0 = s[0]; v1 = s[1]; v8 = s[8]; v9 = s[9];
        }
        r[h * 2]     = h2u(v0, v1);
        r[h * 2 + 1] = h2u(v8, v9);
    }
    outp[(size_t)ub * WQH_ + (size_t)kw * 2048 + (size_t)c * 64 + j * 32 + lane] =
        make_uint4(r[0], r[1], r[2], r[3]);
}

// ---------------- warp-private chunk body (S = stage = c % 4) ------------
// Warp stages ONLY its 16-row x 16-k A slice (512 B = 32 lanes x 16 B).
// NO CTA barriers in the mainloop; per-warp cp.async wait + __syncwarp.
template <int S>
__device__ __forceinline__ void chunk_body(
    int c,
    __half (*Asw)[16][24], uint4 (&w4)[4][2], float (&acc)[4][4],
    const __half* __restrict__ Am,       // warp-fixed A source
    const uint4* __restrict__ wq,
    size_t aoff, int srowL, int scol, int lane)
{
    constexpr int SN = (S + 3) & 3;
    // W prefetch: chunk c+3 -> slot SN
    if (c + 3 < 32) {
        const uint4* wc = wq + (size_t)(c + 3) * 64;
        w4[SN][0] = __ldg(wc);
        w4[SN][1] = __ldg(wc + 32);
    }
    cpa_wait<2>();       // this warp's chunk-c slice resident
    __syncwarp();
    // issue A chunk c+3 slice -> warp stage SN; commit unconditionally
    {
        const int kn = c + 3;
        if (kn < 32)
            cpa16(s2u(&Asw[SN][srowL][scol]), Am + (size_t)kn * 16 + aoff);
        cpa_commit();
    }
    // compute chunk c from stage S: one k16 slab, 4 n8 tiles
    {
        const int ar = lane >> 2;
        const int ak = (lane & 3) * 2;
        unsigned a[4];
        a[0] = *(const unsigned*)&Asw[S][ar][ak];
        a[1] = *(const unsigned*)&Asw[S][ar + 8][ak];
        a[2] = *(const unsigned*)&Asw[S][ar][ak + 8];
        a[3] = *(const unsigned*)&Asw[S][ar + 8][ak + 8];
        mma_f16(acc[0], a, w4[S][0].x, w4[S][0].y);
        mma_f16(acc[1], a, w4[S][0].z, w4[S][0].w);
        mma_f16(acc[2], a, w4[S][1].x, w4[S][1].y);
        mma_f16(acc[3], a, w4[S][1].z, w4[S][1].w);
    }
}

// ---------------- gate GEMM for one phase (16 warps: 4 mw x 4 kw) --------
// sg4[kw][64 batch][34] partial gates; caller sums sg4[0..3].
__device__ __forceinline__ void gemm_phase(
    __half* AsBase, float (*sg4)[64][34],
    const __half* __restrict__ A0, const __half* __restrict__ A1,
    const uint4* __restrict__ Wq)     // (phase, ub) base
{
    const int tid = threadIdx.x, lane = tid & 31, wid = tid >> 5;
    const int kw = wid & 3, mw = wid >> 2;

    // warp-private staging region: [4 stages][16 rows][24 halfs]
    __half (*Asw)[16][24] =
        reinterpret_cast<__half(*)[16][24]>(AsBase + (size_t)wid * (4 * 16 * 24));

    // warp-fixed A source: kw 0,1 -> A0 halves; kw 2,3 -> A1 halves
    const __half* Am = (kw < 2) ? A0 : A1;
    const int akoff = (kw & 1) * 512;

    const int srowL = lane >> 1;
    const int scol  = (lane & 1) * 8;
    const size_t aoff = (size_t)(mw * 16 + srowL) * NHID_ + akoff + scol;

    const uint4* wq = Wq + (size_t)kw * 2048 + lane;

    // prologue: A slices of chunks 0,1,2; W chunks 0,1,2 into reg slots
#pragma unroll
    for (int s = 0; s < 3; s++) {
        cpa16(s2u(&Asw[s][srowL][scol]), Am + (size_t)s * 16 + aoff);
        cpa_commit();
    }
    uint4 w4[4][2];
#pragma unroll
    for (int s = 0; s < 3; s++) {
        w4[s][0] = __ldg(wq + (size_t)s * 64);
        w4[s][1] = __ldg(wq + (size_t)s * 64 + 32);
    }

    float acc[4][4] = {};
    for (int kb = 0; kb < 8; kb++) {
        chunk_body<0>(kb * 4,     Asw, w4, acc, Am, wq, aoff, srowL, scol, lane);
        chunk_body<1>(kb * 4 + 1, Asw, w4, acc, Am, wq, aoff, srowL, scol, lane);
        chunk_body<2>(kb * 4 + 2, Asw, w4, acc, Am, wq, aoff, srowL, scol, lane);
        chunk_body<3>(kb * 4 + 3, Asw, w4, acc, Am, wq, aoff, srowL, scol, lane);
    }

    // dump partials: sg4[kw][batch row][gate-col]
    {
        const int er = mw * 16 + (lane >> 2);
        const int ec = (lane & 3) * 2;
#pragma unroll
        for (int nt = 0; nt < 4; nt++) {
            const int cc = nt * 8 + ec;
            *(float2*)&sg4[kw][er][cc]     = make_float2(acc[nt][0], acc[nt][1]);
            *(float2*)&sg4[kw][er + 8][cc] = make_float2(acc[nt][2], acc[nt][3]);
        }
    }
    __syncthreads();   // the ONLY CTA barrier in the phase
}

// ---------------- persistent recurrence kernel (512 threads) -------------
__global__ void __launch_bounds__(512, 1) hrnn_persist(
    const int* __restrict__ tokens, const int* __restrict__ measure,
    const float* __restrict__ c0l, const float* __restrict__ c0h,
    float* __restrict__ out, int out_size)
{
    extern __shared__ char dsm[];
    __half* AsBase = reinterpret_cast<__half*>(dsm);                         // 49152 B
    float (*sg4)[64][34] = reinterpret_cast<float(*)[64][34]>(dsm + 49152);  // 34816 B

    const int tid = threadIdx.x;
    const int ub = blockIdx.x;
    const int u0 = ub * 8;
    const uint4* WqL = d_Wph + (size_t)ub * WQH_;
    const uint4* WqH = d_Wph + (size_t)(NB_ + ub) * WQH_;

    __half* hl0 = d_hl[0]; __half* hl1 = d_hl[1];
    __half* hh0 = d_hh[0]; __half* hh1 = d_hh[1];

    // epilogue: exactly one (b, u) pair per thread
    const int b = tid >> 3;
    const int uA = tid & 7;
    const int unit = u0 + uA;

    float cl = c0l[b * NHID_ + unit];
    float ch = c0h[b * NHID_ + unit];
    float bv[4];
#pragma unroll
    for (int g = 0; g < 4; g++) bv[g] = __ldg(&d_biasHi[g * NHID_ + unit]);
    const int mval = *measure;

    for (int t = 0; t < T_; t++) {
        __half* hlA = (t & 1) ? hl1 : hl0;
        __half* hlN = (t & 1) ? hl0 : hl1;
        __half* hhA = (t & 1) ? hh1 : hh0;
        __half* hhN = (t & 1) ? hh0 : hh1;

        // prefetch epilogue operands for the low phase
        const int tok = __ldg(&tokens[b * T_ + t]);
        float pv[4];
        {
            const float* bp = d_P + (size_t)tok * NG_ + unit;
#pragma unroll
            for (int g = 0; g < 4; g++) pv[g] = __ldg(bp + g * NHID_);
        }

        // ---- low cell: inp = [emb(tok) | h_h]; emb folded into d_P ----
        gemm_phase(AsBase, sg4, hhA, hlA, WqL);
        {
            float gi = sg4[0][b][uA]      + sg4[1][b][uA]
                     + sg4[2][b][uA]      + sg4[3][b][uA]      + pv[0];
            float gf = sg4[0][b][8 + uA]  + sg4[1][b][8 + uA]
                     + sg4[2][b][8 + uA]  + sg4[3][b][8 + uA]  + pv[1];
            float gg = sg4[0][b][16 + uA] + sg4[1][b][16 + uA]
                     + sg4[2][b][16 + uA] + sg4[3][b][16 + uA] + pv[2];
            float go = sg4[0][b][24 + uA] + sg4[1][b][24 + uA]
                     + sg4[2][b][24 + uA] + sg4[3][b][24 + uA] + pv[3];
            float cn = sigm(gf) * cl + sigm(gi) * tanhf(gg);
            float hn = sigm(go) * tanhf(cn);
            cl = cn;
            hlN[b * NHID_ + unit] = __float2half_rn(hn);
            d_hs[((size_t)t * B_ + b) * NHID_ + unit] = hn;
        }
        gridbar();

        // prefetch kept-path previous high h
        const __half hp = __ldcg(&hhA[b * NHID_ + unit]);

        // ---- high cell: masked update ----
        gemm_phase(AsBase, sg4, hlN, hhA, WqH);
        {
            float gi = sg4[0][b][uA]      + sg4[1][b][uA]
                     + sg4[2][b][uA]      + sg4[3][b][uA]      + bv[0];
            float gf = sg4[0][b][8 + uA]  + sg4[1][b][8 + uA]
                     + sg4[2][b][8 + uA]  + sg4[3][b][8 + uA]  + bv[1];
            float gg = sg4[0][b][16 + uA] + sg4[1][b][16 + uA]
                     + sg4[2][b][16 + uA] + sg4[3][b][16 + uA] + bv[2];
            float go = sg4[0][b][24 + uA] + sg4[1][b][24 + uA]
                     + sg4[2][b][24 + uA] + sg4[3][b][24 + uA] + bv[3];
            float cn = sigm(gf) * ch + sigm(gi) * tanhf(gg);
            float hn = sigm(go) * tanhf(cn);
            bool m = (tok == mval);
            ch = m ? cn : ch;
            hhN[b * NHID_ + unit] = m ? __float2half_rn(hn) : hp;
        }
        gridbar();
    }

    // final states (t=511 wrote ping 0); c still exact in registers
    size_t q = (size_t)B_ * T_ * NTOK_;
    size_t S = (size_t)B_ * NHID_;
    if ((size_t)out_size >= q + 4 * S) {
        size_t o = (size_t)b * NHID_ + unit;
        out[q + o]         = __half2float(__ldcg(&hl0[o]));
        out[q + S + o]     = cl;
        out[q + 2 * S + o] = __half2float(__ldcg(&hh0[o]));
        out[q + 3 * S + o] = ch;
    }
}

// ---------------- generic tf32 GEMM: C[MxN] = A[MxK] @ Bw[N,K]^T + bias ----
template <int REMAP>
__global__ void __launch_bounds__(256) gemm_k(
    const float* __restrict__ A, int lda,
    const float* __restrict__ Bw, int ldb,
    const float* __restrict__ bias1, const float* __restrict__ bias2,
    float* __restrict__ C, int ldc, int K)
{
    __shared__ unsigned As[64][36];
    __shared__ unsigned Bs[64][36];

    const int tid = threadIdx.x, lane = tid & 31, wid = tid >> 5;
    const int m0 = blockIdx.y * 64, n0 = blockIdx.x * 64;

    const float* Ab;
    long as;
    if (REMAP) {
        Ab = A + ((size_t)(m0 % T_) * B_ + (m0 / T_)) * NHID_;
        as = (long)B_ * NHID_;
    } else {
        Ab = A + (size_t)m0 * lda;
        as = lda;
    }

    const int r = tid >> 3, c4 = (tid & 7) * 4;
    float4 pa0 = *(const float4*)(Ab + (long)r * as + c4);
    float4 pa1 = *(const float4*)(Ab + (long)(r + 32) * as + c4);
    float4 pb0 = *(const float4*)(Bw + (size_t)(n0 + r) * ldb + c4);
    float4 pb1 = *(const float4*)(Bw + (size_t)(n0 + r + 32) * ldb + c4);

    const int mw = wid >> 1, nw = wid & 1;
    float acc[4][4] = {};

    const int nch = K / 32;
    for (int kc = 0; kc < nch; kc++) {
        *(uint4*)&As[r][c4]      = tf4(pa0);
        *(uint4*)&As[r + 32][c4] = tf4(pa1);
        *(uint4*)&Bs[r][c4]      = tf4(pb0);
        *(uint4*)&Bs[r + 32][c4] = tf4(pb1);
        __syncthreads();
        if (kc + 1 < nch) {
            int ko = (kc + 1) * 32 + c4;
            pa0 = *(const float4*)(Ab + (long)r * as + ko);
            pa1 = *(const float4*)(Ab + (long)(r + 32) * as + ko);
            pb0 = *(const float4*)(Bw + (size_t)(n0 + r) * ldb + ko);
            pb1 = *(const float4*)(Bw + (size_t)(n0 + r + 32) * ldb + ko);
        }
#pragma unroll
        for (int kk = 0; kk < 4; kk++) {
            const int ak = kk * 8 + (lane & 3);
            const int ar = mw * 16 + (lane >> 2);
            unsigned a[4];
            a[0] = As[ar][ak];     a[1] = As[ar + 8][ak];
            a[2] = As[ar][ak + 4]; a[3] = As[ar + 8][ak + 4];
#pragma unroll
            for (int nt = 0; nt < 4; nt++) {
                const int br = nw * 32 + nt * 8 + (lane >> 2);
                mma_tf32(acc[nt], a, Bs[br][ak], Bs[br][ak + 4]);
            }
        }
        __syncthreads();
    }

    const int er = m0 + mw * 16 + (lane >> 2);
    const int ec0 = n0 + nw * 32 + (lane & 3) * 2;
#pragma unroll
    for (int nt = 0; nt < 4; nt++) {
        int c = ec0 + nt * 8;
        float bv0 = bias1[c]     + (bias2 ? bias2[c]     : 0.0f);
        float bv1 = bias1[c + 1] + (bias2 ? bias2[c + 1] : 0.0f);
        *(float2*)&C[(size_t)er * ldc + c] =
            make_float2(acc[nt][0] + bv0, acc[nt][1] + bv1);
        *(float2*)&C[(size_t)(er + 8) * ldc + c] =
            make_float2(acc[nt][2] + bv0, acc[nt][3] + bv1);
    }
}

// ---------------- init ----------------
__global__ void init_k(const float* h0l, const float* h0h,
                       const float* bih, const float* bhh)
{
    int i = blockIdx.x * blockDim.x + threadIdx.x;
    if (i < B_ * NHID_) {
        d_hl[0][i] = __float2half_rn(h0l[i]);
        d_hh[0][i] = __float2half_rn(h0h[i]);
    }
    if (i < NG_) d_biasHi[i] = bih[i] + bhh[i];
}

// ---------------- launch ----------------
extern "C" void kernel_launch(void* const* d_in, const int* in_sizes, int n_in,
                              void* d_out, int out_size)
{
    const int*   tokens  = (const int*)d_in[0];
    const int*   measure = (const int*)d_in[1];
    const float* emb     = (const float*)d_in[2];
    const float* Wil     = (const float*)d_in[3];   // [4096][1536]
    const float* Whl     = (const float*)d_in[4];   // [4096][1024]
    const float* bil     = (const float*)d_in[5];
    const float* bhl     = (const float*)d_in[6];
    const float* Wih     = (const float*)d_in[7];   // [4096][1024]
    const float* Whh     = (const float*)d_in[8];   // [4096][1024]
    const float* bih     = (const float*)d_in[9];
    const float* bhh     = (const float*)d_in[10];
    const float* Wd      = (const float*)d_in[11];  // [2048][1024]
    const float* bd      = (const float*)d_in[12];
    const float* h0l     = (const float*)d_in[13];
    const float* c0l     = (const float*)d_in[14];
    const float* h0h     = (const float*)d_in[15];
    const float* c0h     = (const float*)d_in[16];
    float* out = (float*)d_out;

    void* p;
    cudaGetSymbolAddress(&p, d_P);   float* Pp  = (float*)p;
    cudaGetSymbolAddress(&p, d_hs);  float* hsP = (float*)p;
    cudaGetSymbolAddress(&p, d_Wph); uint4* WpP = (uint4*)p;

    init_k<<<256, 256>>>(h0l, h0h, bih, bhh);

    // frag-pack recurrent weights to fp16 (per-kw K-quarters)
    prepack_h_k<<<dim3(32, NB_, 4), 64>>>(Wil, NINP_ + NHID_, NINP_,
                                          Whl, NHID_, WpP);
    prepack_h_k<<<dim3(32, NB_, 4), 64>>>(Wih, NHID_, 0,
                                          Whh, NHID_, WpP + (size_t)NB_ * WQH_);

    // P[v][j] = emb[v,:512] @ W_ih_low[j,:512]^T + b_ih_low[j] + b_hh_low[j]
    gemm_k<0><<<dim3(NG_ / 64, NTOK_ / 64), 256>>>(
        emb, NINP_, Wil, NINP_ + NHID_, bil, bhl, Pp, NG_, NINP_);

    // entire 512-step recurrence in one persistent kernel (84 KB dyn smem)
    cudaFuncSetAttribute(hrnn_persist,
                         cudaFuncAttributeMaxDynamicSharedMemorySize, 84480);
    hrnn_persist<<<NB_, 512, 83968>>>(tokens, measure, c0l, c0h, out, out_size);

    // decode: out[b*T+t][n] = hs[t][b][:] @ W_dec[n][:]^T + b_dec[n]
    gemm_k<1><<<dim3(NTOK_ / 64, (B_ * T_) / 64), 256>>>(
        hsP, 0, Wd, NHID_, bd, (const float*)0, out, NTOK_, NHID_);
}

// round 15
// speedup vs baseline: 3.3271x; 1.7413x over previous
#include <cuda_runtime.h>
#include <cuda_fp16.h>
#include <math.h>

#define B_    64
#define T_    512
#define NHID_ 1024
#define NG_   4096
#define NTOK_ 2048
#define NINP_ 512
#define NB_   128            // persistent CTAs (one per 8 hidden units)
#define WQH_  8192ULL        // packed-W uint4 per (phase, ub): 4 kw * 32 chunks * 64

// ---------------- device scratch (static: no allocations) ----------------
__device__ float  d_P[(size_t)NTOK_ * NG_];       // 32 MB per-token low-gate base
__device__ __half d_hl[2][B_ * NHID_];            // h state, fp16
__device__ __half d_hh[2][B_ * NHID_];
__device__ float  d_hs[(size_t)T_ * B_ * NHID_];  // h_low per step (fp32, for decode)
__device__ float  d_biasHi[NG_];
__device__ uint4  d_Wph[2ULL * NB_ * WQH_];       // 32 MB frag-packed fp16 weights
__device__ int    d_flag[T_];                     // step needs high-cell update?
__device__ unsigned g_cnt;
__device__ unsigned g_gen;

// ---------------- helpers ----------------
__device__ __forceinline__ unsigned tf(float f) {
    unsigned u;
    asm("cvt.rna.tf32.f32 %0, %1;" : "=r"(u) : "f"(f));
    return u;
}
__device__ __forceinline__ uint4 tf4(float4 v) {
    return make_uint4(tf(v.x), tf(v.y), tf(v.z), tf(v.w));
}

__device__ __forceinline__ void mma_tf32(float* d, const unsigned* a,
                                         unsigned b0, unsigned b1) {
    asm volatile(
        "mma.sync.aligned.m16n8k8.row.col.f32.tf32.tf32.f32 "
        "{%0,%1,%2,%3},{%4,%5,%6,%7},{%8,%9},{%0,%1,%2,%3};\n"
        : "+f"(d[0]), "+f"(d[1]), "+f"(d[2]), "+f"(d[3])
        : "r"(a[0]), "r"(a[1]), "r"(a[2]), "r"(a[3]), "r"(b0), "r"(b1));
}

__device__ __forceinline__ void mma_f16(float* d, const unsigned* a,
                                        unsigned b0, unsigned b1) {
    asm volatile(
        "mma.sync.aligned.m16n8k16.row.col.f32.f16.f16.f32 "
        "{%0,%1,%2,%3},{%4,%5,%6,%7},{%8,%9},{%0,%1,%2,%3};\n"
        : "+f"(d[0]), "+f"(d[1]), "+f"(d[2]), "+f"(d[3])
        : "r"(a[0]), "r"(a[1]), "r"(a[2]), "r"(a[3]), "r"(b0), "r"(b1));
}

__device__ __forceinline__ float sigm(float x) { return 1.0f / (1.0f + expf(-x)); }

__device__ __forceinline__ unsigned s2u(const void* p) {
    return (unsigned)__cvta_generic_to_shared(p);
}
__device__ __forceinline__ void cpa16(unsigned sa, const void* g) {
    asm volatile("cp.async.cg.shared.global [%0], [%1], 16;" :: "r"(sa), "l"(g));
}
__device__ __forceinline__ void cpa_commit() {
    asm volatile("cp.async.commit_group;" ::: "memory");
}
template <int N>
__device__ __forceinline__ void cpa_wait() {
    asm volatile("cp.async.wait_group %0;" :: "n"(N) : "memory");
}
__device__ __forceinline__ unsigned h2u(float a, float b) {
    __half2 h = __floats2half2_rn(a, b);
    return *reinterpret_cast<unsigned*>(&h);
}

// Grid-wide barrier
__device__ __forceinline__ void gridbar() {
    __threadfence();
    __syncthreads();
    if (threadIdx.x == 0) {
        unsigned gen = *(volatile unsigned*)&g_gen;
        unsigned prev = atomicAdd(&g_cnt, 1u);
        if (prev == NB_ - 1) {
            atomicExch(&g_cnt, 0u);
            __threadfence();
            atomicExch(&g_gen, gen + 1u);
        } else {
            while (*(volatile unsigned*)&g_gen == gen) __nanosleep(32);
        }
    }
    __syncthreads();
}

// ---------------- weight prepack: fp16 frag-quads, per-kw K-quarters -----
__global__ void __launch_bounds__(64) prepack_h_k(
    const float* __restrict__ W0, int ldw0, int col0,   // k < 1024 source
    const float* __restrict__ W1, int ldw1,             // k >= 1024 source
    uint4* __restrict__ outp)                           // phase base
{
    const int c = blockIdx.x, ub = blockIdx.y, kw = blockIdx.z;
    const int t = threadIdx.x, lane = t & 31, j = t >> 5;
    const int k = kw * 512 + c * 16 + (lane & 3) * 2;
    unsigned r[4];
#pragma unroll
    for (int h = 0; h < 2; h++) {
        const int n = (2 * j + h) * 8 + (lane >> 2);
        const size_t row = (size_t)(n >> 3) * NHID_ + ub * 8 + (n & 7);
        float v0, v1, v8, v9;
        if (k < 1024) {
            const float* s = W0 + row * ldw0 + col0 + k;
            v0 = s[0]; v1 = s[1]; v8 = s[8]; v9 = s[9];
        } else {
            const float* s = W1 + row * ldw1 + (k - 1024);
            v0 = s[0]; v1 = s[1]; v8 = s[8]; v9 = s[9];
        }
        r[h * 2]     = h2u(v0, v1);
        r[h * 2 + 1] = h2u(v8, v9);
    }
    outp[(size_t)ub * WQH_ + (size_t)kw * 2048 + (size_t)c * 64 + j * 32 + lane] =
        make_uint4(r[0], r[1], r[2], r[3]);
}

// ---------------- per-step high-cell-needed flags ----------------
__global__ void flag_k(const int* __restrict__ tokens,
                       const int* __restrict__ measure)
{
    const int t = blockIdx.x * blockDim.x + threadIdx.x;
    if (t >= T_) return;
    const int mval = *measure;
    int f = 0;
    for (int b = 0; b < B_; b++)
        f |= (tokens[b * T_ + t] == mval);
    d_flag[t] = f;
}

// ---------------- warp-private chunk body (S = stage = c % 4) ------------
template <int S>
__device__ __forceinline__ void chunk_body(
    int c,
    __half (*Asw)[16][24], uint4 (&w4)[4][2], float (&acc)[4][4],
    const __half* __restrict__ Am,       // warp-fixed A source
    const uint4* __restrict__ wq,
    size_t aoff, int srowL, int scol, int lane)
{
    constexpr int SN = (S + 3) & 3;
    if (c + 3 < 32) {
        const uint4* wc = wq + (size_t)(c + 3) * 64;
        w4[SN][0] = __ldg(wc);
        w4[SN][1] = __ldg(wc + 32);
    }
    cpa_wait<2>();
    __syncwarp();
    {
        const int kn = c + 3;
        if (kn < 32)
            cpa16(s2u(&Asw[SN][srowL][scol]), Am + (size_t)kn * 16 + aoff);
        cpa_commit();
    }
    {
        const int ar = lane >> 2;
        const int ak = (lane & 3) * 2;
        unsigned a[4];
        a[0] = *(const unsigned*)&Asw[S][ar][ak];
        a[1] = *(const unsigned*)&Asw[S][ar + 8][ak];
        a[2] = *(const unsigned*)&Asw[S][ar][ak + 8];
        a[3] = *(const unsigned*)&Asw[S][ar + 8][ak + 8];
        mma_f16(acc[0], a, w4[S][0].x, w4[S][0].y);
        mma_f16(acc[1], a, w4[S][0].z, w4[S][0].w);
        mma_f16(acc[2], a, w4[S][1].x, w4[S][1].y);
        mma_f16(acc[3], a, w4[S][1].z, w4[S][1].w);
    }
}

// ---------------- gate GEMM for one phase (16 warps: 4 mw x 4 kw) --------
__device__ __forceinline__ void gemm_phase(
    __half* AsBase, float (*sg4)[64][34],
    const __half* __restrict__ A0, const __half* __restrict__ A1,
    const uint4* __restrict__ Wq)
{
    const int tid = threadIdx.x, lane = tid & 31, wid = tid >> 5;
    const int kw = wid & 3, mw = wid >> 2;

    __half (*Asw)[16][24] =
        reinterpret_cast<__half(*)[16][24]>(AsBase + (size_t)wid * (4 * 16 * 24));

    const __half* Am = (kw < 2) ? A0 : A1;
    const int akoff = (kw & 1) * 512;

    const int srowL = lane >> 1;
    const int scol  = (lane & 1) * 8;
    const size_t aoff = (size_t)(mw * 16 + srowL) * NHID_ + akoff + scol;

    const uint4* wq = Wq + (size_t)kw * 2048 + lane;

#pragma unroll
    for (int s = 0; s < 3; s++) {
        cpa16(s2u(&Asw[s][srowL][scol]), Am + (size_t)s * 16 + aoff);
        cpa_commit();
    }
    uint4 w4[4][2];
#pragma unroll
    for (int s = 0; s < 3; s++) {
        w4[s][0] = __ldg(wq + (size_t)s * 64);
        w4[s][1] = __ldg(wq + (size_t)s * 64 + 32);
    }

    float acc[4][4] = {};
    for (int kb = 0; kb < 8; kb++) {
        chunk_body<0>(kb * 4,     Asw, w4, acc, Am, wq, aoff, srowL, scol, lane);
        chunk_body<1>(kb * 4 + 1, Asw, w4, acc, Am, wq, aoff, srowL, scol, lane);
        chunk_body<2>(kb * 4 + 2, Asw, w4, acc, Am, wq, aoff, srowL, scol, lane);
        chunk_body<3>(kb * 4 + 3, Asw, w4, acc, Am, wq, aoff, srowL, scol, lane);
    }

    {
        const int er = mw * 16 + (lane >> 2);
        const int ec = (lane & 3) * 2;
#pragma unroll
        for (int nt = 0; nt < 4; nt++) {
            const int cc = nt * 8 + ec;
            *(float2*)&sg4[kw][er][cc]     = make_float2(acc[nt][0], acc[nt][1]);
            *(float2*)&sg4[kw][er + 8][cc] = make_float2(acc[nt][2], acc[nt][3]);
        }
    }
    __syncthreads();
}

// ---------------- persistent recurrence kernel (512 threads) -------------
__global__ void __launch_bounds__(512, 1) hrnn_persist(
    const int* __restrict__ tokens, const int* __restrict__ measure,
    const float* __restrict__ c0l, const float* __restrict__ c0h,
    float* __restrict__ out, int out_size)
{
    extern __shared__ char dsm[];
    __half* AsBase = reinterpret_cast<__half*>(dsm);                         // 49152 B
    float (*sg4)[64][34] = reinterpret_cast<float(*)[64][34]>(dsm + 49152);  // 34816 B

    const int tid = threadIdx.x;
    const int ub = blockIdx.x;
    const int u0 = ub * 8;
    const uint4* WqL = d_Wph + (size_t)ub * WQH_;
    const uint4* WqH = d_Wph + (size_t)(NB_ + ub) * WQH_;

    __half* hl0 = d_hl[0]; __half* hl1 = d_hl[1];

    const int b = tid >> 3;
    const int uA = tid & 7;
    const int unit = u0 + uA;

    float cl = c0l[b * NHID_ + unit];
    float ch = c0h[b * NHID_ + unit];
    float bv[4];
#pragma unroll
    for (int g = 0; g < 4; g++) bv[g] = __ldg(&d_biasHi[g * NHID_ + unit]);
    const int mval = *measure;

    int hp = 0;   // high-state buffer parity (uniform across grid: flips
                  // only on steps where d_flag[t] != 0)

    for (int t = 0; t < T_; t++) {
        __half* hlA = (t & 1) ? hl1 : hl0;
        __half* hlN = (t & 1) ? hl0 : hl1;
        __half* hhA = d_hh[hp];

        // prefetch epilogue operands for the low phase
        const int tok = __ldg(&tokens[b * T_ + t]);
        float pv[4];
        {
            const float* bp = d_P + (size_t)tok * NG_ + unit;
#pragma unroll
            for (int g = 0; g < 4; g++) pv[g] = __ldg(bp + g * NHID_);
        }
        const int need_high = __ldg(&d_flag[t]);

        // ---- low cell: inp = [emb(tok) | h_h]; emb folded into d_P ----
        gemm_phase(AsBase, sg4, hhA, hlA, WqL);
        {
            float gi = sg4[0][b][uA]      + sg4[1][b][uA]
                     + sg4[2][b][uA]      + sg4[3][b][uA]      + pv[0];
            float gf = sg4[0][b][8 + uA]  + sg4[1][b][8 + uA]
                     + sg4[2][b][8 + uA]  + sg4[3][b][8 + uA]  + pv[1];
            float gg = sg4[0][b][16 + uA] + sg4[1][b][16 + uA]
                     + sg4[2][b][16 + uA] + sg4[3][b][16 + uA] + pv[2];
            float go = sg4[0][b][24 + uA] + sg4[1][b][24 + uA]
                     + sg4[2][b][24 + uA] + sg4[3][b][24 + uA] + pv[3];
            float cn = sigm(gf) * cl + sigm(gi) * tanhf(gg);
            float hn = sigm(go) * tanhf(cn);
            cl = cn;
            hlN[b * NHID_ + unit] = __float2half_rn(hn);
            d_hs[((size_t)t * B_ + b) * NHID_ + unit] = hn;
        }
        gridbar();

        // ---- high cell: only when some batch row is masked this step ----
        // (otherwise h_h, c_h are bit-exactly unchanged: filt == 0 for all b)
        if (need_high) {
            __half* hhN = d_hh[hp ^ 1];
            const __half hpv = __ldcg(&hhA[b * NHID_ + unit]);

            gemm_phase(AsBase, sg4, hlN, hhA, WqH);
            {
                float gi = sg4[0][b][uA]      + sg4[1][b][uA]
                         + sg4[2][b][uA]      + sg4[3][b][uA]      + bv[0];
                float gf = sg4[0][b][8 + uA]  + sg4[1][b][8 + uA]
                         + sg4[2][b][8 + uA]  + sg4[3][b][8 + uA]  + bv[1];
                float gg = sg4[0][b][16 + uA] + sg4[1][b][16 + uA]
                         + sg4[2][b][16 + uA] + sg4[3][b][16 + uA] + bv[2];
                float go = sg4[0][b][24 + uA] + sg4[1][b][24 + uA]
                         + sg4[2][b][24 + uA] + sg4[3][b][24 + uA] + bv[3];
                float cn = sigm(gf) * ch + sigm(gi) * tanhf(gg);
                float hn = sigm(go) * tanhf(cn);
                bool m = (tok == mval);
                ch = m ? cn : ch;
                hhN[b * NHID_ + unit] = m ? __float2half_rn(hn) : hpv;
            }
            gridbar();
            hp ^= 1;
        }
    }

    // final states (t=511 wrote hl ping 0); c still exact in registers
    size_t q = (size_t)B_ * T_ * NTOK_;
    size_t S = (size_t)B_ * NHID_;
    if ((size_t)out_size >= q + 4 * S) {
        size_t o = (size_t)b * NHID_ + unit;
        out[q + o]         = __half2float(__ldcg(&hl0[o]));
        out[q + S + o]     = cl;
        out[q + 2 * S + o] = __half2float(__ldcg(&d_hh[hp][o]));
        out[q + 3 * S + o] = ch;
    }
}

// ---------------- generic tf32 GEMM: C[MxN] = A[MxK] @ Bw[N,K]^T + bias ----
template <int REMAP>
__global__ void __launch_bounds__(256) gemm_k(
    const float* __restrict__ A, int lda,
    const float* __restrict__ Bw, int ldb,
    const float* __restrict__ bias1, const float* __restrict__ bias2,
    float* __restrict__ C, int ldc, int K)
{
    __shared__ unsigned As[64][36];
    __shared__ unsigned Bs[64][36];

    const int tid = threadIdx.x, lane = tid & 31, wid = tid >> 5;
    const int m0 = blockIdx.y * 64, n0 = blockIdx.x * 64;

    const float* Ab;
    long as;
    if (REMAP) {
        Ab = A + ((size_t)(m0 % T_) * B_ + (m0 / T_)) * NHID_;
        as = (long)B_ * NHID_;
    } else {
        Ab = A + (size_t)m0 * lda;
        as = lda;
    }

    const int r = tid >> 3, c4 = (tid & 7) * 4;
    float4 pa0 = *(const float4*)(Ab + (long)r * as + c4);
    float4 pa1 = *(const float4*)(Ab + (long)(r + 32) * as + c4);
    float4 pb0 = *(const float4*)(Bw + (size_t)(n0 + r) * ldb + c4);
    float4 pb1 = *(const float4*)(Bw + (size_t)(n0 + r + 32) * ldb + c4);

    const int mw = wid >> 1, nw = wid & 1;
    float acc[4][4] = {};

    const int nch = K / 32;
    for (int kc = 0; kc < nch; kc++) {
        *(uint4*)&As[r][c4]      = tf4(pa0);
        *(uint4*)&As[r + 32][c4] = tf4(pa1);
        *(uint4*)&Bs[r][c4]      = tf4(pb0);
        *(uint4*)&Bs[r + 32][c4] = tf4(pb1);
        __syncthreads();
        if (kc + 1 < nch) {
            int ko = (kc + 1) * 32 + c4;
            pa0 = *(const float4*)(Ab + (long)r * as + ko);
            pa1 = *(const float4*)(Ab + (long)(r + 32) * as + ko);
            pb0 = *(const float4*)(Bw + (size_t)(n0 + r) * ldb + ko);
            pb1 = *(const float4*)(Bw + (size_t)(n0 + r + 32) * ldb + ko);
        }
#pragma unroll
        for (int kk = 0; kk < 4; kk++) {
            const int ak = kk * 8 + (lane & 3);
            const int ar = mw * 16 + (lane >> 2);
            unsigned a[4];
            a[0] = As[ar][ak];     a[1] = As[ar + 8][ak];
            a[2] = As[ar][ak + 4]; a[3] = As[ar + 8][ak + 4];
#pragma unroll
            for (int nt = 0; nt < 4; nt++) {
                const int br = nw * 32 + nt * 8 + (lane >> 2);
                mma_tf32(acc[nt], a, Bs[br][ak], Bs[br][ak + 4]);
            }
        }
        __syncthreads();
    }

    const int er = m0 + mw * 16 + (lane >> 2);
    const int ec0 = n0 + nw * 32 + (lane & 3) * 2;
#pragma unroll
    for (int nt = 0; nt < 4; nt++) {
        int c = ec0 + nt * 8;
        float bv0 = bias1[c]     + (bias2 ? bias2[c]     : 0.0f);
        float bv1 = bias1[c + 1] + (bias2 ? bias2[c + 1] : 0.0f);
        *(float2*)&C[(size_t)er * ldc + c] =
            make_float2(acc[nt][0] + bv0, acc[nt][1] + bv1);
        *(float2*)&C[(size_t)(er + 8) * ldc + c] =
            make_float2(acc[nt][2] + bv0, acc[nt][3] + bv1);
    }
}

// ---------------- init ----------------
__global__ void init_k(const float* h0l, const float* h0h,
                       const float* bih, const float* bhh)
{
    int i = blockIdx.x * blockDim.x + threadIdx.x;
    if (i < B_ * NHID_) {
        d_hl[0][i] = __float2half_rn(h0l[i]);
        d_hh[0][i] = __float2half_rn(h0h[i]);
    }
    if (i < NG_) d_biasHi[i] = bih[i] + bhh[i];
}

// ---------------- launch ----------------
extern "C" void kernel_launch(void* const* d_in, const int* in_sizes, int n_in,
                              void* d_out, int out_size)
{
    const int*   tokens  = (const int*)d_in[0];
    const int*   measure = (const int*)d_in[1];
    const float* emb     = (const float*)d_in[2];
    const float* Wil     = (const float*)d_in[3];   // [4096][1536]
    const float* Whl     = (const float*)d_in[4];   // [4096][1024]
    const float* bil     = (const float*)d_in[5];
    const float* bhl     = (const float*)d_in[6];
    const float* Wih     = (const float*)d_in[7];   // [4096][1024]
    const float* Whh     = (const float*)d_in[8];   // [4096][1024]
    const float* bih     = (const float*)d_in[9];
    const float* bhh     = (const float*)d_in[10];
    const float* Wd      = (const float*)d_in[11];  // [2048][1024]
    const float* bd      = (const float*)d_in[12];
    const float* h0l     = (const float*)d_in[13];
    const float* c0l     = (const float*)d_in[14];
    const float* h0h     = (const float*)d_in[15];
    const float* c0h     = (const float*)d_in[16];
    float* out = (float*)d_out;

    void* p;
    cudaGetSymbolAddress(&p, d_P);   float* Pp  = (float*)p;
    cudaGetSymbolAddress(&p, d_hs);  float* hsP = (float*)p;
    cudaGetSymbolAddress(&p, d_Wph); uint4* WpP = (uint4*)p;

    init_k<<<256, 256>>>(h0l, h0h, bih, bhh);
    flag_k<<<2, 256>>>(tokens, measure);

    // frag-pack recurrent weights to fp16 (per-kw K-quarters)
    prepack_h_k<<<dim3(32, NB_, 4), 64>>>(Wil, NINP_ + NHID_, NINP_,
                                          Whl, NHID_, WpP);
    prepack_h_k<<<dim3(32, NB_, 4), 64>>>(Wih, NHID_, 0,
                                          Whh, NHID_, WpP + (size_t)NB_ * WQH_);

    // P[v][j] = emb[v,:512] @ W_ih_low[j,:512]^T + b_ih_low[j] + b_hh_low[j]
    gemm_k<0><<<dim3(NG_ / 64, NTOK_ / 64), 256>>>(
        emb, NINP_, Wil, NINP_ + NHID_, bil, bhl, Pp, NG_, NINP_);

    // entire 512-step recurrence in one persistent kernel (84 KB dyn smem)
    cudaFuncSetAttribute(hrnn_persist,
                         cudaFuncAttributeMaxDynamicSharedMemorySize, 84480);
    hrnn_persist<<<NB_, 512, 83968>>>(tokens, measure, c0l, c0h, out, out_size);

    // decode: out[b*T+t][n] = hs[t][b][:] @ W_dec[n][:]^T + b_dec[n]
    gemm_k<1><<<dim3(NTOK_ / 64, (B_ * T_) / 64), 256>>>(
        hsP, 0, Wd, NHID_, bd, (const float*)0, out, NTOK_, NHID_);
}

// round 16
// speedup vs baseline: 4.9480x; 1.4872x over previous
#include <cuda_runtime.h>
#include <cuda_fp16.h>
#include <math.h>

#define B_    64
#define T_    512
#define NHID_ 1024
#define NG_   4096
#define NTOK_ 2048
#define NINP_ 512
#define NB_   128            // persistent CTAs (one per 8 hidden units)
#define WQH_  8192ULL        // packed-W uint4 per (phase, ub): 4 kw * 32 chunks * 64

// ---------------- device scratch (static: no allocations) ----------------
__device__ float  d_P[(size_t)NTOK_ * NG_];       // 32 MB per-token low-gate base
// h state in FRAGMENT layout: [mg=row/16][kchunk=unit/16][lane][uint4 frag]
// lane l's uint4 = { h2(A[r][k],A[r][k+1]), h2(A[r+8][k],..), h2(A[r][k+8],..),
//                    h2(A[r+8][k+8],..) }, r = mg*16 + (l>>2), k = c*16 + (l&3)*2
__device__ uint4  d_hlF[2][4 * 64 * 32];          // 128 KB per ping
__device__ uint4  d_hhF[2][4 * 64 * 32];
__device__ float  d_hs[(size_t)T_ * B_ * NHID_];  // h_low per step (fp32, decode)
__device__ float  d_biasHi[NG_];
__device__ uint4  d_Wph[2ULL * NB_ * WQH_];       // 32 MB frag-packed fp16 weights
__device__ int    d_flag[T_];                     // step needs high-cell update?
__device__ unsigned g_cnt;
__device__ unsigned g_gen;

// ---------------- helpers ----------------
__device__ __forceinline__ unsigned tf(float f) {
    unsigned u;
    asm("cvt.rna.tf32.f32 %0, %1;" : "=r"(u) : "f"(f));
    return u;
}
__device__ __forceinline__ uint4 tf4(float4 v) {
    return make_uint4(tf(v.x), tf(v.y), tf(v.z), tf(v.w));
}

__device__ __forceinline__ void mma_tf32(float* d, const unsigned* a,
                                         unsigned b0, unsigned b1) {
    asm volatile(
        "mma.sync.aligned.m16n8k8.row.col.f32.tf32.tf32.f32 "
        "{%0,%1,%2,%3},{%4,%5,%6,%7},{%8,%9},{%0,%1,%2,%3};\n"
        : "+f"(d[0]), "+f"(d[1]), "+f"(d[2]), "+f"(d[3])
        : "r"(a[0]), "r"(a[1]), "r"(a[2]), "r"(a[3]), "r"(b0), "r"(b1));
}

__device__ __forceinline__ void mma_f16(float* d, const unsigned* a,
                                        unsigned b0, unsigned b1) {
    asm volatile(
        "mma.sync.aligned.m16n8k16.row.col.f32.f16.f16.f32 "
        "{%0,%1,%2,%3},{%4,%5,%6,%7},{%8,%9},{%0,%1,%2,%3};\n"
        : "+f"(d[0]), "+f"(d[1]), "+f"(d[2]), "+f"(d[3])
        : "r"(a[0]), "r"(a[1]), "r"(a[2]), "r"(a[3]), "r"(b0), "r"(b1));
}

__device__ __forceinline__ float sigm(float x) { return 1.0f / (1.0f + expf(-x)); }

__device__ __forceinline__ unsigned h2u(float a, float b) {
    __half2 h = __floats2half2_rn(a, b);
    return *reinterpret_cast<unsigned*>(&h);
}

// byte offset of element (b, unit) inside a frag-layout h array
__device__ __forceinline__ size_t frag_off(int b, int unit) {
    const int mg = b >> 4, r = b & 15;
    const int c = unit >> 4, klo = unit & 15;
    const int lane = (r & 7) * 4 + ((klo & 7) >> 1);
    const int aidx = ((klo >> 3) << 1) + (r >> 3);
    return ((((size_t)mg * 64 + c) * 32 + lane) << 4) + aidx * 4 + ((klo & 1) << 1);
}

// Grid-wide barrier
__device__ __forceinline__ void gridbar() {
    __threadfence();
    __syncthreads();
    if (threadIdx.x == 0) {
        unsigned gen = *(volatile unsigned*)&g_gen;
        unsigned prev = atomicAdd(&g_cnt, 1u);
        if (prev == NB_ - 1) {
            atomicExch(&g_cnt, 0u);
            __threadfence();
            atomicExch(&g_gen, gen + 1u);
        } else {
            while (*(volatile unsigned*)&g_gen == gen) __nanosleep(32);
        }
    }
    __syncthreads();
}

// ---------------- weight prepack: fp16 frag-quads, per-kw K-quarters -----
__global__ void __launch_bounds__(64) prepack_h_k(
    const float* __restrict__ W0, int ldw0, int col0,   // k < 1024 source
    const float* __restrict__ W1, int ldw1,             // k >= 1024 source
    uint4* __restrict__ outp)                           // phase base
{
    const int c = blockIdx.x, ub = blockIdx.y, kw = blockIdx.z;
    const int t = threadIdx.x, lane = t & 31, j = t >> 5;
    const int k = kw * 512 + c * 16 + (lane & 3) * 2;
    unsigned r[4];
#pragma unroll
    for (int h = 0; h < 2; h++) {
        const int n = (2 * j + h) * 8 + (lane >> 2);
        const size_t row = (size_t)(n >> 3) * NHID_ + ub * 8 + (n & 7);
        float v0, v1, v8, v9;
        if (k < 1024) {
            const float* s = W0 + row * ldw0 + col0 + k;
            v0 = s[0]; v1 = s[1]; v8 = s[8]; v9 = s[9];
        } else {
            const float* s = W1 + row * ldw1 + (k - 1024);
            v0 = s[0]; v1 = s[1]; v8 = s[8]; v9 = s[9];
        }
        r[h * 2]     = h2u(v0, v1);
        r[h * 2 + 1] = h2u(v8, v9);
    }
    outp[(size_t)ub * WQH_ + (size_t)kw * 2048 + (size_t)c * 64 + j * 32 + lane] =
        make_uint4(r[0], r[1], r[2], r[3]);
}

// ---------------- per-step high-cell-needed flags ----------------
__global__ void flag_k(const int* __restrict__ tokens,
                       const int* __restrict__ measure)
{
    const int t = blockIdx.x * blockDim.x + threadIdx.x;
    if (t >= T_) return;
    const int mval = *measure;
    int f = 0;
    for (int b = 0; b < B_; b++)
        f |= (tokens[b * T_ + t] == mval);
    d_flag[t] = f;
}

// ---------------- chunk body: pure register-ring, no smem, no barriers ---
template <int S>
__device__ __forceinline__ void body(
    int cc, uint4 (&Ar)[4], uint4 (&w4)[4][2], float (&acc)[4][4],
    const uint4* __restrict__ aq, const uint4* __restrict__ wq)
{
    constexpr int SN = (S + 3) & 3;
    if (cc + 3 < 32) {
        w4[SN][0] = __ldg(wq + (size_t)(cc + 3) * 64);
        w4[SN][1] = __ldg(wq + (size_t)(cc + 3) * 64 + 32);
        Ar[SN]    = __ldcg(aq + (size_t)(cc + 3) * 32);
    }
    const unsigned* a = reinterpret_cast<const unsigned*>(&Ar[S]);
    mma_f16(acc[0], a, w4[S][0].x, w4[S][0].y);
    mma_f16(acc[1], a, w4[S][0].z, w4[S][0].w);
    mma_f16(acc[2], a, w4[S][1].x, w4[S][1].y);
    mma_f16(acc[3], a, w4[S][1].z, w4[S][1].w);
}

// ---------------- gate GEMM for one phase (16 warps: 4 mw x 4 kw) --------
// A read directly from frag-layout global arrays: 1 LDG.128 per chunk.
__device__ __forceinline__ void gemm_phase(
    float (*sg4)[64][34],
    const uint4* __restrict__ A0F, const uint4* __restrict__ A1F,
    const uint4* __restrict__ Wq)
{
    const int tid = threadIdx.x, lane = tid & 31, wid = tid >> 5;
    const int kw = wid & 3, mw = wid >> 2;

    const uint4* AmF = (kw < 2) ? A0F : A1F;
    const uint4* aq = AmF + ((size_t)(mw * 64 + (kw & 1) * 32) * 32 + lane);
    const uint4* wq = Wq + (size_t)kw * 2048 + lane;

    uint4 Ar[4];
    uint4 w4[4][2];
#pragma unroll
    for (int s = 0; s < 3; s++) {
        Ar[s]    = __ldcg(aq + (size_t)s * 32);
        w4[s][0] = __ldg(wq + (size_t)s * 64);
        w4[s][1] = __ldg(wq + (size_t)s * 64 + 32);
    }

    float acc[4][4] = {};
    for (int kb = 0; kb < 8; kb++) {
        body<0>(kb * 4,     Ar, w4, acc, aq, wq);
        body<1>(kb * 4 + 1, Ar, w4, acc, aq, wq);
        body<2>(kb * 4 + 2, Ar, w4, acc, aq, wq);
        body<3>(kb * 4 + 3, Ar, w4, acc, aq, wq);
    }

    // dump partials: sg4[kw][batch row][gate-col]
    {
        const int er = mw * 16 + (lane >> 2);
        const int ec = (lane & 3) * 2;
#pragma unroll
        for (int nt = 0; nt < 4; nt++) {
            const int cc = nt * 8 + ec;
            *(float2*)&sg4[kw][er][cc]     = make_float2(acc[nt][0], acc[nt][1]);
            *(float2*)&sg4[kw][er + 8][cc] = make_float2(acc[nt][2], acc[nt][3]);
        }
    }
    __syncthreads();   // the ONLY CTA barrier in the phase
}

// ---------------- persistent recurrence kernel (512 threads) -------------
__global__ void __launch_bounds__(512, 1) hrnn_persist(
    const int* __restrict__ tokens, const int* __restrict__ measure,
    const float* __restrict__ c0l, const float* __restrict__ c0h,
    float* __restrict__ out, int out_size)
{
    __shared__ float sg4[4][64][34];   // 34816 B

    const int tid = threadIdx.x;
    const int ub = blockIdx.x;
    const int u0 = ub * 8;
    const uint4* WqL = d_Wph + (size_t)ub * WQH_;
    const uint4* WqH = d_Wph + (size_t)(NB_ + ub) * WQH_;

    const int b = tid >> 3;
    const int uA = tid & 7;
    const int unit = u0 + uA;
    const size_t fo = frag_off(b, unit);   // fixed per thread

    char* hlFc[2] = { (char*)d_hlF[0], (char*)d_hlF[1] };
    char* hhFc[2] = { (char*)d_hhF[0], (char*)d_hhF[1] };

    float cl = c0l[b * NHID_ + unit];
    float ch = c0h[b * NHID_ + unit];
    float bv[4];
#pragma unroll
    for (int g = 0; g < 4; g++) bv[g] = __ldg(&d_biasHi[g * NHID_ + unit]);
    const int mval = *measure;

    int hp = 0;   // high-state parity (uniform: flips only on flagged steps)

    for (int t = 0; t < T_; t++) {
        const int lA = t & 1, lN = lA ^ 1;

        // prefetch epilogue operands for the low phase
        const int tok = __ldg(&tokens[b * T_ + t]);
        float pv[4];
        {
            const float* bp = d_P + (size_t)tok * NG_ + unit;
#pragma unroll
            for (int g = 0; g < 4; g++) pv[g] = __ldg(bp + g * NHID_);
        }
        const int need_high = __ldg(&d_flag[t]);

        // ---- low cell: A0 = h_high(frag), A1 = h_low(frag) ----
        gemm_phase(sg4, d_hhF[hp], d_hlF[lA], WqL);
        {
            float gi = sg4[0][b][uA]      + sg4[1][b][uA]
                     + sg4[2][b][uA]      + sg4[3][b][uA]      + pv[0];
            float gf = sg4[0][b][8 + uA]  + sg4[1][b][8 + uA]
                     + sg4[2][b][8 + uA]  + sg4[3][b][8 + uA]  + pv[1];
            float gg = sg4[0][b][16 + uA] + sg4[1][b][16 + uA]
                     + sg4[2][b][16 + uA] + sg4[3][b][16 + uA] + pv[2];
            float go = sg4[0][b][24 + uA] + sg4[1][b][24 + uA]
                     + sg4[2][b][24 + uA] + sg4[3][b][24 + uA] + pv[3];
            float cn = sigm(gf) * cl + sigm(gi) * tanhf(gg);
            float hn = sigm(go) * tanhf(cn);
            cl = cn;
            *(__half*)(hlFc[lN] + fo) = __float2half_rn(hn);
            d_hs[((size_t)t * B_ + b) * NHID_ + unit] = hn;
        }
        gridbar();

        // ---- high cell: only when some batch row is masked this step ----
        if (need_high) {
            const __half hpv = __ldcg((const __half*)(hhFc[hp] + fo));

            gemm_phase(sg4, d_hlF[lN], d_hhF[hp], WqH);
            {
                float gi = sg4[0][b][uA]      + sg4[1][b][uA]
                         + sg4[2][b][uA]      + sg4[3][b][uA]      + bv[0];
                float gf = sg4[0][b][8 + uA]  + sg4[1][b][8 + uA]
                         + sg4[2][b][8 + uA]  + sg4[3][b][8 + uA]  + bv[1];
                float gg = sg4[0][b][16 + uA] + sg4[1][b][16 + uA]
                         + sg4[2][b][16 + uA] + sg4[3][b][16 + uA] + bv[2];
                float go = sg4[0][b][24 + uA] + sg4[1][b][24 + uA]
                         + sg4[2][b][24 + uA] + sg4[3][b][24 + uA] + bv[3];
                float cn = sigm(gf) * ch + sigm(gi) * tanhf(gg);
                float hn = sigm(go) * tanhf(cn);
                bool m = (tok == mval);
                ch = m ? cn : ch;
                *(__half*)(hhFc[hp ^ 1] + fo) = m ? __float2half_rn(hn) : hpv;
            }
            gridbar();
            hp ^= 1;
        }
    }

    // final states (t=511 wrote hl ping 0); c still exact in registers
    size_t q = (size_t)B_ * T_ * NTOK_;
    size_t S = (size_t)B_ * NHID_;
    if ((size_t)out_size >= q + 4 * S) {
        size_t o = (size_t)b * NHID_ + unit;
        out[q + o]         = __half2float(*(const __half*)(hlFc[0] + fo));
        out[q + S + o]     = cl;
        out[q + 2 * S + o] = __half2float(*(const __half*)(hhFc[hp] + fo));
        out[q + 3 * S + o] = ch;
    }
}

// ---------------- generic tf32 GEMM: C[MxN] = A[MxK] @ Bw[N,K]^T + bias ----
template <int REMAP>
__global__ void __launch_bounds__(256) gemm_k(
    const float* __restrict__ A, int lda,
    const float* __restrict__ Bw, int ldb,
    const float* __restrict__ bias1, const float* __restrict__ bias2,
    float* __restrict__ C, int ldc, int K)
{
    __shared__ unsigned As[64][36];
    __shared__ unsigned Bs[64][36];

    const int tid = threadIdx.x, lane = tid & 31, wid = tid >> 5;
    const int m0 = blockIdx.y * 64, n0 = blockIdx.x * 64;

    const float* Ab;
    long as;
    if (REMAP) {
        Ab = A + ((size_t)(m0 % T_) * B_ + (m0 / T_)) * NHID_;
        as = (long)B_ * NHID_;
    } else {
        Ab = A + (size_t)m0 * lda;
        as = lda;
    }

    const int r = tid >> 3, c4 = (tid & 7) * 4;
    float4 pa0 = *(const float4*)(Ab + (long)r * as + c4);
    float4 pa1 = *(const float4*)(Ab + (long)(r + 32) * as + c4);
    float4 pb0 = *(const float4*)(Bw + (size_t)(n0 + r) * ldb + c4);
    float4 pb1 = *(const float4*)(Bw + (size_t)(n0 + r + 32) * ldb + c4);

    const int mw = wid >> 1, nw = wid & 1;
    float acc[4][4] = {};

    const int nch = K / 32;
    for (int kc = 0; kc < nch; kc++) {
        *(uint4*)&As[r][c4]      = tf4(pa0);
        *(uint4*)&As[r + 32][c4] = tf4(pa1);
        *(uint4*)&Bs[r][c4]      = tf4(pb0);
        *(uint4*)&Bs[r + 32][c4] = tf4(pb1);
        __syncthreads();
        if (kc + 1 < nch) {
            int ko = (kc + 1) * 32 + c4;
            pa0 = *(const float4*)(Ab + (long)r * as + ko);
            pa1 = *(const float4*)(Ab + (long)(r + 32) * as + ko);
            pb0 = *(const float4*)(Bw + (size_t)(n0 + r) * ldb + ko);
            pb1 = *(const float4*)(Bw + (size_t)(n0 + r + 32) * ldb + ko);
        }
#pragma unroll
        for (int kk = 0; kk < 4; kk++) {
            const int ak = kk * 8 + (lane & 3);
            const int ar = mw * 16 + (lane >> 2);
            unsigned a[4];
            a[0] = As[ar][ak];     a[1] = As[ar + 8][ak];
            a[2] = As[ar][ak + 4]; a[3] = As[ar + 8][ak + 4];
#pragma unroll
            for (int nt = 0; nt < 4; nt++) {
                const int br = nw * 32 + nt * 8 + (lane >> 2);
                mma_tf32(acc[nt], a, Bs[br][ak], Bs[br][ak + 4]);
            }
        }
        __syncthreads();
    }

    const int er = m0 + mw * 16 + (lane >> 2);
    const int ec0 = n0 + nw * 32 + (lane & 3) * 2;
#pragma unroll
    for (int nt = 0; nt < 4; nt++) {
        int c = ec0 + nt * 8;
        float bv0 = bias1[c]     + (bias2 ? bias2[c]     : 0.0f);
        float bv1 = bias1[c + 1] + (bias2 ? bias2[c + 1] : 0.0f);
        *(float2*)&C[(size_t)er * ldc + c] =
            make_float2(acc[nt][0] + bv0, acc[nt][1] + bv1);
        *(float2*)&C[(size_t)(er + 8) * ldc + c] =
            make_float2(acc[nt][2] + bv0, acc[nt][3] + bv1);
    }
}

// ---------------- init: scatter initial h into frag layout ----------------
__global__ void init_k(const float* h0l, const float* h0h,
                       const float* bih, const float* bhh)
{
    int i = blockIdx.x * blockDim.x + threadIdx.x;
    if (i < B_ * NHID_) {
        int b = i / NHID_, unit = i % NHID_;
        size_t fo = frag_off(b, unit);
        *(__half*)((char*)d_hlF[0] + fo) = __float2half_rn(h0l[i]);
        *(__half*)((char*)d_hhF[0] + fo) = __float2half_rn(h0h[i]);
    }
    if (i < NG_) d_biasHi[i] = bih[i] + bhh[i];
}

// ---------------- launch ----------------
extern "C" void kernel_launch(void* const* d_in, const int* in_sizes, int n_in,
                              void* d_out, int out_size)
{
    const int*   tokens  = (const int*)d_in[0];
    const int*   measure = (const int*)d_in[1];
    const float* emb     = (const float*)d_in[2];
    const float* Wil     = (const float*)d_in[3];   // [4096][1536]
    const float* Whl     = (const float*)d_in[4];   // [4096][1024]
    const float* bil     = (const float*)d_in[5];
    const float* bhl     = (const float*)d_in[6];
    const float* Wih     = (const float*)d_in[7];   // [4096][1024]
    const float* Whh     = (const float*)d_in[8];   // [4096][1024]
    const float* bih     = (const float*)d_in[9];
    const float* bhh     = (const float*)d_in[10];
    const float* Wd      = (const float*)d_in[11];  // [2048][1024]
    const float* bd      = (const float*)d_in[12];
    const float* h0l     = (const float*)d_in[13];
    const float* c0l     = (const float*)d_in[14];
    const float* h0h     = (const float*)d_in[15];
    const float* c0h     = (const float*)d_in[16];
    float* out = (float*)d_out;

    void* p;
    cudaGetSymbolAddress(&p, d_P);   float* Pp  = (float*)p;
    cudaGetSymbolAddress(&p, d_hs);  float* hsP = (float*)p;
    cudaGetSymbolAddress(&p, d_Wph); uint4* WpP = (uint4*)p;

    init_k<<<256, 256>>>(h0l, h0h, bih, bhh);
    flag_k<<<2, 256>>>(tokens, measure);

    // frag-pack recurrent weights to fp16 (per-kw K-quarters)
    prepack_h_k<<<dim3(32, NB_, 4), 64>>>(Wil, NINP_ + NHID_, NINP_,
                                          Whl, NHID_, WpP);
    prepack_h_k<<<dim3(32, NB_, 4), 64>>>(Wih, NHID_, 0,
                                          Whh, NHID_, WpP + (size_t)NB_ * WQH_);

    // P[v][j] = emb[v,:512] @ W_ih_low[j,:512]^T + b_ih_low[j] + b_hh_low[j]
    gemm_k<0><<<dim3(NG_ / 64, NTOK_ / 64), 256>>>(
        emb, NINP_, Wil, NINP_ + NHID_, bil, bhl, Pp, NG_, NINP_);

    // entire 512-step recurrence in one persistent kernel (static smem only)
    hrnn_persist<<<NB_, 512>>>(tokens, measure, c0l, c0h, out, out_size);

    // decode: out[b*T+t][n] = hs[t][b][:] @ W_dec[n][:]^T + b_dec[n]
    gemm_k<1><<<dim3(NTOK_ / 64, (B_ * T_) / 64), 256>>>(
        hsP, 0, Wd, NHID_, bd, (const float*)0, out, NTOK_, NHID_);
}

// round 17
// speedup vs baseline: 5.3972x; 1.0908x over previous
#include <cuda_runtime.h>
#include <cuda_fp16.h>
#include <math.h>

#define B_    64
#define T_    512
#define NHID_ 1024
#define NG_   4096
#define NTOK_ 2048
#define NINP_ 512
#define NB_   128            // persistent CTAs (one per 8 hidden units)
#define WQH_  8192ULL        // packed-W uint4 per (phase, ub): 4 kw * 32 chunks * 64

// ---------------- device scratch (static: no allocations) ----------------
__device__ float  d_P[(size_t)NTOK_ * NG_];       // 32 MB per-token low-gate base
// h state in FRAGMENT layout: [mg=row/16][kchunk=unit/16][lane][uint4 frag]
__device__ uint4  d_hlF[2][4 * 64 * 32];          // 128 KB per ping
__device__ uint4  d_hhF[2][4 * 64 * 32];
__device__ __half d_hs[(size_t)T_ * B_ * NHID_];  // h_low per step (fp16, decode)
__device__ float  d_biasHi[NG_];
__device__ uint4  d_Wph[2ULL * NB_ * WQH_];       // 32 MB frag-packed fp16 weights
__device__ int    d_flag[T_];                     // step needs high-cell update?
__device__ unsigned g_cnt;
__device__ unsigned g_gen;

// ---------------- helpers ----------------
__device__ __forceinline__ unsigned tf(float f) {
    unsigned u;
    asm("cvt.rna.tf32.f32 %0, %1;" : "=r"(u) : "f"(f));
    return u;
}
__device__ __forceinline__ uint4 tf4(float4 v) {
    return make_uint4(tf(v.x), tf(v.y), tf(v.z), tf(v.w));
}

__device__ __forceinline__ void mma_tf32(float* d, const unsigned* a,
                                         unsigned b0, unsigned b1) {
    asm volatile(
        "mma.sync.aligned.m16n8k8.row.col.f32.tf32.tf32.f32 "
        "{%0,%1,%2,%3},{%4,%5,%6,%7},{%8,%9},{%0,%1,%2,%3};\n"
        : "+f"(d[0]), "+f"(d[1]), "+f"(d[2]), "+f"(d[3])
        : "r"(a[0]), "r"(a[1]), "r"(a[2]), "r"(a[3]), "r"(b0), "r"(b1));
}

__device__ __forceinline__ void mma_f16(float* d, const unsigned* a,
                                        unsigned b0, unsigned b1) {
    asm volatile(
        "mma.sync.aligned.m16n8k16.row.col.f32.f16.f16.f32 "
        "{%0,%1,%2,%3},{%4,%5,%6,%7},{%8,%9},{%0,%1,%2,%3};\n"
        : "+f"(d[0]), "+f"(d[1]), "+f"(d[2]), "+f"(d[3])
        : "r"(a[0]), "r"(a[1]), "r"(a[2]), "r"(a[3]), "r"(b0), "r"(b1));
}

__device__ __forceinline__ float sigm(float x) { return 1.0f / (1.0f + expf(-x)); }

__device__ __forceinline__ unsigned h2u(float a, float b) {
    __half2 h = __floats2half2_rn(a, b);
    return *reinterpret_cast<unsigned*>(&h);
}

__device__ __forceinline__ unsigned s2u(const void* p) {
    return (unsigned)__cvta_generic_to_shared(p);
}
__device__ __forceinline__ void cpa16(unsigned sa, const void* g) {
    asm volatile("cp.async.cg.shared.global [%0], [%1], 16;" :: "r"(sa), "l"(g));
}
__device__ __forceinline__ void cpa_commit() {
    asm volatile("cp.async.commit_group;" ::: "memory");
}
template <int N>
__device__ __forceinline__ void cpa_wait() {
    asm volatile("cp.async.wait_group %0;" :: "n"(N) : "memory");
}

// byte offset of element (b, unit) inside a frag-layout h array
__device__ __forceinline__ size_t frag_off(int b, int unit) {
    const int mg = b >> 4, r = b & 15;
    const int c = unit >> 4, klo = unit & 15;
    const int lane = (r & 7) * 4 + ((klo & 7) >> 1);
    const int aidx = ((klo >> 3) << 1) + (r >> 3);
    return ((((size_t)mg * 64 + c) * 32 + lane) << 4) + aidx * 4 + ((klo & 1) << 1);
}

// Grid-wide barrier
__device__ __forceinline__ void gridbar() {
    __threadfence();
    __syncthreads();
    if (threadIdx.x == 0) {
        unsigned gen = *(volatile unsigned*)&g_gen;
        unsigned prev = atomicAdd(&g_cnt, 1u);
        if (prev == NB_ - 1) {
            atomicExch(&g_cnt, 0u);
            __threadfence();
            atomicExch(&g_gen, gen + 1u);
        } else {
            while (*(volatile unsigned*)&g_gen == gen) __nanosleep(32);
        }
    }
    __syncthreads();
}

// ---------------- weight prepack: fp16 frag-quads, per-kw K-quarters -----
__global__ void __launch_bounds__(64) prepack_h_k(
    const float* __restrict__ W0, int ldw0, int col0,   // k < 1024 source
    const float* __restrict__ W1, int ldw1,             // k >= 1024 source
    uint4* __restrict__ outp)                           // phase base
{
    const int c = blockIdx.x, ub = blockIdx.y, kw = blockIdx.z;
    const int t = threadIdx.x, lane = t & 31, j = t >> 5;
    const int k = kw * 512 + c * 16 + (lane & 3) * 2;
    unsigned r[4];
#pragma unroll
    for (int h = 0; h < 2; h++) {
        const int n = (2 * j + h) * 8 + (lane >> 2);
        const size_t row = (size_t)(n >> 3) * NHID_ + ub * 8 + (n & 7);
        float v0, v1, v8, v9;
        if (k < 1024) {
            const float* s = W0 + row * ldw0 + col0 + k;
            v0 = s[0]; v1 = s[1]; v8 = s[8]; v9 = s[9];
        } else {
            const float* s = W1 + row * ldw1 + (k - 1024);
            v0 = s[0]; v1 = s[1]; v8 = s[8]; v9 = s[9];
        }
        r[h * 2]     = h2u(v0, v1);
        r[h * 2 + 1] = h2u(v8, v9);
    }
    outp[(size_t)ub * WQH_ + (size_t)kw * 2048 + (size_t)c * 64 + j * 32 + lane] =
        make_uint4(r[0], r[1], r[2], r[3]);
}

// ---------------- per-step high-cell-needed flags ----------------
__global__ void flag_k(const int* __restrict__ tokens,
                       const int* __restrict__ measure)
{
    const int t = blockIdx.x * blockDim.x + threadIdx.x;
    if (t >= T_) return;
    const int mval = *measure;
    int f = 0;
    for (int b = 0; b < B_; b++)
        f |= (tokens[b * T_ + t] == mval);
    d_flag[t] = f;
}

// ---------------- chunk body: pure register-ring, no smem, no barriers ---
template <int S>
__device__ __forceinline__ void body(
    int cc, uint4 (&Ar)[4], uint4 (&w4)[4][2], float (&acc)[4][4],
    const uint4* __restrict__ aq, const uint4* __restrict__ wq)
{
    constexpr int SN = (S + 3) & 3;
    if (cc + 3 < 32) {
        Ar[SN]    = __ldcg(aq + (size_t)(cc + 3) * 32);   // L2 path first
        w4[SN][0] = __ldg(wq + (size_t)(cc + 3) * 64);    // L1-resident
        w4[SN][1] = __ldg(wq + (size_t)(cc + 3) * 64 + 32);
    }
    const unsigned* a = reinterpret_cast<const unsigned*>(&Ar[S]);
    mma_f16(acc[0], a, w4[S][0].x, w4[S][0].y);
    mma_f16(acc[1], a, w4[S][0].z, w4[S][0].w);
    mma_f16(acc[2], a, w4[S][1].x, w4[S][1].y);
    mma_f16(acc[3], a, w4[S][1].z, w4[S][1].w);
}

// ---------------- gate GEMM for one phase (16 warps: 4 mw x 4 kw) --------
__device__ __forceinline__ void gemm_phase(
    float (*sg4)[64][34],
    const uint4* __restrict__ A0F, const uint4* __restrict__ A1F,
    const uint4* __restrict__ Wq)
{
    const int tid = threadIdx.x, lane = tid & 31, wid = tid >> 5;
    const int kw = wid & 3, mw = wid >> 2;

    const uint4* AmF = (kw < 2) ? A0F : A1F;
    const uint4* aq = AmF + ((size_t)(mw * 64 + (kw & 1) * 32) * 32 + lane);
    const uint4* wq = Wq + (size_t)kw * 2048 + lane;

    uint4 Ar[4];
    uint4 w4[4][2];
#pragma unroll
    for (int s = 0; s < 3; s++) {
        Ar[s]    = __ldcg(aq + (size_t)s * 32);
        w4[s][0] = __ldg(wq + (size_t)s * 64);
        w4[s][1] = __ldg(wq + (size_t)s * 64 + 32);
    }

    float acc[4][4] = {};
    for (int kb = 0; kb < 8; kb++) {
        body<0>(kb * 4,     Ar, w4, acc, aq, wq);
        body<1>(kb * 4 + 1, Ar, w4, acc, aq, wq);
        body<2>(kb * 4 + 2, Ar, w4, acc, aq, wq);
        body<3>(kb * 4 + 3, Ar, w4, acc, aq, wq);
    }

    // dump partials: sg4[kw][batch row][gate-col]
    {
        const int er = mw * 16 + (lane >> 2);
        const int ec = (lane & 3) * 2;
#pragma unroll
        for (int nt = 0; nt < 4; nt++) {
            const int cc = nt * 8 + ec;
            *(float2*)&sg4[kw][er][cc]     = make_float2(acc[nt][0], acc[nt][1]);
            *(float2*)&sg4[kw][er + 8][cc] = make_float2(acc[nt][2], acc[nt][3]);
        }
    }
    __syncthreads();   // the ONLY CTA barrier in the phase
}

// ---------------- persistent recurrence kernel (512 threads) -------------
__global__ void __launch_bounds__(512, 1) hrnn_persist(
    const int* __restrict__ tokens, const int* __restrict__ measure,
    const float* __restrict__ c0l, const float* __restrict__ c0h,
    float* __restrict__ out, int out_size)
{
    __shared__ float sg4[4][64][34];   // 34816 B

    const int tid = threadIdx.x;
    const int ub = blockIdx.x;
    const int u0 = ub * 8;
    const uint4* WqL = d_Wph + (size_t)ub * WQH_;
    const uint4* WqH = d_Wph + (size_t)(NB_ + ub) * WQH_;

    const int b = tid >> 3;
    const int uA = tid & 7;
    const int unit = u0 + uA;
    const size_t fo = frag_off(b, unit);   // fixed per thread

    char* hlFc[2] = { (char*)d_hlF[0], (char*)d_hlF[1] };
    char* hhFc[2] = { (char*)d_hhF[0], (char*)d_hhF[1] };

    float cl = c0l[b * NHID_ + unit];
    float ch = c0h[b * NHID_ + unit];
    float bv[4];
#pragma unroll
    for (int g = 0; g < 4; g++) bv[g] = __ldg(&d_biasHi[g * NHID_ + unit]);
    const int mval = *measure;

    int hp = 0;   // high-state parity (uniform: flips only on flagged steps)

    for (int t = 0; t < T_; t++) {
        const int lA = t & 1, lN = lA ^ 1;

        // prefetch epilogue operands for the low phase
        const int tok = __ldg(&tokens[b * T_ + t]);
        float pv[4];
        {
            const float* bp = d_P + (size_t)tok * NG_ + unit;
#pragma unroll
            for (int g = 0; g < 4; g++) pv[g] = __ldg(bp + g * NHID_);
        }
        const int need_high = __ldg(&d_flag[t]);

        // ---- low cell: A0 = h_high(frag), A1 = h_low(frag) ----
        gemm_phase(sg4, d_hhF[hp], d_hlF[lA], WqL);
        {
            float gi = sg4[0][b][uA]      + sg4[1][b][uA]
                     + sg4[2][b][uA]      + sg4[3][b][uA]      + pv[0];
            float gf = sg4[0][b][8 + uA]  + sg4[1][b][8 + uA]
                     + sg4[2][b][8 + uA]  + sg4[3][b][8 + uA]  + pv[1];
            float gg = sg4[0][b][16 + uA] + sg4[1][b][16 + uA]
                     + sg4[2][b][16 + uA] + sg4[3][b][16 + uA] + pv[2];
            float go = sg4[0][b][24 + uA] + sg4[1][b][24 + uA]
                     + sg4[2][b][24 + uA] + sg4[3][b][24 + uA] + pv[3];
            float cn = sigm(gf) * cl + sigm(gi) * tanhf(gg);
            float hn = sigm(go) * tanhf(cn);
            cl = cn;
            const __half hh16 = __float2half_rn(hn);
            *(__half*)(hlFc[lN] + fo) = hh16;
            d_hs[((size_t)t * B_ + b) * NHID_ + unit] = hh16;
        }
        gridbar();

        // ---- high cell: only when some batch row is masked this step ----
        if (need_high) {
            const __half hpv = __ldcg((const __half*)(hhFc[hp] + fo));

            gemm_phase(sg4, d_hlF[lN], d_hhF[hp], WqH);
            {
                float gi = sg4[0][b][uA]      + sg4[1][b][uA]
                         + sg4[2][b][uA]      + sg4[3][b][uA]      + bv[0];
                float gf = sg4[0][b][8 + uA]  + sg4[1][b][8 + uA]
                         + sg4[2][b][8 + uA]  + sg4[3][b][8 + uA]  + bv[1];
                float gg = sg4[0][b][16 + uA] + sg4[1][b][16 + uA]
                         + sg4[2][b][16 + uA] + sg4[3][b][16 + uA] + bv[2];
                float go = sg4[0][b][24 + uA] + sg4[1][b][24 + uA]
                         + sg4[2][b][24 + uA] + sg4[3][b][24 + uA] + bv[3];
                float cn = sigm(gf) * ch + sigm(gi) * tanhf(gg);
                float hn = sigm(go) * tanhf(cn);
                bool m = (tok == mval);
                ch = m ? cn : ch;
                *(__half*)(hhFc[hp ^ 1] + fo) = m ? __float2half_rn(hn) : hpv;
            }
            gridbar();
            hp ^= 1;
        }
    }

    // final states (t=511 wrote hl ping 0); c still exact in registers
    size_t q = (size_t)B_ * T_ * NTOK_;
    size_t S = (size_t)B_ * NHID_;
    if ((size_t)out_size >= q + 4 * S) {
        size_t o = (size_t)b * NHID_ + unit;
        out[q + o]         = __half2float(*(const __half*)(hlFc[0] + fo));
        out[q + S + o]     = cl;
        out[q + 2 * S + o] = __half2float(*(const __half*)(hhFc[hp] + fo));
        out[q + 3 * S + o] = ch;
    }
}

// ---------------- fp16 decode GEMM ----------------
// C[b*T+t][n] = hs[t][b][:] @ Wd[n][:]^T + bd[n]; A = fp16 hs (cp.async),
// B = Wd converted fp32->fp16 at staging. 64x64 tiles, 8 warps (2mw x 4nw).
__global__ void __launch_bounds__(256) dec_k(
    const __half* __restrict__ hs,
    const float* __restrict__ Wd,
    const float* __restrict__ bd,
    float* __restrict__ C)
{
    __shared__ __half As[2][64][40];
    __shared__ __half Bs[2][64][40];

    const int tid = threadIdx.x, lane = tid & 31, wid = tid >> 5;
    const int m0 = blockIdx.y * 64, n0 = blockIdx.x * 64;
    const int nw = wid & 3, mw = wid >> 2;

    // A rows: hs[(m0%T + i)][m0/T][:], row stride B*NHID
    const __half* Ab = hs + ((size_t)(m0 % T_) * B_ + (m0 / T_)) * NHID_;
    const long as = (long)B_ * NHID_;

    const int r = tid >> 2, c8 = (tid & 3) * 8;
    const __half* arow = Ab + (long)r * as + c8;
    const float*  brow = Wd + (size_t)(n0 + r) * NHID_ + c8;

    // stage chunk 0
    cpa16(s2u(&As[0][r][c8]), arow);
    cpa_commit();
    {
        float4 f0 = *(const float4*)brow;
        float4 f1 = *(const float4*)(brow + 4);
        *(uint4*)&Bs[0][r][c8] =
            make_uint4(h2u(f0.x, f0.y), h2u(f0.z, f0.w),
                       h2u(f1.x, f1.y), h2u(f1.z, f1.w));
    }
    cpa_wait<0>();
    __syncthreads();

    float acc[2][2][4] = {};

    for (int kc = 0; kc < 32; kc++) {
        const int cur = kc & 1;
        if (kc + 1 < 32) {
            const int ko = (kc + 1) * 32;
            cpa16(s2u(&As[cur ^ 1][r][c8]), arow + ko);
            cpa_commit();
            float4 f0 = *(const float4*)(brow + ko);
            float4 f1 = *(const float4*)(brow + ko + 4);
            *(uint4*)&Bs[cur ^ 1][r][c8] =
                make_uint4(h2u(f0.x, f0.y), h2u(f0.z, f0.w),
                           h2u(f1.x, f1.y), h2u(f1.z, f1.w));
        }
#pragma unroll
        for (int s = 0; s < 2; s++) {
            const int ak = s * 16 + (lane & 3) * 2;
#pragma unroll
            for (int mt = 0; mt < 2; mt++) {
                const int ar = mw * 32 + mt * 16 + (lane >> 2);
                unsigned a[4];
                a[0] = *(const unsigned*)&As[cur][ar][ak];
                a[1] = *(const unsigned*)&As[cur][ar + 8][ak];
                a[2] = *(const unsigned*)&As[cur][ar][ak + 8];
                a[3] = *(const unsigned*)&As[cur][ar + 8][ak + 8];
#pragma unroll
                for (int nt = 0; nt < 2; nt++) {
                    const int nr = nw * 16 + nt * 8 + (lane >> 2);
                    unsigned b0 = *(const unsigned*)&Bs[cur][nr][ak];
                    unsigned b1 = *(const unsigned*)&Bs[cur][nr][ak + 8];
                    mma_f16(acc[mt][nt], a, b0, b1);
                }
            }
        }
        cpa_wait<0>();
        __syncthreads();
    }

    // epilogue
#pragma unroll
    for (int mt = 0; mt < 2; mt++) {
        const int er = m0 + mw * 32 + mt * 16 + (lane >> 2);
#pragma unroll
        for (int nt = 0; nt < 2; nt++) {
            const int c = n0 + nw * 16 + nt * 8 + (lane & 3) * 2;
            float bv0 = bd[c], bv1 = bd[c + 1];
            *(float2*)&C[(size_t)er * NTOK_ + c] =
                make_float2(acc[mt][nt][0] + bv0, acc[mt][nt][1] + bv1);
            *(float2*)&C[(size_t)(er + 8) * NTOK_ + c] =
                make_float2(acc[mt][nt][2] + bv0, acc[mt][nt][3] + bv1);
        }
    }
}

// ---------------- tf32 GEMM for P precompute ----------------
__global__ void __launch_bounds__(256) gemm_k(
    const float* __restrict__ A, int lda,
    const float* __restrict__ Bw, int ldb,
    const float* __restrict__ bias1, const float* __restrict__ bias2,
    float* __restrict__ C, int ldc, int K)
{
    __shared__ unsigned As[64][36];
    __shared__ unsigned Bs[64][36];

    const int tid = threadIdx.x, lane = tid & 31, wid = tid >> 5;
    const int m0 = blockIdx.y * 64, n0 = blockIdx.x * 64;

    const float* Ab = A + (size_t)m0 * lda;
    const long as = lda;

    const int r = tid >> 3, c4 = (tid & 7) * 4;
    float4 pa0 = *(const float4*)(Ab + (long)r * as + c4);
    float4 pa1 = *(const float4*)(Ab + (long)(r + 32) * as + c4);
    float4 pb0 = *(const float4*)(Bw + (size_t)(n0 + r) * ldb + c4);
    float4 pb1 = *(const float4*)(Bw + (size_t)(n0 + r + 32) * ldb + c4);

    const int mw = wid >> 1, nw = wid & 1;
    float acc[4][4] = {};

    const int nch = K / 32;
    for (int kc = 0; kc < nch; kc++) {
        *(uint4*)&As[r][c4]      = tf4(pa0);
        *(uint4*)&As[r + 32][c4] = tf4(pa1);
        *(uint4*)&Bs[r][c4]      = tf4(pb0);
        *(uint4*)&Bs[r + 32][c4] = tf4(pb1);
        __syncthreads();
        if (kc + 1 < nch) {
            int ko = (kc + 1) * 32 + c4;
            pa0 = *(const float4*)(Ab + (long)r * as + ko);
            pa1 = *(const float4*)(Ab + (long)(r + 32) * as + ko);
            pb0 = *(const float4*)(Bw + (size_t)(n0 + r) * ldb + ko);
            pb1 = *(const float4*)(Bw + (size_t)(n0 + r + 32) * ldb + ko);
        }
#pragma unroll
        for (int kk = 0; kk < 4; kk++) {
            const int ak = kk * 8 + (lane & 3);
            const int ar = mw * 16 + (lane >> 2);
            unsigned a[4];
            a[0] = As[ar][ak];     a[1] = As[ar + 8][ak];
            a[2] = As[ar][ak + 4]; a[3] = As[ar + 8][ak + 4];
#pragma unroll
            for (int nt = 0; nt < 4; nt++) {
                const int br = nw * 32 + nt * 8 + (lane >> 2);
                mma_tf32(acc[nt], a, Bs[br][ak], Bs[br][ak + 4]);
            }
        }
        __syncthreads();
    }

    const int er = m0 + mw * 16 + (lane >> 2);
    const int ec0 = n0 + nw * 32 + (lane & 3) * 2;
#pragma unroll
    for (int nt = 0; nt < 4; nt++) {
        int c = ec0 + nt * 8;
        float bv0 = bias1[c] + bias2[c];
        float bv1 = bias1[c + 1] + bias2[c + 1];
        *(float2*)&C[(size_t)er * ldc + c] =
            make_float2(acc[nt][0] + bv0, acc[nt][1] + bv1);
        *(float2*)&C[(size_t)(er + 8) * ldc + c] =
            make_float2(acc[nt][2] + bv0, acc[nt][3] + bv1);
    }
}

// ---------------- init: scatter initial h into frag layout ----------------
__global__ void init_k(const float* h0l, const float* h0h,
                       const float* bih, const float* bhh)
{
    int i = blockIdx.x * blockDim.x + threadIdx.x;
    if (i < B_ * NHID_) {
        int b = i / NHID_, unit = i % NHID_;
        size_t fo = frag_off(b, unit);
        *(__half*)((char*)d_hlF[0] + fo) = __float2half_rn(h0l[i]);
        *(__half*)((char*)d_hhF[0] + fo) = __float2half_rn(h0h[i]);
    }
    if (i < NG_) d_biasHi[i] = bih[i] + bhh[i];
}

// ---------------- launch ----------------
extern "C" void kernel_launch(void* const* d_in, const int* in_sizes, int n_in,
                              void* d_out, int out_size)
{
    const int*   tokens  = (const int*)d_in[0];
    const int*   measure = (const int*)d_in[1];
    const float* emb     = (const float*)d_in[2];
    const float* Wil     = (const float*)d_in[3];   // [4096][1536]
    const float* Whl     = (const float*)d_in[4];   // [4096][1024]
    const float* bil     = (const float*)d_in[5];
    const float* bhl     = (const float*)d_in[6];
    const float* Wih     = (const float*)d_in[7];   // [4096][1024]
    const float* Whh     = (const float*)d_in[8];   // [4096][1024]
    const float* bih     = (const float*)d_in[9];
    const float* bhh     = (const float*)d_in[10];
    const float* Wd      = (const float*)d_in[11];  // [2048][1024]
    const float* bd      = (const float*)d_in[12];
    const float* h0l     = (const float*)d_in[13];
    const float* c0l     = (const float*)d_in[14];
    const float* h0h     = (const float*)d_in[15];
    const float* c0h     = (const float*)d_in[16];
    float* out = (float*)d_out;

    void* p;
    cudaGetSymbolAddress(&p, d_P);   float*  Pp  = (float*)p;
    cudaGetSymbolAddress(&p, d_hs);  __half* hsP = (__half*)p;
    cudaGetSymbolAddress(&p, d_Wph); uint4*  WpP = (uint4*)p;

    init_k<<<256, 256>>>(h0l, h0h, bih, bhh);
    flag_k<<<2, 256>>>(tokens, measure);

    // frag-pack recurrent weights to fp16 (per-kw K-quarters)
    prepack_h_k<<<dim3(32, NB_, 4), 64>>>(Wil, NINP_ + NHID_, NINP_,
                                          Whl, NHID_, WpP);
    prepack_h_k<<<dim3(32, NB_, 4), 64>>>(Wih, NHID_, 0,
                                          Whh, NHID_, WpP + (size_t)NB_ * WQH_);

    // P[v][j] = emb[v,:512] @ W_ih_low[j,:512]^T + b_ih_low[j] + b_hh_low[j]
    gemm_k<<<dim3(NG_ / 64, NTOK_ / 64), 256>>>(
        emb, NINP_, Wil, NINP_ + NHID_, bil, bhl, Pp, NG_, NINP_);

    // entire 512-step recurrence in one persistent kernel (static smem only)
    hrnn_persist<<<NB_, 512>>>(tokens, measure, c0l, c0h, out, out_size);

    // decode (fp16): out[b*T+t][n] = hs[t][b][:] @ W_dec[n][:]^T + b_dec[n]
    dec_k<<<dim3(NTOK_ / 64, (B_ * T_) / 64), 256>>>(hsP, Wd, bd, out);
}